// round 5
// baseline (speedup 1.0000x reference)
#include <cuda_runtime.h>
#include <math.h>

#define NT 32768      // B*L tokens
#define DD 1024
#define NGC 1024
#define NLC 256
#define NCC 1280      // NGC + NLC
#define EPSN 1e-12f

// ---------------- scratch (device globals; no allocation allowed) -------------
__device__ float U_NORM[(size_t)NT * DD];        // l2-normalized noise
__device__ float Z_NORM[(size_t)NT * DD];        // l2-normalized z_proj
__device__ float HBUF[(size_t)NT * DD];          // relu(z@W1+b1)
__device__ float GATE[(size_t)NT * DD];          // sigmoid(zp@Wg+bg)
__device__ float ZPROJ[(size_t)NT * DD];         // z_proj (aligned copy)
__device__ float LOGITS[(size_t)NT * NCC];       // sims, then logits/weights
__device__ float COMBINED[(size_t)NCC * DD];     // updated [gdict; ldict]
__device__ float SUMS[(size_t)NCC * DD];         // segment sums
__device__ float COUNTS[NCC];
__device__ int   IDXG[NT];
__device__ int   IDXL[NT];
__device__ double LOSSACC[3];                    // g, l, direct

// ---------------- zero init -------------------------------------------------
__global__ void zero_kernel() {
    size_t i = (size_t)blockIdx.x * blockDim.x + threadIdx.x;
    size_t tot = (size_t)NCC * DD;
    if (i < tot) SUMS[i] = 0.f;
    if (i < NCC) COUNTS[i] = 0.f;
    if (i < 3) LOSSACC[i] = 0.0;
}

// ---------------- row l2norm of noise + copy raw u to output ----------------
__global__ __launch_bounds__(256) void unorm_kernel(const float* __restrict__ u,
                                                    float* __restrict__ out_u) {
    int row = blockIdx.x;
    int t = threadIdx.x;
    const float* ur = u + (size_t)row * DD;
    float v[4]; float ss = 0.f;
#pragma unroll
    for (int q = 0; q < 4; q++) { v[q] = ur[t + q * 256]; ss += v[q] * v[q]; }
    __shared__ float red[256];
    red[t] = ss; __syncthreads();
    for (int s = 128; s > 0; s >>= 1) { if (t < s) red[t] += red[t + s]; __syncthreads(); }
    float inv = 1.f / fmaxf(sqrtf(red[0]), EPSN);
    float* un = U_NORM + (size_t)row * DD;
    float* ou = out_u + (size_t)row * DD;
#pragma unroll
    for (int q = 0; q < 4; q++) { un[t + q * 256] = v[q] * inv; ou[t + q * 256] = v[q]; }
}

// ---------------- z_proj row norm + loss_direct -----------------------------
__global__ __launch_bounds__(256) void znorm_kernel(const float* __restrict__ zp) {
    int row = blockIdx.x;
    int t = threadIdx.x;
    const float* zr = zp + (size_t)row * DD;
    const float* ur = U_NORM + (size_t)row * DD;
    float v[4]; float ss = 0.f, dp = 0.f;
#pragma unroll
    for (int q = 0; q < 4; q++) {
        v[q] = zr[t + q * 256];
        ss += v[q] * v[q];
        dp += v[q] * ur[t + q * 256];
    }
    __shared__ float redA[256];
    __shared__ float redB[256];
    redA[t] = ss; redB[t] = dp; __syncthreads();
    for (int s = 128; s > 0; s >>= 1) {
        if (t < s) { redA[t] += redA[t + s]; redB[t] += redB[t + s]; }
        __syncthreads();
    }
    float nrm = fmaxf(sqrtf(redA[0]), EPSN);
    float inv = 1.f / nrm;
    float* zn = Z_NORM + (size_t)row * DD;
#pragma unroll
    for (int q = 0; q < 4; q++) zn[t + q * 256] = v[q] * inv;
    if (t == 0) atomicAdd(&LOSSACC[2], (double)(fabsf(redB[0]) * inv));
}

// ---------------- tiled SIMT GEMM (128x128x16, 8x8/thread) ------------------
// TB=1: C = A[M,K] * B[Nn,K]^T   TB=0: C = A[M,K] * B[K,Nn]
// EPI: 0 store, 1 relu+bias, 2 bias (+dual store to C2), 3 sigmoid+bias,
//      4 store+abs-loss, 5 zclean
template <int TB, int EPI>
__global__ __launch_bounds__(256) void gemm_kernel(
    const float* __restrict__ A, const float* __restrict__ B, float* __restrict__ C,
    int M, int Nn, int K, int ldc,
    const float* __restrict__ bias,
    const float* __restrict__ Zin, const float* __restrict__ Gt,
    float* __restrict__ C2)
{
    __shared__ float As[16][132];
    __shared__ float Bs[16][132];
    const int bx = blockIdx.x, by = blockIdx.y;
    const int t = threadIdx.x;
    const int tx = t & 15, ty = t >> 4;
    const int row0 = by * 128, col0 = bx * 128;
    const int lr = t >> 2;
    const int lc4 = (t & 3) * 4;
    const int nnr = t >> 5;
    const int nnc = (t & 31) * 4;

    float acc[8][8];
#pragma unroll
    for (int i = 0; i < 8; i++)
#pragma unroll
        for (int j = 0; j < 8; j++) acc[i][j] = 0.f;

    for (int k0 = 0; k0 < K; k0 += 16) {
#pragma unroll
        for (int h = 0; h < 2; h++) {
            int r = lr + h * 64;
            float4 v = *(const float4*)(A + (size_t)(row0 + r) * K + k0 + lc4);
            As[lc4 + 0][r] = v.x; As[lc4 + 1][r] = v.y;
            As[lc4 + 2][r] = v.z; As[lc4 + 3][r] = v.w;
        }
        if (TB) {
#pragma unroll
            for (int h = 0; h < 2; h++) {
                int r = lr + h * 64;
                float4 v = *(const float4*)(B + (size_t)(col0 + r) * K + k0 + lc4);
                Bs[lc4 + 0][r] = v.x; Bs[lc4 + 1][r] = v.y;
                Bs[lc4 + 2][r] = v.z; Bs[lc4 + 3][r] = v.w;
            }
        } else {
#pragma unroll
            for (int h = 0; h < 2; h++) {
                int kr = nnr + h * 8;
                float4 v = *(const float4*)(B + (size_t)(k0 + kr) * Nn + col0 + nnc);
                *(float4*)&Bs[kr][nnc] = v;
            }
        }
        __syncthreads();
#pragma unroll
        for (int kk = 0; kk < 16; kk++) {
            float a[8], b[8];
#pragma unroll
            for (int i = 0; i < 4; i++) {
                a[i]     = As[kk][ty * 4 + i];
                a[i + 4] = As[kk][64 + ty * 4 + i];
                b[i]     = Bs[kk][tx * 4 + i];
                b[i + 4] = Bs[kk][64 + tx * 4 + i];
            }
#pragma unroll
            for (int i = 0; i < 8; i++)
#pragma unroll
                for (int j = 0; j < 8; j++) acc[i][j] += a[i] * b[j];
        }
        __syncthreads();
    }

    float absSum = 0.f;
#pragma unroll
    for (int i = 0; i < 8; i++) {
        int r = row0 + ((i < 4) ? ty * 4 + i : 64 + ty * 4 + (i - 4));
#pragma unroll
        for (int j = 0; j < 8; j++) {
            int c = col0 + ((j < 4) ? tx * 4 + j : 64 + tx * 4 + (j - 4));
            float v = acc[i][j];
            size_t idx = (size_t)r * ldc + c;
            if (EPI == 0) C[idx] = v;
            else if (EPI == 1) { v += bias[c]; C[idx] = fmaxf(v, 0.f); }
            else if (EPI == 2) { v += bias[c]; C[idx] = v; C2[idx] = v; }
            else if (EPI == 3) { v += bias[c]; C[idx] = 1.f / (1.f + __expf(-v)); }
            else if (EPI == 4) { C[idx] = v; absSum += fabsf(v); }
            else if (EPI == 5) { C[idx] = Zin[idx] - Gt[idx] * v; }
        }
    }
    if (EPI == 4) {
        __shared__ float red[256];
        red[t] = absSum; __syncthreads();
        for (int s = 128; s > 0; s >>= 1) { if (t < s) red[t] += red[t + s]; __syncthreads(); }
        if (t == 0) atomicAdd(&LOSSACC[(col0 >= NGC) ? 1 : 0], (double)red[0]);
    }
}

// ---------------- argmax over sims ------------------------------------------
__global__ __launch_bounds__(256) void argmax_kernel() {
    int row = blockIdx.x;
    int t = threadIdx.x;
    const float* L = LOGITS + (size_t)row * NCC;
    __shared__ float sv[256];
    __shared__ int si[256];
    // global part [0,1024)
    float best = -3.0e38f; int bi = 0;
    for (int j = t; j < NGC; j += 256) {
        float v = L[j];
        if (v > best) { best = v; bi = j; }
    }
    sv[t] = best; si[t] = bi; __syncthreads();
    for (int s = 128; s > 0; s >>= 1) {
        if (t < s) {
            float ov = sv[t + s]; int oi = si[t + s];
            if (ov > sv[t] || (ov == sv[t] && oi < si[t])) { sv[t] = ov; si[t] = oi; }
        }
        __syncthreads();
    }
    if (t == 0) IDXG[row] = si[0];
    __syncthreads();
    // local part [1024,1280) : one element per thread (t<256)
    float v = L[NGC + t];
    sv[t] = v; si[t] = t; __syncthreads();
    for (int s = 128; s > 0; s >>= 1) {
        if (t < s) {
            float ov = sv[t + s]; int oi = si[t + s];
            if (ov > sv[t] || (ov == sv[t] && oi < si[t])) { sv[t] = ov; si[t] = oi; }
        }
        __syncthreads();
    }
    if (t == 0) IDXL[row] = si[0];
}

// ---------------- segment scatter-add ---------------------------------------
__global__ __launch_bounds__(256) void scatter_kernel() {
    int row = blockIdx.x;
    int t = threadIdx.x;
    int ig = IDXG[row], il = IDXL[row];
    const float* u = U_NORM + (size_t)row * DD;
    float* sg = SUMS + (size_t)ig * DD;
    float* sl = SUMS + (size_t)(NGC + il) * DD;
#pragma unroll
    for (int q = 0; q < 4; q++) {
        int j = t + q * 256;
        float v = u[j];
        atomicAdd(&sg[j], v);
        atomicAdd(&sl[j], v);
    }
    if (t == 0) { atomicAdd(&COUNTS[ig], 1.f); atomicAdd(&COUNTS[NGC + il], 1.f); }
}

// ---------------- dict EMA update + renorm -> COMBINED ----------------------
__global__ __launch_bounds__(256) void dictupd_kernel(const float* __restrict__ gd,
                                                      const float* __restrict__ ld) {
    int k = blockIdx.x;
    int t = threadIdx.x;
    const float* old = (k < NGC) ? (gd + (size_t)k * DD) : (ld + (size_t)(k - NGC) * DD);
    float m = (k < NGC) ? 0.999f : 0.8f;
    float cnt = COUNTS[k];
    float up[4]; float ss = 0.f;
#pragma unroll
    for (int q = 0; q < 4; q++) {
        int j = t + q * 256;
        float o = old[j];
        float u;
        if (cnt > 0.f) {
            float mean = SUMS[(size_t)k * DD + j] / fmaxf(cnt, 1.f);
            u = m * o + (1.f - m) * mean;
        } else u = o;
        up[q] = u; ss += u * u;
    }
    __shared__ float red[256];
    red[t] = ss; __syncthreads();
    for (int s = 128; s > 0; s >>= 1) { if (t < s) red[t] += red[t + s]; __syncthreads(); }
    float inv = 1.f / fmaxf(sqrtf(red[0]), EPSN);
#pragma unroll
    for (int q = 0; q < 4; q++) COMBINED[(size_t)k * DD + t + q * 256] = up[q] * inv;
}

// ---------------- softmax over logits/TEMP (in place) -----------------------
__global__ __launch_bounds__(256) void softmax_kernel() {
    int row = blockIdx.x;
    int t = threadIdx.x;
    float* L = LOGITS + (size_t)row * NCC;
    const float invT = 1.f / 0.07f;
    float v[5];
    float mx = -3.0e38f;
#pragma unroll
    for (int q = 0; q < 5; q++) { v[q] = L[t + q * 256] * invT; mx = fmaxf(mx, v[q]); }
    __shared__ float red[256];
    red[t] = mx; __syncthreads();
    for (int s = 128; s > 0; s >>= 1) { if (t < s) red[t] = fmaxf(red[t], red[t + s]); __syncthreads(); }
    mx = red[0]; __syncthreads();
    float sum = 0.f;
#pragma unroll
    for (int q = 0; q < 5; q++) { v[q] = __expf(v[q] - mx); sum += v[q]; }
    red[t] = sum; __syncthreads();
    for (int s = 128; s > 0; s >>= 1) { if (t < s) red[t] += red[t + s]; __syncthreads(); }
    float inv = 1.f / red[0];
#pragma unroll
    for (int q = 0; q < 5; q++) L[t + q * 256] = v[q] * inv;
}

// ---------------- finalize loss ---------------------------------------------
__global__ void finalize_kernel(float* __restrict__ out_loss) {
    double lg = LOSSACC[0] / ((double)NT * (double)NGC);
    double ll = LOSSACC[1] / ((double)NT * (double)NLC);
    double ldir = LOSSACC[2] / (double)NT;
    *out_loss = (float)(lg + ll + ldir);
}

// ---------------- driver -----------------------------------------------------
extern "C" void kernel_launch(void* const* d_in, const int* in_sizes, int n_in,
                              void* d_out, int out_size) {
    const float* content = (const float*)d_in[0];
    const float* noise   = (const float*)d_in[1];
    const float* W1 = (const float*)d_in[2];
    const float* b1 = (const float*)d_in[3];
    const float* W2 = (const float*)d_in[4];
    const float* b2 = (const float*)d_in[5];
    const float* Wg = (const float*)d_in[6];
    const float* bg = (const float*)d_in[7];
    const float* gdict = (const float*)d_in[8];
    const float* ldict = (const float*)d_in[9];

    float* out = (float*)d_out;
    float* out_zc   = out;                                   // [NT*DD]
    float* out_loss = out + (size_t)NT * DD;                 // [1]
    float* out_zp   = out_loss + 1;                          // [NT*DD] (4B-aligned only!)
    float* out_u    = out_zp + (size_t)NT * DD;              // [NT*DD] (4B-aligned only!)

    // scratch pointers for kernels that need them as args
    float* LOGITS_p; cudaGetSymbolAddress((void**)&LOGITS_p, LOGITS);
    float* HBUF_p;   cudaGetSymbolAddress((void**)&HBUF_p, HBUF);
    float* GATE_p;   cudaGetSymbolAddress((void**)&GATE_p, GATE);
    float* UN_p;     cudaGetSymbolAddress((void**)&UN_p, U_NORM);
    float* ZN_p;     cudaGetSymbolAddress((void**)&ZN_p, Z_NORM);
    float* CMB_p;    cudaGetSymbolAddress((void**)&CMB_p, COMBINED);
    float* ZP_p;     cudaGetSymbolAddress((void**)&ZP_p, ZPROJ);

    // 1. zero accumulators
    {
        size_t tot = (size_t)NCC * DD;
        int blocks = (int)((tot + 255) / 256);
        zero_kernel<<<blocks, 256>>>();
    }
    // 2. u_norm + copy u to output (scalar stores; out_u may be 4B-aligned only)
    unorm_kernel<<<NT, 256>>>(noise, out_u);

    dim3 thr(256);
    // 3-4. assignment sims over OLD dicts -> LOGITS[:, :1024], [:,1024:]
    gemm_kernel<1, 0><<<dim3(NGC / 128, NT / 128), thr>>>(
        UN_p, gdict, LOGITS_p, NT, NGC, DD, NCC, nullptr, nullptr, nullptr, nullptr);
    gemm_kernel<1, 0><<<dim3(NLC / 128, NT / 128), thr>>>(
        UN_p, ldict, LOGITS_p + NGC, NT, NLC, DD, NCC, nullptr, nullptr, nullptr, nullptr);
    // 5. argmax
    argmax_kernel<<<NT, 256>>>();
    // 6. scatter segment sums
    scatter_kernel<<<NT, 256>>>();
    // 7. dict EMA + renorm -> COMBINED (new [gdict; ldict])
    dictupd_kernel<<<NCC, 256>>>(gdict, ldict);

    // 8. H = relu(content @ W1 + b1)
    gemm_kernel<0, 1><<<dim3(DD / 128, NT / 128), thr>>>(
        content, W1, HBUF_p, NT, DD, DD, DD, b1, nullptr, nullptr, nullptr);
    // 9. z_proj = H @ W2 + b2  -> ZPROJ (aligned) + dual scalar store to out_zp
    gemm_kernel<0, 2><<<dim3(DD / 128, NT / 128), thr>>>(
        HBUF_p, W2, ZP_p, NT, DD, DD, DD, b2, nullptr, nullptr, out_zp);
    // 10. gate = sigmoid(z_proj @ Wg + bg)  (reads aligned ZPROJ)
    gemm_kernel<0, 3><<<dim3(DD / 128, NT / 128), thr>>>(
        ZP_p, Wg, GATE_p, NT, DD, DD, DD, bg, nullptr, nullptr, nullptr);
    // 11. z_norm + loss_direct (reads aligned ZPROJ)
    znorm_kernel<<<NT, 256>>>(ZP_p);

    // 12. logits = z_norm @ COMBINED^T  (epilogue: loss_g / loss_l abs-sums)
    gemm_kernel<1, 4><<<dim3(NCC / 128, NT / 128), thr>>>(
        ZN_p, CMB_p, LOGITS_p, NT, NCC, DD, NCC, nullptr, nullptr, nullptr, nullptr);
    // 13. softmax (with 1/TEMP), in place
    softmax_kernel<<<NT, 256>>>();
    // 14. z_clean = content - gate * (weights @ COMBINED)
    gemm_kernel<0, 5><<<dim3(DD / 128, NT / 128), thr>>>(
        LOGITS_p, CMB_p, out_zc, NT, DD, NCC, DD, nullptr, content, GATE_p, nullptr);
    // 15. loss
    finalize_kernel<<<1, 1>>>(out_loss);
}

// round 7
// speedup vs baseline: 2.1259x; 2.1259x over previous
#include <cuda_runtime.h>
#include <cuda_bf16.h>
#include <math.h>
#include <cstdint>

#define NT 32768      // B*L tokens
#define DD 1024
#define NGC 1024
#define NLC 256
#define NCC 1280      // NGC + NLC
#define EPSN 1e-12f

// ===================== helpers ==============================================
__device__ __forceinline__ uint32_t smem_u32(const void* p) {
    uint32_t a;
    asm("{ .reg .u64 t; cvta.to.shared.u64 t, %1; cvt.u32.u64 %0, t; }" : "=r"(a) : "l"(p));
    return a;
}

#define LDSM_X4(r0, r1, r2, r3, addr) \
    asm volatile("ldmatrix.sync.aligned.m8n8.x4.shared.b16 {%0,%1,%2,%3}, [%4];" \
                 : "=r"(r0), "=r"(r1), "=r"(r2), "=r"(r3) : "r"(addr))

__device__ __forceinline__ void mma_bf16(float* c, const uint32_t* a, const uint32_t* b) {
    asm volatile(
        "mma.sync.aligned.m16n8k16.row.col.f32.bf16.bf16.f32 "
        "{%0,%1,%2,%3}, {%4,%5,%6,%7}, {%8,%9}, {%0,%1,%2,%3};"
        : "+f"(c[0]), "+f"(c[1]), "+f"(c[2]), "+f"(c[3])
        : "r"(a[0]), "r"(a[1]), "r"(a[2]), "r"(a[3]), "r"(b[0]), "r"(b[1]));
}

#define CP_ASYNC16(dst, src) \
    asm volatile("cp.async.cg.shared.global [%0], [%1], 16;" :: "r"(dst), "l"(src) : "memory")
#define CP_COMMIT() asm volatile("cp.async.commit_group;" ::: "memory")
#define CP_WAIT1()  asm volatile("cp.async.wait_group 1;" ::: "memory")
#define CP_WAIT0()  asm volatile("cp.async.wait_group 0;" ::: "memory")

__device__ __forceinline__ void split2(float x, __nv_bfloat16& h, __nv_bfloat16& l) {
    h = __float2bfloat16(x);
    l = __float2bfloat16(x - __bfloat162float(h));
}

// ===================== scratch ==============================================
__device__ float U_NORM[(size_t)NT * DD];
__device__ float GATE[(size_t)NT * DD];
__device__ float ZPROJ[(size_t)NT * DD];
__device__ float LOGITS[(size_t)NT * NCC];
__device__ float COMBINED[(size_t)NCC * DD];
__device__ float SUMS[(size_t)NCC * DD];
__device__ float COUNTS[NCC];
__device__ int   IDXG[NT];
__device__ int   IDXL[NT];
__device__ double LOSSACC[3];

#define BUF(name, n) __device__ __align__(256) __nv_bfloat16 name[(size_t)(n)]
BUF(CTh, NT* DD);  BUF(CTl, NT* DD);
BUF(UNh, NT* DD);  BUF(UNl, NT* DD);
BUF(Hh,  NT* DD);  BUF(Hl,  NT* DD);
BUF(ZPh, NT* DD);  BUF(ZPl, NT* DD);
BUF(ZNh, NT* DD);  BUF(ZNl, NT* DD);
BUF(WTSh, NT* NCC); BUF(WTSl, NT* NCC);
BUF(DICh, NCC* DD); BUF(DICl, NCC* DD);
BUF(CMBh, NCC* DD); BUF(CMBl, NCC* DD);
BUF(CMBTh, DD* NCC); BUF(CMBTl, DD* NCC);
BUF(W1Th, DD* DD); BUF(W1Tl, DD* DD);
BUF(W2Th, DD* DD); BUF(W2Tl, DD* DD);
BUF(WgTh, DD* DD); BUF(WgTl, DD* DD);

// ===================== small kernels ========================================
__global__ void zero_kernel() {
    size_t i = (size_t)blockIdx.x * blockDim.x + threadIdx.x;
    size_t tot = (size_t)NCC * DD;
    if (i < tot) SUMS[i] = 0.f;
    if (i < NCC) COUNTS[i] = 0.f;
    if (i < 3) LOSSACC[i] = 0.0;
}

__global__ __launch_bounds__(256) void split_kernel(const float* __restrict__ src,
                                                    __nv_bfloat16* __restrict__ dh,
                                                    __nv_bfloat16* __restrict__ dl, size_t n) {
    for (size_t i = (size_t)blockIdx.x * blockDim.x + threadIdx.x; i < n;
         i += (size_t)gridDim.x * blockDim.x) {
        __nv_bfloat16 h, l;
        split2(src[i], h, l);
        dh[i] = h; dl[i] = l;
    }
}

// W[R,C] -> out[C,R] with bf16 split
__global__ void tsplit_kernel(const float* __restrict__ W,
                              __nv_bfloat16* __restrict__ oh, __nv_bfloat16* __restrict__ ol,
                              int R, int Cc) {
    __shared__ float tile[32][33];
    int bx = blockIdx.x, by = blockIdx.y;
    int x = bx * 32 + threadIdx.x;
    int y = by * 32 + threadIdx.y;
    tile[threadIdx.y][threadIdx.x] = W[(size_t)y * Cc + x];
    __syncthreads();
    int orow = bx * 32 + threadIdx.y;
    int ocol = by * 32 + threadIdx.x;
    __nv_bfloat16 h, l;
    split2(tile[threadIdx.x][threadIdx.y], h, l);
    oh[(size_t)orow * R + ocol] = h;
    ol[(size_t)orow * R + ocol] = l;
}

__global__ __launch_bounds__(256) void unorm_kernel(const float* __restrict__ u,
                                                    float* __restrict__ out_u) {
    int row = blockIdx.x, t = threadIdx.x;
    const float* ur = u + (size_t)row * DD;
    float v[4]; float ss = 0.f;
#pragma unroll
    for (int q = 0; q < 4; q++) { v[q] = ur[t + q * 256]; ss += v[q] * v[q]; }
    __shared__ float red[256];
    red[t] = ss; __syncthreads();
    for (int s = 128; s > 0; s >>= 1) { if (t < s) red[t] += red[t + s]; __syncthreads(); }
    float inv = 1.f / fmaxf(sqrtf(red[0]), EPSN);
    size_t base = (size_t)row * DD;
#pragma unroll
    for (int q = 0; q < 4; q++) {
        int j = t + q * 256;
        float un = v[q] * inv;
        U_NORM[base + j] = un;
        out_u[base + j] = v[q];
        __nv_bfloat16 h, l; split2(un, h, l);
        UNh[base + j] = h; UNl[base + j] = l;
    }
}

__global__ __launch_bounds__(256) void znorm_kernel() {
    int row = blockIdx.x, t = threadIdx.x;
    size_t base = (size_t)row * DD;
    float v[4]; float ss = 0.f, dp = 0.f;
#pragma unroll
    for (int q = 0; q < 4; q++) {
        int j = t + q * 256;
        v[q] = ZPROJ[base + j];
        ss += v[q] * v[q];
        dp += v[q] * U_NORM[base + j];
    }
    __shared__ float redA[256];
    __shared__ float redB[256];
    redA[t] = ss; redB[t] = dp; __syncthreads();
    for (int s = 128; s > 0; s >>= 1) {
        if (t < s) { redA[t] += redA[t + s]; redB[t] += redB[t + s]; }
        __syncthreads();
    }
    float inv = 1.f / fmaxf(sqrtf(redA[0]), EPSN);
#pragma unroll
    for (int q = 0; q < 4; q++) {
        int j = t + q * 256;
        __nv_bfloat16 h, l; split2(v[q] * inv, h, l);
        ZNh[base + j] = h; ZNl[base + j] = l;
    }
    if (t == 0) atomicAdd(&LOSSACC[2], (double)(fabsf(redB[0]) * inv));
}

__global__ __launch_bounds__(256) void argmax_kernel() {
    int row = blockIdx.x, t = threadIdx.x;
    const float* L = LOGITS + (size_t)row * NCC;
    __shared__ float sv[256];
    __shared__ int si[256];
    float best = -3.0e38f; int bi = 0;
    for (int j = t; j < NGC; j += 256) {
        float v = L[j];
        if (v > best) { best = v; bi = j; }
    }
    sv[t] = best; si[t] = bi; __syncthreads();
    for (int s = 128; s > 0; s >>= 1) {
        if (t < s) {
            float ov = sv[t + s]; int oi = si[t + s];
            if (ov > sv[t] || (ov == sv[t] && oi < si[t])) { sv[t] = ov; si[t] = oi; }
        }
        __syncthreads();
    }
    if (t == 0) IDXG[row] = si[0];
    __syncthreads();
    float v = L[NGC + t];
    sv[t] = v; si[t] = t; __syncthreads();
    for (int s = 128; s > 0; s >>= 1) {
        if (t < s) {
            float ov = sv[t + s]; int oi = si[t + s];
            if (ov > sv[t] || (ov == sv[t] && oi < si[t])) { sv[t] = ov; si[t] = oi; }
        }
        __syncthreads();
    }
    if (t == 0) IDXL[row] = si[0];
}

__global__ __launch_bounds__(256) void scatter_kernel() {
    int row = blockIdx.x, t = threadIdx.x;
    int ig = IDXG[row], il = IDXL[row];
    const float* u = U_NORM + (size_t)row * DD;
    float* sg = SUMS + (size_t)ig * DD;
    float* sl = SUMS + (size_t)(NGC + il) * DD;
#pragma unroll
    for (int q = 0; q < 4; q++) {
        int j = t + q * 256;
        float v = u[j];
        atomicAdd(&sg[j], v);
        atomicAdd(&sl[j], v);
    }
    if (t == 0) { atomicAdd(&COUNTS[ig], 1.f); atomicAdd(&COUNTS[NGC + il], 1.f); }
}

__global__ __launch_bounds__(256) void dictupd_kernel(const float* __restrict__ gd,
                                                      const float* __restrict__ ld) {
    int k = blockIdx.x, t = threadIdx.x;
    const float* old = (k < NGC) ? (gd + (size_t)k * DD) : (ld + (size_t)(k - NGC) * DD);
    float m = (k < NGC) ? 0.999f : 0.8f;
    float cnt = COUNTS[k];
    float up[4]; float ss = 0.f;
#pragma unroll
    for (int q = 0; q < 4; q++) {
        int j = t + q * 256;
        float o = old[j];
        float u;
        if (cnt > 0.f) {
            float mean = SUMS[(size_t)k * DD + j] / fmaxf(cnt, 1.f);
            u = m * o + (1.f - m) * mean;
        } else u = o;
        up[q] = u; ss += u * u;
    }
    __shared__ float red[256];
    red[t] = ss; __syncthreads();
    for (int s = 128; s > 0; s >>= 1) { if (t < s) red[t] += red[t + s]; __syncthreads(); }
    float inv = 1.f / fmaxf(sqrtf(red[0]), EPSN);
    size_t base = (size_t)k * DD;
#pragma unroll
    for (int q = 0; q < 4; q++) {
        int j = t + q * 256;
        float u = up[q] * inv;
        COMBINED[base + j] = u;
        __nv_bfloat16 h, l; split2(u, h, l);
        CMBh[base + j] = h; CMBl[base + j] = l;
    }
}

__global__ __launch_bounds__(256) void softmax_kernel() {
    int row = blockIdx.x, t = threadIdx.x;
    const float* L = LOGITS + (size_t)row * NCC;
    const float invT = 1.f / 0.07f;
    float v[5];
    float mx = -3.0e38f;
#pragma unroll
    for (int q = 0; q < 5; q++) { v[q] = L[t + q * 256] * invT; mx = fmaxf(mx, v[q]); }
    __shared__ float red[256];
    red[t] = mx; __syncthreads();
    for (int s = 128; s > 0; s >>= 1) { if (t < s) red[t] = fmaxf(red[t], red[t + s]); __syncthreads(); }
    mx = red[0]; __syncthreads();
    float sum = 0.f;
#pragma unroll
    for (int q = 0; q < 5; q++) { v[q] = __expf(v[q] - mx); sum += v[q]; }
    red[t] = sum; __syncthreads();
    for (int s = 128; s > 0; s >>= 1) { if (t < s) red[t] += red[t + s]; __syncthreads(); }
    float inv = 1.f / red[0];
    size_t base = (size_t)row * NCC;
#pragma unroll
    for (int q = 0; q < 5; q++) {
        __nv_bfloat16 h, l; split2(v[q] * inv, h, l);
        WTSh[base + t + q * 256] = h;
        WTSl[base + t + q * 256] = l;
    }
}

__global__ void finalize_kernel(float* __restrict__ out_loss) {
    double lg = LOSSACC[0] / ((double)NT * (double)NGC);
    double ll = LOSSACC[1] / ((double)NT * (double)NLC);
    double ldir = LOSSACC[2] / (double)NT;
    *out_loss = (float)(lg + ll + ldir);
}

// ===================== mma.sync split-bf16 GEMM =============================
// C[M,N] = A[M,K] * B[N,K]^T, fp32 effective (3-pass split bf16).
// CTA 128x128, 8 warps (2x4), warp tile 64x32 via m16n8k16.
// SMEM: 2 stages x 4 operands x [128 rows x 32 cols bf16, row stride 80B].
// EPI: 0 store C | 1 relu+bias->Oh/Ol | 2 bias->C+C2+Oh/Ol | 3 sigmoid+bias->C
//      4 C+abs-loss | 5 C=Zin-Gt*acc
#define OP_B 10240               // bytes per operand tile (128*80)
#define STG_B (4 * OP_B)         // bytes per stage
#define SMEM_DYN (2 * STG_B)     // 81920

template <int EPI>
__global__ __launch_bounds__(256, 2) void gemm_mma(
    const __nv_bfloat16* __restrict__ Ah, const __nv_bfloat16* __restrict__ Al,
    const __nv_bfloat16* __restrict__ Bh, const __nv_bfloat16* __restrict__ Bl,
    int K, int ldc,
    float* __restrict__ C, const float* __restrict__ bias,
    __nv_bfloat16* __restrict__ Oh, __nv_bfloat16* __restrict__ Ol,
    float* __restrict__ C2,
    const float* __restrict__ Zin, const float* __restrict__ Gt)
{
    extern __shared__ char smem[];
    const uint32_t sb = smem_u32(smem);
    const int t = threadIdx.x;
    const int lane = t & 31, wid = t >> 5;
    const int wm = wid & 1, wn = wid >> 1;          // 2 x 4 warp grid
    const int row0 = blockIdx.y * 128, col0 = blockIdx.x * 128;

    float acc[4][4][4];
#pragma unroll
    for (int mi = 0; mi < 4; mi++)
#pragma unroll
        for (int ni = 0; ni < 4; ni++)
#pragma unroll
            for (int rr = 0; rr < 4; rr++) acc[mi][ni][rr] = 0.f;

    const int NCH = K >> 5;
    const __nv_bfloat16* gp0 = Ah;
    const __nv_bfloat16* gp1 = Al;
    const __nv_bfloat16* gp2 = Bh;
    const __nv_bfloat16* gp3 = Bl;

    // issue cp.async loads for chunk c into stage buf
    auto issue = [&](int c, int buf) {
        const int k0 = c << 5;
        const uint32_t base = sb + buf * STG_B;
        const __nv_bfloat16* srcs[4] = {gp0, gp1, gp2, gp3};
#pragma unroll
        for (int o = 0; o < 4; o++) {
            const __nv_bfloat16* src = srcs[o];
            const int r0g = (o < 2) ? row0 : col0;
            const uint32_t ob = base + o * OP_B;
#pragma unroll
            for (int s2 = 0; s2 < 2; s2++) {
                int s = t + s2 * 256;          // 0..511
                int row = s >> 2, part = s & 3;
                uint32_t dst = ob + row * 80 + part * 16;
                const void* sp = src + (size_t)(r0g + row) * K + k0 + part * 8;
                CP_ASYNC16(dst, sp);
            }
        }
        CP_COMMIT();
    };

    issue(0, 0);
    for (int c = 0; c < NCH; c++) {
        if (c + 1 < NCH) { issue(c + 1, (c + 1) & 1); CP_WAIT1(); }
        else             { CP_WAIT0(); }
        __syncthreads();
        const uint32_t bb = sb + (c & 1) * STG_B;
#pragma unroll
        for (int ks = 0; ks < 32; ks += 16) {
            // B fragments: 4 n8-tiles, each (bh[2], bl[2])
            uint32_t bh[4][2], bl[4][2];
#pragma unroll
            for (int g2 = 0; g2 < 2; g2++) {
                int n0 = wn * 32 + g2 * 16;
                int r = n0 + (lane & 7) + (lane >> 4) * 8;
                int cc = ks + ((lane >> 3) & 1) * 8;
                uint32_t off = r * 80 + cc * 2;
                uint32_t r0, r1, r2, r3;
                LDSM_X4(r0, r1, r2, r3, bb + 2 * OP_B + off);
                bh[2 * g2 + 0][0] = r0; bh[2 * g2 + 0][1] = r1;
                bh[2 * g2 + 1][0] = r2; bh[2 * g2 + 1][1] = r3;
                LDSM_X4(r0, r1, r2, r3, bb + 3 * OP_B + off);
                bl[2 * g2 + 0][0] = r0; bl[2 * g2 + 0][1] = r1;
                bl[2 * g2 + 1][0] = r2; bl[2 * g2 + 1][1] = r3;
            }
#pragma unroll
            for (int mi = 0; mi < 4; mi++) {
                int m0 = wm * 64 + mi * 16;
                int r = m0 + (lane & 7) + ((lane >> 3) & 1) * 8;
                int cc = ks + (lane >> 4) * 8;
                uint32_t off = r * 80 + cc * 2;
                uint32_t ah[4], al[4];
                LDSM_X4(ah[0], ah[1], ah[2], ah[3], bb + 0 * OP_B + off);
                LDSM_X4(al[0], al[1], al[2], al[3], bb + 1 * OP_B + off);
#pragma unroll
                for (int ni = 0; ni < 4; ni++) {
                    mma_bf16(acc[mi][ni], ah, bh[ni]);
                    mma_bf16(acc[mi][ni], ah, bl[ni]);
                    mma_bf16(acc[mi][ni], al, bh[ni]);
                }
            }
        }
        __syncthreads();
    }

    // ---------------- epilogue ----------------
    float absSum = 0.f;
    const int g = lane >> 2, tid4 = lane & 3;
#pragma unroll
    for (int mi = 0; mi < 4; mi++) {
#pragma unroll
        for (int ni = 0; ni < 4; ni++) {
#pragma unroll
            for (int rr = 0; rr < 4; rr++) {
                int r = row0 + wm * 64 + mi * 16 + g + ((rr >> 1) & 1) * 8;
                int cidx = col0 + wn * 32 + ni * 8 + tid4 * 2 + (rr & 1);
                float v = acc[mi][ni][rr];
                size_t idx = (size_t)r * ldc + cidx;
                if (EPI == 0) C[idx] = v;
                else if (EPI == 1) {
                    v = fmaxf(v + bias[cidx], 0.f);
                    __nv_bfloat16 h, l; split2(v, h, l);
                    Oh[idx] = h; Ol[idx] = l;
                } else if (EPI == 2) {
                    v += bias[cidx];
                    C[idx] = v; C2[idx] = v;
                    __nv_bfloat16 h, l; split2(v, h, l);
                    Oh[idx] = h; Ol[idx] = l;
                } else if (EPI == 3) {
                    v += bias[cidx];
                    C[idx] = 1.f / (1.f + __expf(-v));
                } else if (EPI == 4) {
                    C[idx] = v; absSum += fabsf(v);
                } else if (EPI == 5) {
                    C[idx] = Zin[idx] - Gt[idx] * v;
                }
            }
        }
    }
    if (EPI == 4) {
#pragma unroll
        for (int o = 16; o > 0; o >>= 1) absSum += __shfl_xor_sync(0xffffffffu, absSum, o);
        if (lane == 0) atomicAdd(&LOSSACC[col0 >= NGC ? 1 : 0], (double)absSum);
    }
}

// ===================== driver ===============================================
extern "C" void kernel_launch(void* const* d_in, const int* in_sizes, int n_in,
                              void* d_out, int out_size) {
    const float* content = (const float*)d_in[0];
    const float* noise   = (const float*)d_in[1];
    const float* W1 = (const float*)d_in[2];
    const float* b1 = (const float*)d_in[3];
    const float* W2 = (const float*)d_in[4];
    const float* b2 = (const float*)d_in[5];
    const float* Wg = (const float*)d_in[6];
    const float* bg = (const float*)d_in[7];
    const float* gdict = (const float*)d_in[8];
    const float* ldict = (const float*)d_in[9];

    float* out = (float*)d_out;
    float* out_zc   = out;                        // [NT*DD]
    float* out_loss = out + (size_t)NT * DD;      // [1]
    float* out_zp   = out_loss + 1;               // [NT*DD] 4B-aligned only
    float* out_u    = out_zp + (size_t)NT * DD;   // [NT*DD] 4B-aligned only

#define SYM(T, p, s) T* p; cudaGetSymbolAddress((void**)&p, s)
    SYM(float, LOG_p, LOGITS);  SYM(float, CMB_p, COMBINED);
    SYM(__nv_bfloat16, CTh_p, CTh);  SYM(__nv_bfloat16, CTl_p, CTl);
    SYM(__nv_bfloat16, UNh_p, UNh);  SYM(__nv_bfloat16, UNl_p, UNl);
    SYM(__nv_bfloat16, Hh_p, Hh);    SYM(__nv_bfloat16, Hl_p, Hl);
    SYM(__nv_bfloat16, ZPh_p, ZPh);  SYM(__nv_bfloat16, ZPl_p, ZPl);
    SYM(__nv_bfloat16, ZNh_p, ZNh);  SYM(__nv_bfloat16, ZNl_p, ZNl);
    SYM(__nv_bfloat16, WTSh_p, WTSh); SYM(__nv_bfloat16, WTSl_p, WTSl);
    SYM(__nv_bfloat16, DICh_p, DICh); SYM(__nv_bfloat16, DICl_p, DICl);
    SYM(__nv_bfloat16, CMBh_p, CMBh); SYM(__nv_bfloat16, CMBl_p, CMBl);
    SYM(__nv_bfloat16, CMBTh_p, CMBTh); SYM(__nv_bfloat16, CMBTl_p, CMBTl);
    SYM(__nv_bfloat16, W1Th_p, W1Th); SYM(__nv_bfloat16, W1Tl_p, W1Tl);
    SYM(__nv_bfloat16, W2Th_p, W2Th); SYM(__nv_bfloat16, W2Tl_p, W2Tl);
    SYM(__nv_bfloat16, WgTh_p, WgTh); SYM(__nv_bfloat16, WgTl_p, WgTl);
    SYM(float, ZP_p, ZPROJ); SYM(float, GATE_p, GATE);

    cudaFuncSetAttribute(gemm_mma<0>, cudaFuncAttributeMaxDynamicSharedMemorySize, SMEM_DYN);
    cudaFuncSetAttribute(gemm_mma<1>, cudaFuncAttributeMaxDynamicSharedMemorySize, SMEM_DYN);
    cudaFuncSetAttribute(gemm_mma<2>, cudaFuncAttributeMaxDynamicSharedMemorySize, SMEM_DYN);
    cudaFuncSetAttribute(gemm_mma<3>, cudaFuncAttributeMaxDynamicSharedMemorySize, SMEM_DYN);
    cudaFuncSetAttribute(gemm_mma<4>, cudaFuncAttributeMaxDynamicSharedMemorySize, SMEM_DYN);
    cudaFuncSetAttribute(gemm_mma<5>, cudaFuncAttributeMaxDynamicSharedMemorySize, SMEM_DYN);

    // 1. zero + operand conversions
    zero_kernel<<<(NCC * DD + 255) / 256, 256>>>();
    split_kernel<<<2048, 256>>>(content, CTh_p, CTl_p, (size_t)NT * DD);
    split_kernel<<<256, 256>>>(gdict, DICh_p, DICl_p, (size_t)NGC * DD);
    split_kernel<<<64, 256>>>(ldict, DICh_p + (size_t)NGC * DD, DICl_p + (size_t)NGC * DD,
                              (size_t)NLC * DD);
    tsplit_kernel<<<dim3(DD / 32, DD / 32), dim3(32, 32)>>>(W1, W1Th_p, W1Tl_p, DD, DD);
    tsplit_kernel<<<dim3(DD / 32, DD / 32), dim3(32, 32)>>>(W2, W2Th_p, W2Tl_p, DD, DD);
    tsplit_kernel<<<dim3(DD / 32, DD / 32), dim3(32, 32)>>>(Wg, WgTh_p, WgTl_p, DD, DD);
    unorm_kernel<<<NT, 256>>>(noise, out_u);

    // 2. assignment sims over OLD dicts -> LOGITS [NT, 1280]
    gemm_mma<0><<<dim3(NCC / 128, NT / 128), 256, SMEM_DYN>>>(
        UNh_p, UNl_p, DICh_p, DICl_p, DD, NCC, LOG_p, nullptr,
        nullptr, nullptr, nullptr, nullptr, nullptr);
    argmax_kernel<<<NT, 256>>>();
    scatter_kernel<<<NT, 256>>>();
    dictupd_kernel<<<NCC, 256>>>(gdict, ldict);
    tsplit_kernel<<<dim3(DD / 32, NCC / 32), dim3(32, 32)>>>(CMB_p, CMBTh_p, CMBTl_p, NCC, DD);

    // 3. projector chain
    gemm_mma<1><<<dim3(DD / 128, NT / 128), 256, SMEM_DYN>>>(
        CTh_p, CTl_p, W1Th_p, W1Tl_p, DD, DD, nullptr, b1,
        Hh_p, Hl_p, nullptr, nullptr, nullptr);
    gemm_mma<2><<<dim3(DD / 128, NT / 128), 256, SMEM_DYN>>>(
        Hh_p, Hl_p, W2Th_p, W2Tl_p, DD, DD, ZP_p, b2,
        ZPh_p, ZPl_p, out_zp, nullptr, nullptr);
    gemm_mma<3><<<dim3(DD / 128, NT / 128), 256, SMEM_DYN>>>(
        ZPh_p, ZPl_p, WgTh_p, WgTl_p, DD, DD, GATE_p, bg,
        nullptr, nullptr, nullptr, nullptr, nullptr);
    znorm_kernel<<<NT, 256>>>();

    // 4. logits over NEW dicts (+ loss_g / loss_l) -> softmax -> weighted combine
    gemm_mma<4><<<dim3(NCC / 128, NT / 128), 256, SMEM_DYN>>>(
        ZNh_p, ZNl_p, CMBh_p, CMBl_p, DD, NCC, LOG_p, nullptr,
        nullptr, nullptr, nullptr, nullptr, nullptr);
    softmax_kernel<<<NT, 256>>>();
    gemm_mma<5><<<dim3(DD / 128, NT / 128), 256, SMEM_DYN>>>(
        WTSh_p, WTSl_p, CMBTh_p, CMBTl_p, NCC, DD, out_zc, nullptr,
        nullptr, nullptr, nullptr, content, GATE_p);
    finalize_kernel<<<1, 1>>>(out_loss);
}

// round 8
// speedup vs baseline: 2.6405x; 1.2421x over previous
#include <cuda_runtime.h>
#include <cuda_bf16.h>
#include <math.h>
#include <cstdint>

#define NT 32768      // B*L tokens
#define DD 1024
#define NGC 1024
#define NLC 256
#define NCC 1280      // NGC + NLC
#define EPSN 1e-12f

// ===================== helpers ==============================================
__device__ __forceinline__ uint32_t smem_u32(const void* p) {
    uint32_t a;
    asm("{ .reg .u64 t; cvta.to.shared.u64 t, %1; cvt.u32.u64 %0, t; }" : "=r"(a) : "l"(p));
    return a;
}

#define LDSM_X4(r0, r1, r2, r3, addr) \
    asm volatile("ldmatrix.sync.aligned.m8n8.x4.shared.b16 {%0,%1,%2,%3}, [%4];" \
                 : "=r"(r0), "=r"(r1), "=r"(r2), "=r"(r3) : "r"(addr))

__device__ __forceinline__ void mma_bf16(float* c, const uint32_t* a, const uint32_t* b) {
    asm volatile(
        "mma.sync.aligned.m16n8k16.row.col.f32.bf16.bf16.f32 "
        "{%0,%1,%2,%3}, {%4,%5,%6,%7}, {%8,%9}, {%0,%1,%2,%3};"
        : "+f"(c[0]), "+f"(c[1]), "+f"(c[2]), "+f"(c[3])
        : "r"(a[0]), "r"(a[1]), "r"(a[2]), "r"(a[3]), "r"(b[0]), "r"(b[1]));
}

#define CP_ASYNC16(dst, src) \
    asm volatile("cp.async.cg.shared.global [%0], [%1], 16;" :: "r"(dst), "l"(src) : "memory")
#define CP_COMMIT() asm volatile("cp.async.commit_group;" ::: "memory")
#define CP_WAIT1()  asm volatile("cp.async.wait_group 1;" ::: "memory")
#define CP_WAIT0()  asm volatile("cp.async.wait_group 0;" ::: "memory")

__device__ __forceinline__ void split2(float x, __nv_bfloat16& h, __nv_bfloat16& l) {
    h = __float2bfloat16(x);
    l = __float2bfloat16(x - __bfloat162float(h));
}

// monotonic float->u32 mapping (order-preserving for all finite floats)
__device__ __forceinline__ uint32_t fmap(float f) {
    uint32_t u = __float_as_uint(f);
    return (u & 0x80000000u) ? ~u : (u | 0x80000000u);
}

// ===================== scratch ==============================================
__device__ float U_NORM[(size_t)NT * DD];
__device__ float GATE[(size_t)NT * DD];
__device__ float ZPROJ[(size_t)NT * DD];
__device__ float LOGITS[(size_t)NT * NCC];
__device__ float COMBINED[(size_t)NCC * DD];
__device__ float SUMS[(size_t)NCC * DD];
__device__ float COUNTS[NCC];
__device__ unsigned long long AMAXG[NT];   // packed (mapped_val<<32)|~idx
__device__ unsigned long long AMAXL[NT];
__device__ double LOSSACC[3];

#define BUF(name, n) __device__ __align__(256) __nv_bfloat16 name[(size_t)(n)]
BUF(CTh, NT* DD);  BUF(CTl, NT* DD);
BUF(UNh, NT* DD);  BUF(UNl, NT* DD);
BUF(Hh,  NT* DD);  BUF(Hl,  NT* DD);
BUF(ZPh, NT* DD);  BUF(ZPl, NT* DD);
BUF(ZNh, NT* DD);  BUF(ZNl, NT* DD);
BUF(WTSh, NT* NCC); BUF(WTSl, NT* NCC);
BUF(DICh, NCC* DD); BUF(DICl, NCC* DD);
BUF(CMBh, NCC* DD); BUF(CMBl, NCC* DD);
BUF(CMBTh, DD* NCC); BUF(CMBTl, DD* NCC);
BUF(W1Th, DD* DD); BUF(W1Tl, DD* DD);
BUF(W2Th, DD* DD); BUF(W2Tl, DD* DD);
BUF(WgTh, DD* DD); BUF(WgTl, DD* DD);

// ===================== small kernels ========================================
__global__ void zero_kernel() {
    size_t i = (size_t)blockIdx.x * blockDim.x + threadIdx.x;
    size_t tot = (size_t)NCC * DD;
    if (i < tot) SUMS[i] = 0.f;
    if (i < NCC) COUNTS[i] = 0.f;
    if (i < NT) { AMAXG[i] = 0ull; AMAXL[i] = 0ull; }
    if (i < 3) LOSSACC[i] = 0.0;
}

__global__ __launch_bounds__(256) void split_kernel(const float* __restrict__ src,
                                                    __nv_bfloat16* __restrict__ dh,
                                                    __nv_bfloat16* __restrict__ dl, size_t n) {
    for (size_t i = (size_t)blockIdx.x * blockDim.x + threadIdx.x; i < n;
         i += (size_t)gridDim.x * blockDim.x) {
        __nv_bfloat16 h, l;
        split2(src[i], h, l);
        dh[i] = h; dl[i] = l;
    }
}

// W[R,C] -> out[C,R] with bf16 split
__global__ void tsplit_kernel(const float* __restrict__ W,
                              __nv_bfloat16* __restrict__ oh, __nv_bfloat16* __restrict__ ol,
                              int R, int Cc) {
    __shared__ float tile[32][33];
    int bx = blockIdx.x, by = blockIdx.y;
    int x = bx * 32 + threadIdx.x;
    int y = by * 32 + threadIdx.y;
    tile[threadIdx.y][threadIdx.x] = W[(size_t)y * Cc + x];
    __syncthreads();
    int orow = bx * 32 + threadIdx.y;
    int ocol = by * 32 + threadIdx.x;
    __nv_bfloat16 h, l;
    split2(tile[threadIdx.x][threadIdx.y], h, l);
    oh[(size_t)orow * R + ocol] = h;
    ol[(size_t)orow * R + ocol] = l;
}

__global__ __launch_bounds__(256) void unorm_kernel(const float* __restrict__ u,
                                                    float* __restrict__ out_u) {
    int row = blockIdx.x, t = threadIdx.x;
    const float* ur = u + (size_t)row * DD;
    float v[4]; float ss = 0.f;
#pragma unroll
    for (int q = 0; q < 4; q++) { v[q] = ur[t + q * 256]; ss += v[q] * v[q]; }
    __shared__ float red[256];
    red[t] = ss; __syncthreads();
    for (int s = 128; s > 0; s >>= 1) { if (t < s) red[t] += red[t + s]; __syncthreads(); }
    float inv = 1.f / fmaxf(sqrtf(red[0]), EPSN);
    size_t base = (size_t)row * DD;
#pragma unroll
    for (int q = 0; q < 4; q++) {
        int j = t + q * 256;
        float un = v[q] * inv;
        U_NORM[base + j] = un;
        out_u[base + j] = v[q];
        __nv_bfloat16 h, l; split2(un, h, l);
        UNh[base + j] = h; UNl[base + j] = l;
    }
}

__global__ __launch_bounds__(256) void znorm_kernel() {
    int row = blockIdx.x, t = threadIdx.x;
    size_t base = (size_t)row * DD;
    float v[4]; float ss = 0.f, dp = 0.f;
#pragma unroll
    for (int q = 0; q < 4; q++) {
        int j = t + q * 256;
        v[q] = ZPROJ[base + j];
        ss += v[q] * v[q];
        dp += v[q] * U_NORM[base + j];
    }
    __shared__ float redA[256];
    __shared__ float redB[256];
    redA[t] = ss; redB[t] = dp; __syncthreads();
    for (int s = 128; s > 0; s >>= 1) {
        if (t < s) { redA[t] += redA[t + s]; redB[t] += redB[t + s]; }
        __syncthreads();
    }
    float inv = 1.f / fmaxf(sqrtf(redA[0]), EPSN);
#pragma unroll
    for (int q = 0; q < 4; q++) {
        int j = t + q * 256;
        __nv_bfloat16 h, l; split2(v[q] * inv, h, l);
        ZNh[base + j] = h; ZNl[base + j] = l;
    }
    if (t == 0) atomicAdd(&LOSSACC[2], (double)(fabsf(redB[0]) * inv));
}

__global__ __launch_bounds__(256) void scatter_kernel() {
    int row = blockIdx.x, t = threadIdx.x;
    int ig = (int)(~(uint32_t)AMAXG[row]);
    int il = (int)(~(uint32_t)AMAXL[row]);
    const float* u = U_NORM + (size_t)row * DD;
    float* sg = SUMS + (size_t)ig * DD;
    float* sl = SUMS + (size_t)(NGC + il) * DD;
#pragma unroll
    for (int q = 0; q < 4; q++) {
        int j = t + q * 256;
        float v = u[j];
        atomicAdd(&sg[j], v);
        atomicAdd(&sl[j], v);
    }
    if (t == 0) { atomicAdd(&COUNTS[ig], 1.f); atomicAdd(&COUNTS[NGC + il], 1.f); }
}

__global__ __launch_bounds__(256) void dictupd_kernel(const float* __restrict__ gd,
                                                      const float* __restrict__ ld) {
    int k = blockIdx.x, t = threadIdx.x;
    const float* old = (k < NGC) ? (gd + (size_t)k * DD) : (ld + (size_t)(k - NGC) * DD);
    float m = (k < NGC) ? 0.999f : 0.8f;
    float cnt = COUNTS[k];
    float up[4]; float ss = 0.f;
#pragma unroll
    for (int q = 0; q < 4; q++) {
        int j = t + q * 256;
        float o = old[j];
        float u;
        if (cnt > 0.f) {
            float mean = SUMS[(size_t)k * DD + j] / fmaxf(cnt, 1.f);
            u = m * o + (1.f - m) * mean;
        } else u = o;
        up[q] = u; ss += u * u;
    }
    __shared__ float red[256];
    red[t] = ss; __syncthreads();
    for (int s = 128; s > 0; s >>= 1) { if (t < s) red[t] += red[t + s]; __syncthreads(); }
    float inv = 1.f / fmaxf(sqrtf(red[0]), EPSN);
    size_t base = (size_t)k * DD;
#pragma unroll
    for (int q = 0; q < 4; q++) {
        int j = t + q * 256;
        float u = up[q] * inv;
        COMBINED[base + j] = u;
        __nv_bfloat16 h, l; split2(u, h, l);
        CMBh[base + j] = h; CMBl[base + j] = l;
    }
}

__global__ __launch_bounds__(256) void softmax_kernel() {
    int row = blockIdx.x, t = threadIdx.x;
    const float* L = LOGITS + (size_t)row * NCC;
    const float invT = 1.f / 0.07f;
    float v[5];
    float mx = -3.0e38f;
#pragma unroll
    for (int q = 0; q < 5; q++) { v[q] = L[t + q * 256] * invT; mx = fmaxf(mx, v[q]); }
    __shared__ float red[256];
    red[t] = mx; __syncthreads();
    for (int s = 128; s > 0; s >>= 1) { if (t < s) red[t] = fmaxf(red[t], red[t + s]); __syncthreads(); }
    mx = red[0]; __syncthreads();
    float sum = 0.f;
#pragma unroll
    for (int q = 0; q < 5; q++) { v[q] = __expf(v[q] - mx); sum += v[q]; }
    red[t] = sum; __syncthreads();
    for (int s = 128; s > 0; s >>= 1) { if (t < s) red[t] += red[t + s]; __syncthreads(); }
    float inv = 1.f / red[0];
    size_t base = (size_t)row * NCC;
#pragma unroll
    for (int q = 0; q < 5; q++) {
        __nv_bfloat16 h, l; split2(v[q] * inv, h, l);
        WTSh[base + t + q * 256] = h;
        WTSl[base + t + q * 256] = l;
    }
}

__global__ void finalize_kernel(float* __restrict__ out_loss) {
    double lg = LOSSACC[0] / ((double)NT * (double)NGC);
    double ll = LOSSACC[1] / ((double)NT * (double)NLC);
    double ldir = LOSSACC[2] / (double)NT;
    *out_loss = (float)(lg + ll + ldir);
}

// ===================== mma.sync GEMM (split or single pass) =================
// C[M,N] = A[M,K] * B[N,K]^T.  SPLIT=1: fp32-effective 3-pass; SPLIT=0: bf16 1-pass.
// CTA 128x128, 8 warps (2x4), warp tile 64x32 via m16n8k16, cp.async 2-stage.
// EPI: 0 store C | 1 relu+bias->Oh/Ol | 2 bias->C+C2+Oh/Ol | 3 sigmoid+bias->C
//      4 C+abs-loss | 5 C=Zin-Gt*acc | 6 fused row argmax (no C store)
#define OP_B 10240               // bytes per operand tile (128*80)

template <int EPI, int SPLIT>
__global__ __launch_bounds__(256, 2) void gemm_mma(
    const __nv_bfloat16* __restrict__ Ah, const __nv_bfloat16* __restrict__ Al,
    const __nv_bfloat16* __restrict__ Bh, const __nv_bfloat16* __restrict__ Bl,
    int K, int ldc,
    float* __restrict__ C, const float* __restrict__ bias,
    __nv_bfloat16* __restrict__ Oh, __nv_bfloat16* __restrict__ Ol,
    float* __restrict__ C2,
    const float* __restrict__ Zin, const float* __restrict__ Gt)
{
    constexpr int NOPS = SPLIT ? 4 : 2;
    constexpr int STG = NOPS * OP_B;
    constexpr int BH_OFF = SPLIT ? 2 * OP_B : OP_B;

    extern __shared__ char smem[];
    const uint32_t sb = smem_u32(smem);
    const int t = threadIdx.x;
    const int lane = t & 31, wid = t >> 5;
    const int wm = wid & 1, wn = wid >> 1;          // 2 x 4 warp grid
    const int row0 = blockIdx.y * 128, col0 = blockIdx.x * 128;

    float acc[4][4][4];
#pragma unroll
    for (int mi = 0; mi < 4; mi++)
#pragma unroll
        for (int ni = 0; ni < 4; ni++)
#pragma unroll
            for (int rr = 0; rr < 4; rr++) acc[mi][ni][rr] = 0.f;

    const int NCH = K >> 5;
    const __nv_bfloat16* srcs[4] = {Ah, SPLIT ? Al : Bh, Bh, Bl};
    const int rbase[4] = {row0, SPLIT ? row0 : col0, col0, col0};

    auto issue = [&](int c, int buf) {
        const int k0 = c << 5;
        const uint32_t base = sb + buf * STG;
#pragma unroll
        for (int o = 0; o < NOPS; o++) {
            const __nv_bfloat16* src = srcs[o];
            const int r0g = rbase[o];
            const uint32_t ob = base + o * OP_B;
#pragma unroll
            for (int s2 = 0; s2 < 2; s2++) {
                int s = t + s2 * 256;
                int row = s >> 2, part = s & 3;
                uint32_t dst = ob + row * 80 + part * 16;
                const void* sp = src + (size_t)(r0g + row) * K + k0 + part * 8;
                CP_ASYNC16(dst, sp);
            }
        }
        CP_COMMIT();
    };

    issue(0, 0);
    for (int c = 0; c < NCH; c++) {
        if (c + 1 < NCH) { issue(c + 1, (c + 1) & 1); CP_WAIT1(); }
        else             { CP_WAIT0(); }
        __syncthreads();
        const uint32_t bb = sb + (c & 1) * STG;
#pragma unroll
        for (int ks = 0; ks < 32; ks += 16) {
            uint32_t bh[4][2], bl[4][2];
#pragma unroll
            for (int g2 = 0; g2 < 2; g2++) {
                int n0 = wn * 32 + g2 * 16;
                int r = n0 + (lane & 7) + (lane >> 4) * 8;
                int cc = ks + ((lane >> 3) & 1) * 8;
                uint32_t off = r * 80 + cc * 2;
                uint32_t r0, r1, r2, r3;
                LDSM_X4(r0, r1, r2, r3, bb + BH_OFF + off);
                bh[2 * g2 + 0][0] = r0; bh[2 * g2 + 0][1] = r1;
                bh[2 * g2 + 1][0] = r2; bh[2 * g2 + 1][1] = r3;
                if (SPLIT) {
                    LDSM_X4(r0, r1, r2, r3, bb + 3 * OP_B + off);
                    bl[2 * g2 + 0][0] = r0; bl[2 * g2 + 0][1] = r1;
                    bl[2 * g2 + 1][0] = r2; bl[2 * g2 + 1][1] = r3;
                }
            }
#pragma unroll
            for (int mi = 0; mi < 4; mi++) {
                int m0 = wm * 64 + mi * 16;
                int r = m0 + (lane & 7) + ((lane >> 3) & 1) * 8;
                int cc = ks + (lane >> 4) * 8;
                uint32_t off = r * 80 + cc * 2;
                uint32_t ah[4], al[4];
                LDSM_X4(ah[0], ah[1], ah[2], ah[3], bb + 0 * OP_B + off);
                if (SPLIT) LDSM_X4(al[0], al[1], al[2], al[3], bb + 1 * OP_B + off);
#pragma unroll
                for (int ni = 0; ni < 4; ni++) {
                    mma_bf16(acc[mi][ni], ah, bh[ni]);
                    if (SPLIT) {
                        mma_bf16(acc[mi][ni], ah, bl[ni]);
                        mma_bf16(acc[mi][ni], al, bh[ni]);
                    }
                }
            }
        }
        __syncthreads();
    }

    // ---------------- epilogue ----------------
    const int g = lane >> 2, tid4 = lane & 3;
    if (EPI == 6) {
        // per-row argmax -> packed u64 atomicMax
        unsigned long long best[8];
#pragma unroll
        for (int i = 0; i < 8; i++) best[i] = 0ull;
#pragma unroll
        for (int mi = 0; mi < 4; mi++)
#pragma unroll
            for (int ni = 0; ni < 4; ni++)
#pragma unroll
                for (int rr = 0; rr < 4; rr++) {
                    int ri = mi * 2 + ((rr >> 1) & 1);
                    int lcol = wn * 32 + ni * 8 + tid4 * 2 + (rr & 1);
                    int sidx = (col0 >= NGC) ? (col0 - NGC + lcol) : (col0 + lcol);
                    uint32_t u = fmap(acc[mi][ni][rr]);
                    unsigned long long p =
                        ((unsigned long long)u << 32) | (uint32_t)(~sidx);
                    if (p > best[ri]) best[ri] = p;
                }
#pragma unroll
        for (int i = 0; i < 8; i++)
#pragma unroll
            for (int o = 1; o < 4; o <<= 1) {
                unsigned long long ov = __shfl_xor_sync(0xffffffffu, best[i], o);
                if (ov > best[i]) best[i] = ov;
            }
        unsigned long long* S = (unsigned long long*)smem;
        if (tid4 == 0) {
#pragma unroll
            for (int mi = 0; mi < 4; mi++)
#pragma unroll
                for (int b = 0; b < 2; b++) {
                    int lrow = wm * 64 + mi * 16 + g + b * 8;
                    S[lrow * 4 + wn] = best[mi * 2 + b];
                }
        }
        __syncthreads();
        if (t < 128) {
            unsigned long long m = S[t * 4];
#pragma unroll
            for (int w = 1; w < 4; w++) if (S[t * 4 + w] > m) m = S[t * 4 + w];
            unsigned long long* tgt = (col0 >= NGC) ? AMAXL : AMAXG;
            atomicMax(&tgt[row0 + t], m);
        }
        return;
    }

    float absSum = 0.f;
#pragma unroll
    for (int mi = 0; mi < 4; mi++) {
#pragma unroll
        for (int ni = 0; ni < 4; ni++) {
#pragma unroll
            for (int rr = 0; rr < 4; rr++) {
                int r = row0 + wm * 64 + mi * 16 + g + ((rr >> 1) & 1) * 8;
                int cidx = col0 + wn * 32 + ni * 8 + tid4 * 2 + (rr & 1);
                float v = acc[mi][ni][rr];
                size_t idx = (size_t)r * ldc + cidx;
                if (EPI == 0) C[idx] = v;
                else if (EPI == 1) {
                    v = fmaxf(v + bias[cidx], 0.f);
                    __nv_bfloat16 h, l; split2(v, h, l);
                    Oh[idx] = h; Ol[idx] = l;
                } else if (EPI == 2) {
                    v += bias[cidx];
                    C[idx] = v; C2[idx] = v;
                    __nv_bfloat16 h, l; split2(v, h, l);
                    Oh[idx] = h; Ol[idx] = l;
                } else if (EPI == 3) {
                    v += bias[cidx];
                    C[idx] = 1.f / (1.f + __expf(-v));
                } else if (EPI == 4) {
                    C[idx] = v; absSum += fabsf(v);
                } else if (EPI == 5) {
                    C[idx] = Zin[idx] - Gt[idx] * v;
                }
            }
        }
    }
    if (EPI == 4) {
#pragma unroll
        for (int o = 16; o > 0; o >>= 1) absSum += __shfl_xor_sync(0xffffffffu, absSum, o);
        if (lane == 0) atomicAdd(&LOSSACC[col0 >= NGC ? 1 : 0], (double)absSum);
    }
}

// ===================== driver ===============================================
extern "C" void kernel_launch(void* const* d_in, const int* in_sizes, int n_in,
                              void* d_out, int out_size) {
    const float* content = (const float*)d_in[0];
    const float* noise   = (const float*)d_in[1];
    const float* W1 = (const float*)d_in[2];
    const float* b1 = (const float*)d_in[3];
    const float* W2 = (const float*)d_in[4];
    const float* b2 = (const float*)d_in[5];
    const float* Wg = (const float*)d_in[6];
    const float* bg = (const float*)d_in[7];
    const float* gdict = (const float*)d_in[8];
    const float* ldict = (const float*)d_in[9];

    float* out = (float*)d_out;
    float* out_zc   = out;                        // [NT*DD]
    float* out_loss = out + (size_t)NT * DD;      // [1]
    float* out_zp   = out_loss + 1;               // [NT*DD] 4B-aligned only
    float* out_u    = out_zp + (size_t)NT * DD;   // [NT*DD] 4B-aligned only

#define SYM(T, p, s) T* p; cudaGetSymbolAddress((void**)&p, s)
    SYM(float, LOG_p, LOGITS);  SYM(float, CMB_p, COMBINED);
    SYM(__nv_bfloat16, CTh_p, CTh);  SYM(__nv_bfloat16, CTl_p, CTl);
    SYM(__nv_bfloat16, UNh_p, UNh);  SYM(__nv_bfloat16, UNl_p, UNl);
    SYM(__nv_bfloat16, Hh_p, Hh);    SYM(__nv_bfloat16, Hl_p, Hl);
    SYM(__nv_bfloat16, ZPh_p, ZPh);  SYM(__nv_bfloat16, ZPl_p, ZPl);
    SYM(__nv_bfloat16, ZNh_p, ZNh);  SYM(__nv_bfloat16, ZNl_p, ZNl);
    SYM(__nv_bfloat16, WTSh_p, WTSh); SYM(__nv_bfloat16, WTSl_p, WTSl);
    SYM(__nv_bfloat16, DICh_p, DICh); SYM(__nv_bfloat16, DICl_p, DICl);
    SYM(__nv_bfloat16, CMBh_p, CMBh); SYM(__nv_bfloat16, CMBl_p, CMBl);
    SYM(__nv_bfloat16, CMBTh_p, CMBTh); SYM(__nv_bfloat16, CMBTl_p, CMBTl);
    SYM(__nv_bfloat16, W1Th_p, W1Th); SYM(__nv_bfloat16, W1Tl_p, W1Tl);
    SYM(__nv_bfloat16, W2Th_p, W2Th); SYM(__nv_bfloat16, W2Tl_p, W2Tl);
    SYM(__nv_bfloat16, WgTh_p, WgTh); SYM(__nv_bfloat16, WgTl_p, WgTl);
    SYM(float, ZP_p, ZPROJ); SYM(float, GATE_p, GATE);

    const int SM1 = 8 * OP_B;   // split GEMM: 81920
    const int SM0 = 4 * OP_B;   // 1-pass GEMM: 40960
    cudaFuncSetAttribute(gemm_mma<6, 0>, cudaFuncAttributeMaxDynamicSharedMemorySize, SM0);
    cudaFuncSetAttribute(gemm_mma<4, 0>, cudaFuncAttributeMaxDynamicSharedMemorySize, SM0);
    cudaFuncSetAttribute(gemm_mma<1, 1>, cudaFuncAttributeMaxDynamicSharedMemorySize, SM1);
    cudaFuncSetAttribute(gemm_mma<2, 1>, cudaFuncAttributeMaxDynamicSharedMemorySize, SM1);
    cudaFuncSetAttribute(gemm_mma<3, 1>, cudaFuncAttributeMaxDynamicSharedMemorySize, SM1);
    cudaFuncSetAttribute(gemm_mma<5, 1>, cudaFuncAttributeMaxDynamicSharedMemorySize, SM1);

    // 1. zero + operand conversions
    zero_kernel<<<(NCC * DD + 255) / 256, 256>>>();
    split_kernel<<<2048, 256>>>(content, CTh_p, CTl_p, (size_t)NT * DD);
    split_kernel<<<256, 256>>>(gdict, DICh_p, DICl_p, (size_t)NGC * DD);
    split_kernel<<<64, 256>>>(ldict, DICh_p + (size_t)NGC * DD, DICl_p + (size_t)NGC * DD,
                              (size_t)NLC * DD);
    tsplit_kernel<<<dim3(DD / 32, DD / 32), dim3(32, 32)>>>(W1, W1Th_p, W1Tl_p, DD, DD);
    tsplit_kernel<<<dim3(DD / 32, DD / 32), dim3(32, 32)>>>(W2, W2Th_p, W2Tl_p, DD, DD);
    tsplit_kernel<<<dim3(DD / 32, DD / 32), dim3(32, 32)>>>(Wg, WgTh_p, WgTl_p, DD, DD);
    unorm_kernel<<<NT, 256>>>(noise, out_u);

    // 2. assignment sims over OLD dicts, argmax fused (1-pass bf16, no C store)
    gemm_mma<6, 0><<<dim3(NCC / 128, NT / 128), 256, SM0>>>(
        UNh_p, nullptr, DICh_p, nullptr, DD, NCC, nullptr, nullptr,
        nullptr, nullptr, nullptr, nullptr, nullptr);
    scatter_kernel<<<NT, 256>>>();
    dictupd_kernel<<<NCC, 256>>>(gdict, ldict);
    tsplit_kernel<<<dim3(DD / 32, NCC / 32), dim3(32, 32)>>>(CMB_p, CMBTh_p, CMBTl_p, NCC, DD);

    // 3. projector chain (fp32-effective 3-pass)
    gemm_mma<1, 1><<<dim3(DD / 128, NT / 128), 256, SM1>>>(
        CTh_p, CTl_p, W1Th_p, W1Tl_p, DD, DD, nullptr, b1,
        Hh_p, Hl_p, nullptr, nullptr, nullptr);
    gemm_mma<2, 1><<<dim3(DD / 128, NT / 128), 256, SM1>>>(
        Hh_p, Hl_p, W2Th_p, W2Tl_p, DD, DD, ZP_p, b2,
        ZPh_p, ZPl_p, out_zp, nullptr, nullptr);
    gemm_mma<3, 1><<<dim3(DD / 128, NT / 128), 256, SM1>>>(
        ZPh_p, ZPl_p, WgTh_p, WgTl_p, DD, DD, GATE_p, bg,
        nullptr, nullptr, nullptr, nullptr, nullptr);
    znorm_kernel<<<NT, 256>>>();

    // 4. logits over NEW dicts (1-pass bf16 + loss epilogue) -> softmax -> combine
    gemm_mma<4, 0><<<dim3(NCC / 128, NT / 128), 256, SM0>>>(
        ZNh_p, nullptr, CMBh_p, nullptr, DD, NCC, LOG_p, nullptr,
        nullptr, nullptr, nullptr, nullptr, nullptr);
    softmax_kernel<<<NT, 256>>>();
    gemm_mma<5, 1><<<dim3(DD / 128, NT / 128), 256, SM1>>>(
        WTSh_p, WTSl_p, CMBTh_p, CMBTl_p, NCC, DD, out_zc, nullptr,
        nullptr, nullptr, nullptr, content, GATE_p);
    finalize_kernel<<<1, 1>>>(out_loss);
}

// round 11
// speedup vs baseline: 3.3264x; 1.2598x over previous
#include <cuda_runtime.h>
#include <cuda_bf16.h>
#include <math.h>
#include <cstdint>

#define NT 32768      // B*L tokens
#define DD 1024
#define NGC 1024
#define NLC 256
#define NCC 1280      // NGC + NLC
#define EPSN 1e-12f

// ===================== helpers ==============================================
__device__ __forceinline__ uint32_t smem_u32(const void* p) {
    uint32_t a;
    asm("{ .reg .u64 t; cvta.to.shared.u64 t, %1; cvt.u32.u64 %0, t; }" : "=r"(a) : "l"(p));
    return a;
}

#define LDSM_X4(r0, r1, r2, r3, addr) \
    asm volatile("ldmatrix.sync.aligned.m8n8.x4.shared.b16 {%0,%1,%2,%3}, [%4];" \
                 : "=r"(r0), "=r"(r1), "=r"(r2), "=r"(r3) : "r"(addr))

__device__ __forceinline__ void mma_bf16(float* c, const uint32_t* a, const uint32_t* b) {
    asm volatile(
        "mma.sync.aligned.m16n8k16.row.col.f32.bf16.bf16.f32 "
        "{%0,%1,%2,%3}, {%4,%5,%6,%7}, {%8,%9}, {%0,%1,%2,%3};"
        : "+f"(c[0]), "+f"(c[1]), "+f"(c[2]), "+f"(c[3])
        : "r"(a[0]), "r"(a[1]), "r"(a[2]), "r"(a[3]), "r"(b[0]), "r"(b[1]));
}

#define CP_ASYNC16(dst, src) \
    asm volatile("cp.async.cg.shared.global [%0], [%1], 16;" :: "r"(dst), "l"(src) : "memory")
#define CP_COMMIT() asm volatile("cp.async.commit_group;" ::: "memory")
#define CP_WAIT1()  asm volatile("cp.async.wait_group 1;" ::: "memory")
#define CP_WAIT0()  asm volatile("cp.async.wait_group 0;" ::: "memory")

__device__ __forceinline__ void split2(float x, __nv_bfloat16& h, __nv_bfloat16& l) {
    h = __float2bfloat16(x);
    l = __float2bfloat16(x - __bfloat162float(h));
}

// monotonic float->u32 mapping (order-preserving for all finite floats)
__device__ __forceinline__ uint32_t fmap(float f) {
    uint32_t u = __float_as_uint(f);
    return (u & 0x80000000u) ? ~u : (u | 0x80000000u);
}

// ===================== scratch ==============================================
__device__ float U_NORM[(size_t)NT * DD];
__device__ float GATE[(size_t)NT * DD];
__device__ float ZPROJ[(size_t)NT * DD];
__device__ float LOGITS[(size_t)NT * NCC];
__device__ float COMBINED[(size_t)NCC * DD];
__device__ float SUMS[(size_t)NCC * DD];
__device__ float COUNTS[NCC];
__device__ unsigned long long AMAXG[NT];   // packed (mapped_val<<32)|~idx
__device__ unsigned long long AMAXL[NT];
__device__ double LOSSACC[3];

#define BUF(name, n) __device__ __align__(256) __nv_bfloat16 name[(size_t)(n)]
BUF(CTh, NT* DD);  BUF(CTl, NT* DD);
BUF(UNh, NT* DD);
BUF(Hh,  NT* DD);  BUF(Hl,  NT* DD);
BUF(ZPh, NT* DD);
BUF(ZNh, NT* DD);
BUF(WTSh, NT* NCC);
BUF(DICh, NCC* DD);
BUF(CMBh, NCC* DD);
BUF(CMBTh, DD* NCC);
BUF(W1Th, DD* DD); BUF(W1Tl, DD* DD);
BUF(W2Th, DD* DD); BUF(W2Tl, DD* DD);
BUF(WgTh, DD* DD);

// ===================== small kernels ========================================
__global__ void zero_kernel() {
    size_t i = (size_t)blockIdx.x * blockDim.x + threadIdx.x;
    size_t tot = (size_t)NCC * DD;
    if (i < tot) SUMS[i] = 0.f;
    if (i < NCC) COUNTS[i] = 0.f;
    if (i < NT) { AMAXG[i] = 0ull; AMAXL[i] = 0ull; }
    if (i < 3) LOSSACC[i] = 0.0;
}

__global__ __launch_bounds__(256) void split_kernel(const float* __restrict__ src,
                                                    __nv_bfloat16* __restrict__ dh,
                                                    __nv_bfloat16* __restrict__ dl, size_t n) {
    for (size_t i = (size_t)blockIdx.x * blockDim.x + threadIdx.x; i < n;
         i += (size_t)gridDim.x * blockDim.x) {
        __nv_bfloat16 h, l;
        split2(src[i], h, l);
        dh[i] = h;
        if (dl) dl[i] = l;
    }
}

// W[R,C] -> out[C,R] with bf16 split (ol may be null)
__global__ void tsplit_kernel(const float* __restrict__ W,
                              __nv_bfloat16* __restrict__ oh, __nv_bfloat16* __restrict__ ol,
                              int R, int Cc) {
    __shared__ float tile[32][33];
    int bx = blockIdx.x, by = blockIdx.y;
    int x = bx * 32 + threadIdx.x;
    int y = by * 32 + threadIdx.y;
    tile[threadIdx.y][threadIdx.x] = W[(size_t)y * Cc + x];
    __syncthreads();
    int orow = bx * 32 + threadIdx.y;
    int ocol = by * 32 + threadIdx.x;
    __nv_bfloat16 h, l;
    split2(tile[threadIdx.x][threadIdx.y], h, l);
    oh[(size_t)orow * R + ocol] = h;
    if (ol) ol[(size_t)orow * R + ocol] = l;
}

__global__ __launch_bounds__(256) void unorm_kernel(const float* __restrict__ u,
                                                    float* __restrict__ out_u) {
    int row = blockIdx.x, t = threadIdx.x;
    const float* ur = u + (size_t)row * DD;
    float v[4]; float ss = 0.f;
#pragma unroll
    for (int q = 0; q < 4; q++) { v[q] = ur[t + q * 256]; ss += v[q] * v[q]; }
    __shared__ float red[256];
    red[t] = ss; __syncthreads();
    for (int s = 128; s > 0; s >>= 1) { if (t < s) red[t] += red[t + s]; __syncthreads(); }
    float inv = 1.f / fmaxf(sqrtf(red[0]), EPSN);
    size_t base = (size_t)row * DD;
#pragma unroll
    for (int q = 0; q < 4; q++) {
        int j = t + q * 256;
        float un = v[q] * inv;
        U_NORM[base + j] = un;
        out_u[base + j] = v[q];
        UNh[base + j] = __float2bfloat16(un);
    }
}

__global__ __launch_bounds__(256) void znorm_kernel() {
    int row = blockIdx.x, t = threadIdx.x;
    size_t base = (size_t)row * DD;
    float v[4]; float ss = 0.f, dp = 0.f;
#pragma unroll
    for (int q = 0; q < 4; q++) {
        int j = t + q * 256;
        v[q] = ZPROJ[base + j];
        ss += v[q] * v[q];
        dp += v[q] * U_NORM[base + j];
    }
    __shared__ float redA[256];
    __shared__ float redB[256];
    redA[t] = ss; redB[t] = dp; __syncthreads();
    for (int s = 128; s > 0; s >>= 1) {
        if (t < s) { redA[t] += redA[t + s]; redB[t] += redB[t + s]; }
        __syncthreads();
    }
    float inv = 1.f / fmaxf(sqrtf(redA[0]), EPSN);
#pragma unroll
    for (int q = 0; q < 4; q++) {
        int j = t + q * 256;
        ZNh[base + j] = __float2bfloat16(v[q] * inv);
    }
    if (t == 0) atomicAdd(&LOSSACC[2], (double)(fabsf(redB[0]) * inv));
}

__global__ __launch_bounds__(256) void scatter_kernel() {
    int row = blockIdx.x, t = threadIdx.x;
    int ig = (int)(~(uint32_t)AMAXG[row]);
    int il = (int)(~(uint32_t)AMAXL[row]);
    const float* u = U_NORM + (size_t)row * DD;
    float* sg = SUMS + (size_t)ig * DD;
    float* sl = SUMS + (size_t)(NGC + il) * DD;
#pragma unroll
    for (int q = 0; q < 4; q++) {
        int j = t + q * 256;
        float v = u[j];
        atomicAdd(&sg[j], v);
        atomicAdd(&sl[j], v);
    }
    if (t == 0) { atomicAdd(&COUNTS[ig], 1.f); atomicAdd(&COUNTS[NGC + il], 1.f); }
}

__global__ __launch_bounds__(256) void dictupd_kernel(const float* __restrict__ gd,
                                                      const float* __restrict__ ld) {
    int k = blockIdx.x, t = threadIdx.x;
    const float* old = (k < NGC) ? (gd + (size_t)k * DD) : (ld + (size_t)(k - NGC) * DD);
    float m = (k < NGC) ? 0.999f : 0.8f;
    float cnt = COUNTS[k];
    float up[4]; float ss = 0.f;
#pragma unroll
    for (int q = 0; q < 4; q++) {
        int j = t + q * 256;
        float o = old[j];
        float u;
        if (cnt > 0.f) {
            float mean = SUMS[(size_t)k * DD + j] / fmaxf(cnt, 1.f);
            u = m * o + (1.f - m) * mean;
        } else u = o;
        up[q] = u; ss += u * u;
    }
    __shared__ float red[256];
    red[t] = ss; __syncthreads();
    for (int s = 128; s > 0; s >>= 1) { if (t < s) red[t] += red[t + s]; __syncthreads(); }
    float inv = 1.f / fmaxf(sqrtf(red[0]), EPSN);
    size_t base = (size_t)k * DD;
#pragma unroll
    for (int q = 0; q < 4; q++) {
        int j = t + q * 256;
        float u = up[q] * inv;
        COMBINED[base + j] = u;
        CMBh[base + j] = __float2bfloat16(u);
    }
}

__global__ __launch_bounds__(256) void softmax_kernel() {
    int row = blockIdx.x, t = threadIdx.x;
    const float* L = LOGITS + (size_t)row * NCC;
    const float invT = 1.f / 0.07f;
    float v[5];
    float mx = -3.0e38f;
#pragma unroll
    for (int q = 0; q < 5; q++) { v[q] = L[t + q * 256] * invT; mx = fmaxf(mx, v[q]); }
    __shared__ float red[256];
    red[t] = mx; __syncthreads();
    for (int s = 128; s > 0; s >>= 1) { if (t < s) red[t] = fmaxf(red[t], red[t + s]); __syncthreads(); }
    mx = red[0]; __syncthreads();
    float sum = 0.f;
#pragma unroll
    for (int q = 0; q < 5; q++) { v[q] = __expf(v[q] - mx); sum += v[q]; }
    red[t] = sum; __syncthreads();
    for (int s = 128; s > 0; s >>= 1) { if (t < s) red[t] += red[t + s]; __syncthreads(); }
    float inv = 1.f / red[0];
    size_t base = (size_t)row * NCC;
#pragma unroll
    for (int q = 0; q < 5; q++)
        WTSh[base + t + q * 256] = __float2bfloat16(v[q] * inv);
}

__global__ void finalize_kernel(float* __restrict__ out_loss) {
    double lg = LOSSACC[0] / ((double)NT * (double)NGC);
    double ll = LOSSACC[1] / ((double)NT * (double)NLC);
    double ldir = LOSSACC[2] / (double)NT;
    *out_loss = (float)(lg + ll + ldir);
}

// ===================== mma.sync GEMM (split or single pass) =================
// C[M,N] = A[M,K] * B[N,K]^T.  SPLIT=1: fp32-effective 3-pass; SPLIT=0: bf16 1-pass.
// CTA 128x128, 8 warps (2x4), warp tile 64x32 via m16n8k16, cp.async 2-stage.
// EPI: 0 store C | 1 relu+bias->Oh/Ol | 2 bias->C+C2+Oh | 3 sigmoid+bias->C
//      4 C+abs-loss | 5 C=Zin-Gt*acc | 6 fused row argmax (no C store)
#define OP_B 10240               // bytes per operand tile (128*80)

template <int EPI, int SPLIT>
__global__ __launch_bounds__(256, 2) void gemm_mma(
    const __nv_bfloat16* __restrict__ Ah, const __nv_bfloat16* __restrict__ Al,
    const __nv_bfloat16* __restrict__ Bh, const __nv_bfloat16* __restrict__ Bl,
    int K, int ldc,
    float* __restrict__ C, const float* __restrict__ bias,
    __nv_bfloat16* __restrict__ Oh, __nv_bfloat16* __restrict__ Ol,
    float* __restrict__ C2,
    const float* __restrict__ Zin, const float* __restrict__ Gt)
{
    constexpr int NOPS = SPLIT ? 4 : 2;
    constexpr int STG = NOPS * OP_B;
    constexpr int BH_OFF = SPLIT ? 2 * OP_B : OP_B;

    extern __shared__ char smem[];
    const uint32_t sb = smem_u32(smem);
    const int t = threadIdx.x;
    const int lane = t & 31, wid = t >> 5;
    const int wm = wid & 1, wn = wid >> 1;          // 2 x 4 warp grid
    const int row0 = blockIdx.y * 128, col0 = blockIdx.x * 128;

    float acc[4][4][4];
#pragma unroll
    for (int mi = 0; mi < 4; mi++)
#pragma unroll
        for (int ni = 0; ni < 4; ni++)
#pragma unroll
            for (int rr = 0; rr < 4; rr++) acc[mi][ni][rr] = 0.f;

    const int NCH = K >> 5;
    const __nv_bfloat16* srcs[4] = {Ah, SPLIT ? Al : Bh, Bh, Bl};
    const int rbase[4] = {row0, SPLIT ? row0 : col0, col0, col0};

    auto issue = [&](int c, int buf) {
        const int k0 = c << 5;
        const uint32_t base = sb + buf * STG;
#pragma unroll
        for (int o = 0; o < NOPS; o++) {
            const __nv_bfloat16* src = srcs[o];
            const int r0g = rbase[o];
            const uint32_t ob = base + o * OP_B;
#pragma unroll
            for (int s2 = 0; s2 < 2; s2++) {
                int s = t + s2 * 256;
                int row = s >> 2, part = s & 3;
                uint32_t dst = ob + row * 80 + part * 16;
                const void* sp = src + (size_t)(r0g + row) * K + k0 + part * 8;
                CP_ASYNC16(dst, sp);
            }
        }
        CP_COMMIT();
    };

    issue(0, 0);
    for (int c = 0; c < NCH; c++) {
        if (c + 1 < NCH) { issue(c + 1, (c + 1) & 1); CP_WAIT1(); }
        else             { CP_WAIT0(); }
        __syncthreads();
        const uint32_t bb = sb + (c & 1) * STG;
#pragma unroll
        for (int ks = 0; ks < 32; ks += 16) {
            uint32_t bh[4][2], bl[4][2];
#pragma unroll
            for (int g2 = 0; g2 < 2; g2++) {
                int n0 = wn * 32 + g2 * 16;
                int r = n0 + (lane & 7) + (lane >> 4) * 8;
                int cc = ks + ((lane >> 3) & 1) * 8;
                uint32_t off = r * 80 + cc * 2;
                uint32_t r0, r1, r2, r3;
                LDSM_X4(r0, r1, r2, r3, bb + BH_OFF + off);
                bh[2 * g2 + 0][0] = r0; bh[2 * g2 + 0][1] = r1;
                bh[2 * g2 + 1][0] = r2; bh[2 * g2 + 1][1] = r3;
                if (SPLIT) {
                    LDSM_X4(r0, r1, r2, r3, bb + 3 * OP_B + off);
                    bl[2 * g2 + 0][0] = r0; bl[2 * g2 + 0][1] = r1;
                    bl[2 * g2 + 1][0] = r2; bl[2 * g2 + 1][1] = r3;
                }
            }
#pragma unroll
            for (int mi = 0; mi < 4; mi++) {
                int m0 = wm * 64 + mi * 16;
                int r = m0 + (lane & 7) + ((lane >> 3) & 1) * 8;
                int cc = ks + (lane >> 4) * 8;
                uint32_t off = r * 80 + cc * 2;
                uint32_t ah[4], al[4];
                LDSM_X4(ah[0], ah[1], ah[2], ah[3], bb + 0 * OP_B + off);
                if (SPLIT) LDSM_X4(al[0], al[1], al[2], al[3], bb + 1 * OP_B + off);
#pragma unroll
                for (int ni = 0; ni < 4; ni++) {
                    mma_bf16(acc[mi][ni], ah, bh[ni]);
                    if (SPLIT) {
                        mma_bf16(acc[mi][ni], ah, bl[ni]);
                        mma_bf16(acc[mi][ni], al, bh[ni]);
                    }
                }
            }
        }
        __syncthreads();
    }

    // ---------------- epilogue ----------------
    const int g = lane >> 2, tid4 = lane & 3;
    if (EPI == 6) {
        unsigned long long best[8];
#pragma unroll
        for (int i = 0; i < 8; i++) best[i] = 0ull;
#pragma unroll
        for (int mi = 0; mi < 4; mi++)
#pragma unroll
            for (int ni = 0; ni < 4; ni++)
#pragma unroll
                for (int rr = 0; rr < 4; rr++) {
                    int ri = mi * 2 + ((rr >> 1) & 1);
                    int lcol = wn * 32 + ni * 8 + tid4 * 2 + (rr & 1);
                    int sidx = (col0 >= NGC) ? (col0 - NGC + lcol) : (col0 + lcol);
                    uint32_t u = fmap(acc[mi][ni][rr]);
                    unsigned long long p =
                        ((unsigned long long)u << 32) | (uint32_t)(~sidx);
                    if (p > best[ri]) best[ri] = p;
                }
#pragma unroll
        for (int i = 0; i < 8; i++)
#pragma unroll
            for (int o = 1; o < 4; o <<= 1) {
                unsigned long long ov = __shfl_xor_sync(0xffffffffu, best[i], o);
                if (ov > best[i]) best[i] = ov;
            }
        unsigned long long* S = (unsigned long long*)smem;
        if (tid4 == 0) {
#pragma unroll
            for (int mi = 0; mi < 4; mi++)
#pragma unroll
                for (int b = 0; b < 2; b++) {
                    int lrow = wm * 64 + mi * 16 + g + b * 8;
                    S[lrow * 4 + wn] = best[mi * 2 + b];
                }
        }
        __syncthreads();
        if (t < 128) {
            unsigned long long m = S[t * 4];
#pragma unroll
            for (int w = 1; w < 4; w++) if (S[t * 4 + w] > m) m = S[t * 4 + w];
            unsigned long long* tgt = (col0 >= NGC) ? AMAXL : AMAXG;
            atomicMax(&tgt[row0 + t], m);
        }
        return;
    }

    float absSum = 0.f;
#pragma unroll
    for (int mi = 0; mi < 4; mi++) {
#pragma unroll
        for (int ni = 0; ni < 4; ni++) {
#pragma unroll
            for (int rr = 0; rr < 4; rr++) {
                int r = row0 + wm * 64 + mi * 16 + g + ((rr >> 1) & 1) * 8;
                int cidx = col0 + wn * 32 + ni * 8 + tid4 * 2 + (rr & 1);
                float v = acc[mi][ni][rr];
                size_t idx = (size_t)r * ldc + cidx;
                if (EPI == 0) C[idx] = v;
                else if (EPI == 1) {
                    v = fmaxf(v + bias[cidx], 0.f);
                    __nv_bfloat16 h, l; split2(v, h, l);
                    Oh[idx] = h; Ol[idx] = l;
                } else if (EPI == 2) {
                    v += bias[cidx];
                    C[idx] = v; C2[idx] = v;
                    Oh[idx] = __float2bfloat16(v);
                } else if (EPI == 3) {
                    v += bias[cidx];
                    C[idx] = 1.f / (1.f + __expf(-v));
                } else if (EPI == 4) {
                    C[idx] = v; absSum += fabsf(v);
                } else if (EPI == 5) {
                    C[idx] = Zin[idx] - Gt[idx] * v;
                }
            }
        }
    }
    if (EPI == 4) {
#pragma unroll
        for (int o = 16; o > 0; o >>= 1) absSum += __shfl_xor_sync(0xffffffffu, absSum, o);
        if (lane == 0) atomicAdd(&LOSSACC[col0 >= NGC ? 1 : 0], (double)absSum);
    }
}

// ===================== driver ===============================================
extern "C" void kernel_launch(void* const* d_in, const int* in_sizes, int n_in,
                              void* d_out, int out_size) {
    const float* content = (const float*)d_in[0];
    const float* noise   = (const float*)d_in[1];
    const float* W1 = (const float*)d_in[2];
    const float* b1 = (const float*)d_in[3];
    const float* W2 = (const float*)d_in[4];
    const float* b2 = (const float*)d_in[5];
    const float* Wg = (const float*)d_in[6];
    const float* bg = (const float*)d_in[7];
    const float* gdict = (const float*)d_in[8];
    const float* ldict = (const float*)d_in[9];

    float* out = (float*)d_out;
    float* out_zc   = out;                        // [NT*DD]
    float* out_loss = out + (size_t)NT * DD;      // [1]
    float* out_zp   = out_loss + 1;               // [NT*DD] 4B-aligned only
    float* out_u    = out_zp + (size_t)NT * DD;   // [NT*DD] 4B-aligned only

#define SYM(T, p, s) T* p; cudaGetSymbolAddress((void**)&p, s)
    SYM(float, LOG_p, LOGITS);  SYM(float, CMB_p, COMBINED);
    SYM(__nv_bfloat16, CTh_p, CTh);  SYM(__nv_bfloat16, CTl_p, CTl);
    SYM(__nv_bfloat16, UNh_p, UNh);
    SYM(__nv_bfloat16, Hh_p, Hh);    SYM(__nv_bfloat16, Hl_p, Hl);
    SYM(__nv_bfloat16, ZPh_p, ZPh);
    SYM(__nv_bfloat16, ZNh_p, ZNh);
    SYM(__nv_bfloat16, WTSh_p, WTSh);
    SYM(__nv_bfloat16, DICh_p, DICh);
    SYM(__nv_bfloat16, CMBh_p, CMBh);
    SYM(__nv_bfloat16, CMBTh_p, CMBTh);
    SYM(__nv_bfloat16, W1Th_p, W1Th); SYM(__nv_bfloat16, W1Tl_p, W1Tl);
    SYM(__nv_bfloat16, W2Th_p, W2Th); SYM(__nv_bfloat16, W2Tl_p, W2Tl);
    SYM(__nv_bfloat16, WgTh_p, WgTh);
    SYM(float, ZP_p, ZPROJ); SYM(float, GATE_p, GATE);

    const int SM1 = 8 * OP_B;   // split GEMM: 81920
    const int SM0 = 4 * OP_B;   // 1-pass GEMM: 40960
    cudaFuncSetAttribute(gemm_mma<6, 0>, cudaFuncAttributeMaxDynamicSharedMemorySize, SM0);
    cudaFuncSetAttribute(gemm_mma<4, 0>, cudaFuncAttributeMaxDynamicSharedMemorySize, SM0);
    cudaFuncSetAttribute(gemm_mma<3, 0>, cudaFuncAttributeMaxDynamicSharedMemorySize, SM0);
    cudaFuncSetAttribute(gemm_mma<5, 0>, cudaFuncAttributeMaxDynamicSharedMemorySize, SM0);
    cudaFuncSetAttribute(gemm_mma<1, 1>, cudaFuncAttributeMaxDynamicSharedMemorySize, SM1);
    cudaFuncSetAttribute(gemm_mma<2, 1>, cudaFuncAttributeMaxDynamicSharedMemorySize, SM1);

    // 1. zero + operand conversions
    zero_kernel<<<(NCC * DD + 255) / 256, 256>>>();
    split_kernel<<<2048, 256>>>(content, CTh_p, CTl_p, (size_t)NT * DD);
    split_kernel<<<256, 256>>>(gdict, DICh_p, nullptr, (size_t)NGC * DD);
    split_kernel<<<64, 256>>>(ldict, DICh_p + (size_t)NGC * DD, nullptr, (size_t)NLC * DD);
    tsplit_kernel<<<dim3(DD / 32, DD / 32), dim3(32, 32)>>>(W1, W1Th_p, W1Tl_p, DD, DD);
    tsplit_kernel<<<dim3(DD / 32, DD / 32), dim3(32, 32)>>>(W2, W2Th_p, W2Tl_p, DD, DD);
    tsplit_kernel<<<dim3(DD / 32, DD / 32), dim3(32, 32)>>>(Wg, WgTh_p, nullptr, DD, DD);
    unorm_kernel<<<NT, 256>>>(noise, out_u);

    // 2. assignment sims over OLD dicts, argmax fused (1-pass bf16, no C store)
    gemm_mma<6, 0><<<dim3(NCC / 128, NT / 128), 256, SM0>>>(
        UNh_p, nullptr, DICh_p, nullptr, DD, NCC, nullptr, nullptr,
        nullptr, nullptr, nullptr, nullptr, nullptr);
    scatter_kernel<<<NT, 256>>>();
    dictupd_kernel<<<NCC, 256>>>(gdict, ldict);
    tsplit_kernel<<<dim3(DD / 32, NCC / 32), dim3(32, 32)>>>(CMB_p, CMBTh_p, nullptr, NCC, DD);

    // 3. projector chain (z_proj fp32-effective 3-pass; gate 1-pass)
    gemm_mma<1, 1><<<dim3(DD / 128, NT / 128), 256, SM1>>>(
        CTh_p, CTl_p, W1Th_p, W1Tl_p, DD, DD, nullptr, b1,
        Hh_p, Hl_p, nullptr, nullptr, nullptr);
    gemm_mma<2, 1><<<dim3(DD / 128, NT / 128), 256, SM1>>>(
        Hh_p, Hl_p, W2Th_p, W2Tl_p, DD, DD, ZP_p, b2,
        ZPh_p, nullptr, out_zp, nullptr, nullptr);
    gemm_mma<3, 0><<<dim3(DD / 128, NT / 128), 256, SM0>>>(
        ZPh_p, nullptr, WgTh_p, nullptr, DD, DD, GATE_p, bg,
        nullptr, nullptr, nullptr, nullptr, nullptr);
    znorm_kernel<<<NT, 256>>>();

    // 4. logits over NEW dicts (1-pass + loss epilogue) -> softmax -> combine (1-pass)
    gemm_mma<4, 0><<<dim3(NCC / 128, NT / 128), 256, SM0>>>(
        ZNh_p, nullptr, CMBh_p, nullptr, DD, NCC, LOG_p, nullptr,
        nullptr, nullptr, nullptr, nullptr, nullptr);
    softmax_kernel<<<NT, 256>>>();
    gemm_mma<5, 0><<<dim3(DD / 128, NT / 128), 256, SM0>>>(
        WTSh_p, nullptr, CMBTh_p, nullptr, NCC, DD, out_zc, nullptr,
        nullptr, nullptr, nullptr, content, GATE_p);
    finalize_kernel<<<1, 1>>>(out_loss);
}

// round 12
// speedup vs baseline: 3.3631x; 1.0110x over previous
#include <cuda_runtime.h>
#include <cuda_bf16.h>
#include <math.h>
#include <cstdint>

#define NT 32768      // B*L tokens
#define DD 1024
#define NGC 1024
#define NLC 256
#define NCC 1280      // NGC + NLC
#define EPSN 1e-12f

// ===================== helpers ==============================================
__device__ __forceinline__ uint32_t smem_u32(const void* p) {
    uint32_t a;
    asm("{ .reg .u64 t; cvta.to.shared.u64 t, %1; cvt.u32.u64 %0, t; }" : "=r"(a) : "l"(p));
    return a;
}

#define LDSM_X4(r0, r1, r2, r3, addr) \
    asm volatile("ldmatrix.sync.aligned.m8n8.x4.shared.b16 {%0,%1,%2,%3}, [%4];" \
                 : "=r"(r0), "=r"(r1), "=r"(r2), "=r"(r3) : "r"(addr))

__device__ __forceinline__ void mma_bf16(float* c, const uint32_t* a, const uint32_t* b) {
    asm volatile(
        "mma.sync.aligned.m16n8k16.row.col.f32.bf16.bf16.f32 "
        "{%0,%1,%2,%3}, {%4,%5,%6,%7}, {%8,%9}, {%0,%1,%2,%3};"
        : "+f"(c[0]), "+f"(c[1]), "+f"(c[2]), "+f"(c[3])
        : "r"(a[0]), "r"(a[1]), "r"(a[2]), "r"(a[3]), "r"(b[0]), "r"(b[1]));
}

#define CP_ASYNC16(dst, src) \
    asm volatile("cp.async.cg.shared.global [%0], [%1], 16;" :: "r"(dst), "l"(src) : "memory")
#define CP_COMMIT() asm volatile("cp.async.commit_group;" ::: "memory")
#define CP_WAIT1()  asm volatile("cp.async.wait_group 1;" ::: "memory")
#define CP_WAIT0()  asm volatile("cp.async.wait_group 0;" ::: "memory")

__device__ __forceinline__ void split2(float x, __nv_bfloat16& h, __nv_bfloat16& l) {
    h = __float2bfloat16(x);
    l = __float2bfloat16(x - __bfloat162float(h));
}

// monotonic float->u32 mapping (order-preserving for all finite floats)
__device__ __forceinline__ uint32_t fmap(float f) {
    uint32_t u = __float_as_uint(f);
    return (u & 0x80000000u) ? ~u : (u | 0x80000000u);
}

// ===================== scratch ==============================================
__device__ float COMBINED[(size_t)NCC * DD];
__device__ __align__(16) float SUMS[(size_t)NCC * DD];
__device__ float COUNTS[NCC];
__device__ unsigned long long AMAXG[NT];   // packed (mapped_val<<32)|~idx
__device__ unsigned long long AMAXL[NT];
__device__ double LOSSACC[3];

#define BUF(name, n) __device__ __align__(256) __nv_bfloat16 name[(size_t)(n)]
BUF(CTh, NT* DD);  BUF(CTl, NT* DD);
BUF(UNh, NT* DD);
BUF(Hh,  NT* DD);  BUF(Hl,  NT* DD);
BUF(ZPh, NT* DD);
BUF(ZNh, NT* DD);
BUF(GATEh, NT* DD);
BUF(LOGh, NT* NCC);
BUF(WTSh, NT* NCC);
BUF(DICh, NCC* DD);
BUF(CMBh, NCC* DD);
BUF(CMBTh, DD* NCC);
BUF(W1Th, DD* DD); BUF(W1Tl, DD* DD);
BUF(W2Th, DD* DD); BUF(W2Tl, DD* DD);
BUF(WgTh, DD* DD);

// ===================== small kernels ========================================
__global__ void zero_kernel() {
    size_t i = (size_t)blockIdx.x * blockDim.x + threadIdx.x;
    size_t tot = (size_t)NCC * DD;
    if (i < tot) SUMS[i] = 0.f;
    if (i < NCC) COUNTS[i] = 0.f;
    if (i < NT) { AMAXG[i] = 0ull; AMAXL[i] = 0ull; }
    if (i < 3) LOSSACC[i] = 0.0;
}

__global__ __launch_bounds__(256) void split_kernel(const float* __restrict__ src,
                                                    __nv_bfloat16* __restrict__ dh,
                                                    __nv_bfloat16* __restrict__ dl, size_t n) {
    for (size_t i = (size_t)blockIdx.x * blockDim.x + threadIdx.x; i < n;
         i += (size_t)gridDim.x * blockDim.x) {
        __nv_bfloat16 h, l;
        split2(src[i], h, l);
        dh[i] = h;
        if (dl) dl[i] = l;
    }
}

// W[R,C] -> out[C,R] with bf16 split (ol may be null)
__global__ void tsplit_kernel(const float* __restrict__ W,
                              __nv_bfloat16* __restrict__ oh, __nv_bfloat16* __restrict__ ol,
                              int R, int Cc) {
    __shared__ float tile[32][33];
    int bx = blockIdx.x, by = blockIdx.y;
    int x = bx * 32 + threadIdx.x;
    int y = by * 32 + threadIdx.y;
    tile[threadIdx.y][threadIdx.x] = W[(size_t)y * Cc + x];
    __syncthreads();
    int orow = bx * 32 + threadIdx.y;
    int ocol = by * 32 + threadIdx.x;
    __nv_bfloat16 h, l;
    split2(tile[threadIdx.x][threadIdx.y], h, l);
    oh[(size_t)orow * R + ocol] = h;
    if (ol) ol[(size_t)orow * R + ocol] = l;
}

__global__ __launch_bounds__(256) void unorm_kernel(const float* __restrict__ u,
                                                    float* __restrict__ out_u) {
    int row = blockIdx.x, t = threadIdx.x;
    const float* ur = u + (size_t)row * DD;
    float v[4]; float ss = 0.f;
#pragma unroll
    for (int q = 0; q < 4; q++) { v[q] = ur[t + q * 256]; ss += v[q] * v[q]; }
    __shared__ float red[256];
    red[t] = ss; __syncthreads();
    for (int s = 128; s > 0; s >>= 1) { if (t < s) red[t] += red[t + s]; __syncthreads(); }
    float inv = 1.f / fmaxf(sqrtf(red[0]), EPSN);
    size_t base = (size_t)row * DD;
#pragma unroll
    for (int q = 0; q < 4; q++) {
        int j = t + q * 256;
        out_u[base + j] = v[q];
        UNh[base + j] = __float2bfloat16(v[q] * inv);
    }
}

// reads z_proj from out_zp (fp32, scalar) and u_norm from UNh (bf16)
__global__ __launch_bounds__(256) void znorm_kernel(const float* __restrict__ zp) {
    int row = blockIdx.x, t = threadIdx.x;
    size_t base = (size_t)row * DD;
    float v[4]; float ss = 0.f, dp = 0.f;
#pragma unroll
    for (int q = 0; q < 4; q++) {
        int j = t + q * 256;
        v[q] = zp[base + j];
        ss += v[q] * v[q];
        dp += v[q] * __bfloat162float(UNh[base + j]);
    }
    __shared__ float redA[256];
    __shared__ float redB[256];
    redA[t] = ss; redB[t] = dp; __syncthreads();
    for (int s = 128; s > 0; s >>= 1) {
        if (t < s) { redA[t] += redA[t + s]; redB[t] += redB[t + s]; }
        __syncthreads();
    }
    float inv = 1.f / fmaxf(sqrtf(redA[0]), EPSN);
#pragma unroll
    for (int q = 0; q < 4; q++) {
        int j = t + q * 256;
        ZNh[base + j] = __float2bfloat16(v[q] * inv);
    }
    if (t == 0) atomicAdd(&LOSSACC[2], (double)(fabsf(redB[0]) * inv));
}

__global__ __launch_bounds__(256) void scatter_kernel() {
    int row = blockIdx.x, t = threadIdx.x;
    int ig = (int)(~(uint32_t)AMAXG[row]);
    int il = (int)(~(uint32_t)AMAXL[row]);
    const __nv_bfloat16* u = UNh + (size_t)row * DD;
    int j = t * 4;
    uint2 raw = *(const uint2*)(u + j);
    __nv_bfloat162 p0 = *reinterpret_cast<__nv_bfloat162*>(&raw.x);
    __nv_bfloat162 p1 = *reinterpret_cast<__nv_bfloat162*>(&raw.y);
    float4 v = make_float4(__low2float(p0), __high2float(p0),
                           __low2float(p1), __high2float(p1));
    atomicAdd((float4*)(SUMS + (size_t)ig * DD + j), v);
    atomicAdd((float4*)(SUMS + (size_t)(NGC + il) * DD + j), v);
    if (t == 0) { atomicAdd(&COUNTS[ig], 1.f); atomicAdd(&COUNTS[NGC + il], 1.f); }
}

__global__ __launch_bounds__(256) void dictupd_kernel(const float* __restrict__ gd,
                                                      const float* __restrict__ ld) {
    int k = blockIdx.x, t = threadIdx.x;
    const float* old = (k < NGC) ? (gd + (size_t)k * DD) : (ld + (size_t)(k - NGC) * DD);
    float m = (k < NGC) ? 0.999f : 0.8f;
    float cnt = COUNTS[k];
    float up[4]; float ss = 0.f;
#pragma unroll
    for (int q = 0; q < 4; q++) {
        int j = t + q * 256;
        float o = old[j];
        float u;
        if (cnt > 0.f) {
            float mean = SUMS[(size_t)k * DD + j] / fmaxf(cnt, 1.f);
            u = m * o + (1.f - m) * mean;
        } else u = o;
        up[q] = u; ss += u * u;
    }
    __shared__ float red[256];
    red[t] = ss; __syncthreads();
    for (int s = 128; s > 0; s >>= 1) { if (t < s) red[t] += red[t + s]; __syncthreads(); }
    float inv = 1.f / fmaxf(sqrtf(red[0]), EPSN);
    size_t base = (size_t)k * DD;
#pragma unroll
    for (int q = 0; q < 4; q++) {
        int j = t + q * 256;
        float u = up[q] * inv;
        COMBINED[base + j] = u;
        CMBh[base + j] = __float2bfloat16(u);
    }
}

__global__ __launch_bounds__(256) void softmax_kernel() {
    int row = blockIdx.x, t = threadIdx.x;
    const __nv_bfloat16* L = LOGh + (size_t)row * NCC;
    const float invT = 1.f / 0.07f;
    float v[5];
    float mx = -3.0e38f;
#pragma unroll
    for (int q = 0; q < 5; q++) {
        v[q] = __bfloat162float(L[t + q * 256]) * invT;
        mx = fmaxf(mx, v[q]);
    }
    __shared__ float red[256];
    red[t] = mx; __syncthreads();
    for (int s = 128; s > 0; s >>= 1) { if (t < s) red[t] = fmaxf(red[t], red[t + s]); __syncthreads(); }
    mx = red[0]; __syncthreads();
    float sum = 0.f;
#pragma unroll
    for (int q = 0; q < 5; q++) { v[q] = __expf(v[q] - mx); sum += v[q]; }
    red[t] = sum; __syncthreads();
    for (int s = 128; s > 0; s >>= 1) { if (t < s) red[t] += red[t + s]; __syncthreads(); }
    float inv = 1.f / red[0];
    size_t base = (size_t)row * NCC;
#pragma unroll
    for (int q = 0; q < 5; q++)
        WTSh[base + t + q * 256] = __float2bfloat16(v[q] * inv);
}

__global__ void finalize_kernel(float* __restrict__ out_loss) {
    double lg = LOSSACC[0] / ((double)NT * (double)NGC);
    double ll = LOSSACC[1] / ((double)NT * (double)NLC);
    double ldir = LOSSACC[2] / (double)NT;
    *out_loss = (float)(lg + ll + ldir);
}

// ===================== mma.sync GEMM (split or single pass) =================
// C[M,N] = A[M,K] * B[N,K]^T.  SPLIT=1: fp32-effective 3-pass; SPLIT=0: bf16 1-pass.
// CTA 128x128, 8 warps (2x4), warp tile 64x32 via m16n8k16, cp.async 2-stage.
// EPI: 0 store C | 1 relu+bias->Oh/Ol | 2 bias->C2(scalar fp32)+Oh | 3 sigmoid+bias->Oh
//      4 Oh + abs-loss | 5 C=Zin-Gth*acc | 6 fused row argmax (no store)
#define OP_B 10240               // bytes per operand tile (128*80)

template <int EPI, int SPLIT>
__global__ __launch_bounds__(256, 2) void gemm_mma(
    const __nv_bfloat16* __restrict__ Ah, const __nv_bfloat16* __restrict__ Al,
    const __nv_bfloat16* __restrict__ Bh, const __nv_bfloat16* __restrict__ Bl,
    int K, int ldc,
    float* __restrict__ C, const float* __restrict__ bias,
    __nv_bfloat16* __restrict__ Oh, __nv_bfloat16* __restrict__ Ol,
    float* __restrict__ C2,
    const float* __restrict__ Zin, const __nv_bfloat16* __restrict__ Gth)
{
    constexpr int NOPS = SPLIT ? 4 : 2;
    constexpr int STG = NOPS * OP_B;
    constexpr int BH_OFF = SPLIT ? 2 * OP_B : OP_B;

    extern __shared__ char smem[];
    const uint32_t sb = smem_u32(smem);
    const int t = threadIdx.x;
    const int lane = t & 31, wid = t >> 5;
    const int wm = wid & 1, wn = wid >> 1;          // 2 x 4 warp grid
    const int row0 = blockIdx.y * 128, col0 = blockIdx.x * 128;

    float acc[4][4][4];
#pragma unroll
    for (int mi = 0; mi < 4; mi++)
#pragma unroll
        for (int ni = 0; ni < 4; ni++)
#pragma unroll
            for (int rr = 0; rr < 4; rr++) acc[mi][ni][rr] = 0.f;

    const int NCH = K >> 5;
    const __nv_bfloat16* srcs[4] = {Ah, SPLIT ? Al : Bh, Bh, Bl};
    const int rbase[4] = {row0, SPLIT ? row0 : col0, col0, col0};

    auto issue = [&](int c, int buf) {
        const int k0 = c << 5;
        const uint32_t base = sb + buf * STG;
#pragma unroll
        for (int o = 0; o < NOPS; o++) {
            const __nv_bfloat16* src = srcs[o];
            const int r0g = rbase[o];
            const uint32_t ob = base + o * OP_B;
#pragma unroll
            for (int s2 = 0; s2 < 2; s2++) {
                int s = t + s2 * 256;
                int row = s >> 2, part = s & 3;
                uint32_t dst = ob + row * 80 + part * 16;
                const void* sp = src + (size_t)(r0g + row) * K + k0 + part * 8;
                CP_ASYNC16(dst, sp);
            }
        }
        CP_COMMIT();
    };

    issue(0, 0);
    for (int c = 0; c < NCH; c++) {
        if (c + 1 < NCH) { issue(c + 1, (c + 1) & 1); CP_WAIT1(); }
        else             { CP_WAIT0(); }
        __syncthreads();
        const uint32_t bb = sb + (c & 1) * STG;
#pragma unroll
        for (int ks = 0; ks < 32; ks += 16) {
            uint32_t bh[4][2], bl[4][2];
#pragma unroll
            for (int g2 = 0; g2 < 2; g2++) {
                int n0 = wn * 32 + g2 * 16;
                int r = n0 + (lane & 7) + (lane >> 4) * 8;
                int cc = ks + ((lane >> 3) & 1) * 8;
                uint32_t off = r * 80 + cc * 2;
                uint32_t r0, r1, r2, r3;
                LDSM_X4(r0, r1, r2, r3, bb + BH_OFF + off);
                bh[2 * g2 + 0][0] = r0; bh[2 * g2 + 0][1] = r1;
                bh[2 * g2 + 1][0] = r2; bh[2 * g2 + 1][1] = r3;
                if (SPLIT) {
                    LDSM_X4(r0, r1, r2, r3, bb + 3 * OP_B + off);
                    bl[2 * g2 + 0][0] = r0; bl[2 * g2 + 0][1] = r1;
                    bl[2 * g2 + 1][0] = r2; bl[2 * g2 + 1][1] = r3;
                }
            }
#pragma unroll
            for (int mi = 0; mi < 4; mi++) {
                int m0 = wm * 64 + mi * 16;
                int r = m0 + (lane & 7) + ((lane >> 3) & 1) * 8;
                int cc = ks + (lane >> 4) * 8;
                uint32_t off = r * 80 + cc * 2;
                uint32_t ah[4], al[4];
                LDSM_X4(ah[0], ah[1], ah[2], ah[3], bb + 0 * OP_B + off);
                if (SPLIT) LDSM_X4(al[0], al[1], al[2], al[3], bb + 1 * OP_B + off);
#pragma unroll
                for (int ni = 0; ni < 4; ni++) {
                    mma_bf16(acc[mi][ni], ah, bh[ni]);
                    if (SPLIT) {
                        mma_bf16(acc[mi][ni], ah, bl[ni]);
                        mma_bf16(acc[mi][ni], al, bh[ni]);
                    }
                }
            }
        }
        __syncthreads();
    }

    // ---------------- epilogue ----------------
    const int g = lane >> 2, tid4 = lane & 3;
    if (EPI == 6) {
        unsigned long long best[8];
#pragma unroll
        for (int i = 0; i < 8; i++) best[i] = 0ull;
#pragma unroll
        for (int mi = 0; mi < 4; mi++)
#pragma unroll
            for (int ni = 0; ni < 4; ni++)
#pragma unroll
                for (int rr = 0; rr < 4; rr++) {
                    int ri = mi * 2 + ((rr >> 1) & 1);
                    int lcol = wn * 32 + ni * 8 + tid4 * 2 + (rr & 1);
                    int sidx = (col0 >= NGC) ? (col0 - NGC + lcol) : (col0 + lcol);
                    uint32_t u = fmap(acc[mi][ni][rr]);
                    unsigned long long p =
                        ((unsigned long long)u << 32) | (uint32_t)(~sidx);
                    if (p > best[ri]) best[ri] = p;
                }
#pragma unroll
        for (int i = 0; i < 8; i++)
#pragma unroll
            for (int o = 1; o < 4; o <<= 1) {
                unsigned long long ov = __shfl_xor_sync(0xffffffffu, best[i], o);
                if (ov > best[i]) best[i] = ov;
            }
        unsigned long long* S = (unsigned long long*)smem;
        if (tid4 == 0) {
#pragma unroll
            for (int mi = 0; mi < 4; mi++)
#pragma unroll
                for (int b = 0; b < 2; b++) {
                    int lrow = wm * 64 + mi * 16 + g + b * 8;
                    S[lrow * 4 + wn] = best[mi * 2 + b];
                }
        }
        __syncthreads();
        if (t < 128) {
            unsigned long long m = S[t * 4];
#pragma unroll
            for (int w = 1; w < 4; w++) if (S[t * 4 + w] > m) m = S[t * 4 + w];
            unsigned long long* tgt = (col0 >= NGC) ? AMAXL : AMAXG;
            atomicMax(&tgt[row0 + t], m);
        }
        return;
    }

    float absSum = 0.f;
#pragma unroll
    for (int mi = 0; mi < 4; mi++) {
#pragma unroll
        for (int ni = 0; ni < 4; ni++) {
#pragma unroll
            for (int rr = 0; rr < 4; rr++) {
                int r = row0 + wm * 64 + mi * 16 + g + ((rr >> 1) & 1) * 8;
                int cidx = col0 + wn * 32 + ni * 8 + tid4 * 2 + (rr & 1);
                float v = acc[mi][ni][rr];
                size_t idx = (size_t)r * ldc + cidx;
                if (EPI == 0) C[idx] = v;
                else if (EPI == 1) {
                    v = fmaxf(v + bias[cidx], 0.f);
                    __nv_bfloat16 h, l; split2(v, h, l);
                    Oh[idx] = h; Ol[idx] = l;
                } else if (EPI == 2) {
                    v += bias[cidx];
                    C2[idx] = v;
                    Oh[idx] = __float2bfloat16(v);
                } else if (EPI == 3) {
                    v += bias[cidx];
                    Oh[idx] = __float2bfloat16(1.f / (1.f + __expf(-v)));
                } else if (EPI == 4) {
                    Oh[idx] = __float2bfloat16(v);
                    absSum += fabsf(v);
                } else if (EPI == 5) {
                    C[idx] = Zin[idx] - __bfloat162float(Gth[idx]) * v;
                }
            }
        }
    }
    if (EPI == 4) {
#pragma unroll
        for (int o = 16; o > 0; o >>= 1) absSum += __shfl_xor_sync(0xffffffffu, absSum, o);
        if (lane == 0) atomicAdd(&LOSSACC[col0 >= NGC ? 1 : 0], (double)absSum);
    }
}

// ===================== driver ===============================================
extern "C" void kernel_launch(void* const* d_in, const int* in_sizes, int n_in,
                              void* d_out, int out_size) {
    const float* content = (const float*)d_in[0];
    const float* noise   = (const float*)d_in[1];
    const float* W1 = (const float*)d_in[2];
    const float* b1 = (const float*)d_in[3];
    const float* W2 = (const float*)d_in[4];
    const float* b2 = (const float*)d_in[5];
    const float* Wg = (const float*)d_in[6];
    const float* bg = (const float*)d_in[7];
    const float* gdict = (const float*)d_in[8];
    const float* ldict = (const float*)d_in[9];

    float* out = (float*)d_out;
    float* out_zc   = out;                        // [NT*DD]
    float* out_loss = out + (size_t)NT * DD;      // [1]
    float* out_zp   = out_loss + 1;               // [NT*DD] 4B-aligned only
    float* out_u    = out_zp + (size_t)NT * DD;   // [NT*DD] 4B-aligned only

#define SYM(T, p, s) T* p; cudaGetSymbolAddress((void**)&p, s)
    SYM(float, CMB_p, COMBINED);
    SYM(__nv_bfloat16, CTh_p, CTh);  SYM(__nv_bfloat16, CTl_p, CTl);
    SYM(__nv_bfloat16, UNh_p, UNh);
    SYM(__nv_bfloat16, Hh_p, Hh);    SYM(__nv_bfloat16, Hl_p, Hl);
    SYM(__nv_bfloat16, ZPh_p, ZPh);
    SYM(__nv_bfloat16, ZNh_p, ZNh);
    SYM(__nv_bfloat16, GATEh_p, GATEh);
    SYM(__nv_bfloat16, LOGh_p, LOGh);
    SYM(__nv_bfloat16, WTSh_p, WTSh);
    SYM(__nv_bfloat16, DICh_p, DICh);
    SYM(__nv_bfloat16, CMBh_p, CMBh);
    SYM(__nv_bfloat16, CMBTh_p, CMBTh);
    SYM(__nv_bfloat16, W1Th_p, W1Th); SYM(__nv_bfloat16, W1Tl_p, W1Tl);
    SYM(__nv_bfloat16, W2Th_p, W2Th); SYM(__nv_bfloat16, W2Tl_p, W2Tl);
    SYM(__nv_bfloat16, WgTh_p, WgTh);

    const int SM1 = 8 * OP_B;   // split GEMM: 81920
    const int SM0 = 4 * OP_B;   // 1-pass GEMM: 40960
    cudaFuncSetAttribute(gemm_mma<6, 0>, cudaFuncAttributeMaxDynamicSharedMemorySize, SM0);
    cudaFuncSetAttribute(gemm_mma<4, 0>, cudaFuncAttributeMaxDynamicSharedMemorySize, SM0);
    cudaFuncSetAttribute(gemm_mma<3, 0>, cudaFuncAttributeMaxDynamicSharedMemorySize, SM0);
    cudaFuncSetAttribute(gemm_mma<5, 0>, cudaFuncAttributeMaxDynamicSharedMemorySize, SM0);
    cudaFuncSetAttribute(gemm_mma<1, 1>, cudaFuncAttributeMaxDynamicSharedMemorySize, SM1);
    cudaFuncSetAttribute(gemm_mma<2, 1>, cudaFuncAttributeMaxDynamicSharedMemorySize, SM1);

    // 1. zero + operand conversions
    zero_kernel<<<(NCC * DD + 255) / 256, 256>>>();
    split_kernel<<<2048, 256>>>(content, CTh_p, CTl_p, (size_t)NT * DD);
    split_kernel<<<256, 256>>>(gdict, DICh_p, nullptr, (size_t)NGC * DD);
    split_kernel<<<64, 256>>>(ldict, DICh_p + (size_t)NGC * DD, nullptr, (size_t)NLC * DD);
    tsplit_kernel<<<dim3(DD / 32, DD / 32), dim3(32, 32)>>>(W1, W1Th_p, W1Tl_p, DD, DD);
    tsplit_kernel<<<dim3(DD / 32, DD / 32), dim3(32, 32)>>>(W2, W2Th_p, W2Tl_p, DD, DD);
    tsplit_kernel<<<dim3(DD / 32, DD / 32), dim3(32, 32)>>>(Wg, WgTh_p, nullptr, DD, DD);
    unorm_kernel<<<NT, 256>>>(noise, out_u);

    // 2. assignment sims over OLD dicts, argmax fused (1-pass bf16, no store)
    gemm_mma<6, 0><<<dim3(NCC / 128, NT / 128), 256, SM0>>>(
        UNh_p, nullptr, DICh_p, nullptr, DD, NCC, nullptr, nullptr,
        nullptr, nullptr, nullptr, nullptr, nullptr);
    scatter_kernel<<<NT, 256>>>();
    dictupd_kernel<<<NCC, 256>>>(gdict, ldict);
    tsplit_kernel<<<dim3(DD / 32, NCC / 32), dim3(32, 32)>>>(CMB_p, CMBTh_p, nullptr, NCC, DD);

    // 3. projector chain (z_proj fp32-effective 3-pass; gate 1-pass, bf16 out)
    gemm_mma<1, 1><<<dim3(DD / 128, NT / 128), 256, SM1>>>(
        CTh_p, CTl_p, W1Th_p, W1Tl_p, DD, DD, nullptr, b1,
        Hh_p, Hl_p, nullptr, nullptr, nullptr);
    gemm_mma<2, 1><<<dim3(DD / 128, NT / 128), 256, SM1>>>(
        Hh_p, Hl_p, W2Th_p, W2Tl_p, DD, DD, nullptr, b2,
        ZPh_p, nullptr, out_zp, nullptr, nullptr);
    gemm_mma<3, 0><<<dim3(DD / 128, NT / 128), 256, SM0>>>(
        ZPh_p, nullptr, WgTh_p, nullptr, DD, DD, nullptr, bg,
        GATEh_p, nullptr, nullptr, nullptr, nullptr);
    znorm_kernel<<<NT, 256>>>(out_zp);

    // 4. logits over NEW dicts (1-pass, bf16 out + loss epilogue) -> softmax -> combine
    gemm_mma<4, 0><<<dim3(NCC / 128, NT / 128), 256, SM0>>>(
        ZNh_p, nullptr, CMBh_p, nullptr, DD, NCC, nullptr, nullptr,
        LOGh_p, nullptr, nullptr, nullptr, nullptr);
    softmax_kernel<<<NT, 256>>>();
    gemm_mma<5, 0><<<dim3(DD / 128, NT / 128), 256, SM0>>>(
        WTSh_p, nullptr, CMBTh_p, nullptr, NCC, DD, out_zc, nullptr,
        nullptr, nullptr, nullptr, content, GATEh_p);
    finalize_kernel<<<1, 1>>>(out_loss);
}

// round 13
// speedup vs baseline: 3.3748x; 1.0035x over previous
#include <cuda_runtime.h>
#include <cuda_bf16.h>
#include <math.h>
#include <cstdint>

#define NT 32768      // B*L tokens
#define DD 1024
#define NGC 1024
#define NLC 256
#define NCC 1280      // NGC + NLC
#define EPSN 1e-12f

// ===================== helpers ==============================================
__device__ __forceinline__ uint32_t smem_u32(const void* p) {
    uint32_t a;
    asm("{ .reg .u64 t; cvta.to.shared.u64 t, %1; cvt.u32.u64 %0, t; }" : "=r"(a) : "l"(p));
    return a;
}

#define LDSM_X4(r0, r1, r2, r3, addr) \
    asm volatile("ldmatrix.sync.aligned.m8n8.x4.shared.b16 {%0,%1,%2,%3}, [%4];" \
                 : "=r"(r0), "=r"(r1), "=r"(r2), "=r"(r3) : "r"(addr))

__device__ __forceinline__ void mma_bf16(float* c, const uint32_t* a, const uint32_t* b) {
    asm volatile(
        "mma.sync.aligned.m16n8k16.row.col.f32.bf16.bf16.f32 "
        "{%0,%1,%2,%3}, {%4,%5,%6,%7}, {%8,%9}, {%0,%1,%2,%3};"
        : "+f"(c[0]), "+f"(c[1]), "+f"(c[2]), "+f"(c[3])
        : "r"(a[0]), "r"(a[1]), "r"(a[2]), "r"(a[3]), "r"(b[0]), "r"(b[1]));
}

#define CP_ASYNC16(dst, src) \
    asm volatile("cp.async.cg.shared.global [%0], [%1], 16;" :: "r"(dst), "l"(src) : "memory")
#define CP_COMMIT() asm volatile("cp.async.commit_group;" ::: "memory")
#define CP_WAIT2()  asm volatile("cp.async.wait_group 2;" ::: "memory")
#define CP_WAIT1()  asm volatile("cp.async.wait_group 1;" ::: "memory")
#define CP_WAIT0()  asm volatile("cp.async.wait_group 0;" ::: "memory")

__device__ __forceinline__ void split2(float x, __nv_bfloat16& h, __nv_bfloat16& l) {
    h = __float2bfloat16(x);
    l = __float2bfloat16(x - __bfloat162float(h));
}

// monotonic float->u32 mapping (order-preserving for all finite floats)
__device__ __forceinline__ uint32_t fmap(float f) {
    uint32_t u = __float_as_uint(f);
    return (u & 0x80000000u) ? ~u : (u | 0x80000000u);
}

// ===================== scratch ==============================================
__device__ float COMBINED[(size_t)NCC * DD];
__device__ __align__(16) float SUMS[(size_t)NCC * DD];
__device__ float COUNTS[NCC];
__device__ unsigned long long AMAXG[NT];   // packed (mapped_val<<32)|~idx
__device__ unsigned long long AMAXL[NT];
__device__ double LOSSACC[3];

#define BUF(name, n) __device__ __align__(256) __nv_bfloat16 name[(size_t)(n)]
BUF(CTh, NT* DD);  BUF(CTl, NT* DD);
BUF(UNh, NT* DD);
BUF(Hh,  NT* DD);  BUF(Hl,  NT* DD);
BUF(ZPh, NT* DD);
BUF(ZNh, NT* DD);
BUF(GATEh, NT* DD);
BUF(LOGh, NT* NCC);
BUF(WTSh, NT* NCC);
BUF(DICh, NCC* DD);
BUF(CMBh, NCC* DD);
BUF(CMBTh, DD* NCC);
BUF(W1Th, DD* DD); BUF(W1Tl, DD* DD);
BUF(W2Th, DD* DD); BUF(W2Tl, DD* DD);
BUF(WgTh, DD* DD);

// ===================== small kernels ========================================
__global__ void zero_kernel() {
    size_t i = (size_t)blockIdx.x * blockDim.x + threadIdx.x;
    size_t tot = (size_t)NCC * DD;
    if (i < tot) SUMS[i] = 0.f;
    if (i < NCC) COUNTS[i] = 0.f;
    if (i < NT) { AMAXG[i] = 0ull; AMAXL[i] = 0ull; }
    if (i < 3) LOSSACC[i] = 0.0;
}

__global__ __launch_bounds__(256) void split_kernel(const float* __restrict__ src,
                                                    __nv_bfloat16* __restrict__ dh,
                                                    __nv_bfloat16* __restrict__ dl, size_t n) {
    for (size_t i = (size_t)blockIdx.x * blockDim.x + threadIdx.x; i < n;
         i += (size_t)gridDim.x * blockDim.x) {
        __nv_bfloat16 h, l;
        split2(src[i], h, l);
        dh[i] = h;
        if (dl) dl[i] = l;
    }
}

// W[R,C] -> out[C,R] with bf16 split (ol may be null)
__global__ void tsplit_kernel(const float* __restrict__ W,
                              __nv_bfloat16* __restrict__ oh, __nv_bfloat16* __restrict__ ol,
                              int R, int Cc) {
    __shared__ float tile[32][33];
    int bx = blockIdx.x, by = blockIdx.y;
    int x = bx * 32 + threadIdx.x;
    int y = by * 32 + threadIdx.y;
    tile[threadIdx.y][threadIdx.x] = W[(size_t)y * Cc + x];
    __syncthreads();
    int orow = bx * 32 + threadIdx.y;
    int ocol = by * 32 + threadIdx.x;
    __nv_bfloat16 h, l;
    split2(tile[threadIdx.x][threadIdx.y], h, l);
    oh[(size_t)orow * R + ocol] = h;
    if (ol) ol[(size_t)orow * R + ocol] = l;
}

__global__ __launch_bounds__(256) void unorm_kernel(const float* __restrict__ u,
                                                    float* __restrict__ out_u) {
    int row = blockIdx.x, t = threadIdx.x;
    const float* ur = u + (size_t)row * DD;
    float v[4]; float ss = 0.f;
#pragma unroll
    for (int q = 0; q < 4; q++) { v[q] = ur[t + q * 256]; ss += v[q] * v[q]; }
    __shared__ float red[256];
    red[t] = ss; __syncthreads();
    for (int s = 128; s > 0; s >>= 1) { if (t < s) red[t] += red[t + s]; __syncthreads(); }
    float inv = 1.f / fmaxf(sqrtf(red[0]), EPSN);
    size_t base = (size_t)row * DD;
#pragma unroll
    for (int q = 0; q < 4; q++) {
        int j = t + q * 256;
        out_u[base + j] = v[q];
        UNh[base + j] = __float2bfloat16(v[q] * inv);
    }
}

// reads z_proj from out_zp (fp32, scalar) and u_norm from UNh (bf16)
__global__ __launch_bounds__(256) void znorm_kernel(const float* __restrict__ zp) {
    int row = blockIdx.x, t = threadIdx.x;
    size_t base = (size_t)row * DD;
    float v[4]; float ss = 0.f, dp = 0.f;
#pragma unroll
    for (int q = 0; q < 4; q++) {
        int j = t + q * 256;
        v[q] = zp[base + j];
        ss += v[q] * v[q];
        dp += v[q] * __bfloat162float(UNh[base + j]);
    }
    __shared__ float redA[256];
    __shared__ float redB[256];
    redA[t] = ss; redB[t] = dp; __syncthreads();
    for (int s = 128; s > 0; s >>= 1) {
        if (t < s) { redA[t] += redA[t + s]; redB[t] += redB[t + s]; }
        __syncthreads();
    }
    float inv = 1.f / fmaxf(sqrtf(redA[0]), EPSN);
#pragma unroll
    for (int q = 0; q < 4; q++) {
        int j = t + q * 256;
        ZNh[base + j] = __float2bfloat16(v[q] * inv);
    }
    if (t == 0) atomicAdd(&LOSSACC[2], (double)(fabsf(redB[0]) * inv));
}

__global__ __launch_bounds__(256) void scatter_kernel() {
    int row = blockIdx.x, t = threadIdx.x;
    int ig = (int)(~(uint32_t)AMAXG[row]);
    int il = (int)(~(uint32_t)AMAXL[row]);
    const __nv_bfloat16* u = UNh + (size_t)row * DD;
    int j = t * 4;
    uint2 raw = *(const uint2*)(u + j);
    __nv_bfloat162 p0 = *reinterpret_cast<__nv_bfloat162*>(&raw.x);
    __nv_bfloat162 p1 = *reinterpret_cast<__nv_bfloat162*>(&raw.y);
    float4 v = make_float4(__low2float(p0), __high2float(p0),
                           __low2float(p1), __high2float(p1));
    atomicAdd((float4*)(SUMS + (size_t)ig * DD + j), v);
    atomicAdd((float4*)(SUMS + (size_t)(NGC + il) * DD + j), v);
    if (t == 0) { atomicAdd(&COUNTS[ig], 1.f); atomicAdd(&COUNTS[NGC + il], 1.f); }
}

__global__ __launch_bounds__(256) void dictupd_kernel(const float* __restrict__ gd,
                                                      const float* __restrict__ ld) {
    int k = blockIdx.x, t = threadIdx.x;
    const float* old = (k < NGC) ? (gd + (size_t)k * DD) : (ld + (size_t)(k - NGC) * DD);
    float m = (k < NGC) ? 0.999f : 0.8f;
    float cnt = COUNTS[k];
    float up[4]; float ss = 0.f;
#pragma unroll
    for (int q = 0; q < 4; q++) {
        int j = t + q * 256;
        float o = old[j];
        float u;
        if (cnt > 0.f) {
            float mean = SUMS[(size_t)k * DD + j] / fmaxf(cnt, 1.f);
            u = m * o + (1.f - m) * mean;
        } else u = o;
        up[q] = u; ss += u * u;
    }
    __shared__ float red[256];
    red[t] = ss; __syncthreads();
    for (int s = 128; s > 0; s >>= 1) { if (t < s) red[t] += red[t + s]; __syncthreads(); }
    float inv = 1.f / fmaxf(sqrtf(red[0]), EPSN);
    size_t base = (size_t)k * DD;
#pragma unroll
    for (int q = 0; q < 4; q++) {
        int j = t + q * 256;
        float u = up[q] * inv;
        COMBINED[base + j] = u;
        CMBh[base + j] = __float2bfloat16(u);
    }
}

__global__ __launch_bounds__(256) void softmax_kernel() {
    int row = blockIdx.x, t = threadIdx.x;
    const __nv_bfloat16* L = LOGh + (size_t)row * NCC;
    const float invT = 1.f / 0.07f;
    float v[5];
    float mx = -3.0e38f;
#pragma unroll
    for (int q = 0; q < 5; q++) {
        v[q] = __bfloat162float(L[t + q * 256]) * invT;
        mx = fmaxf(mx, v[q]);
    }
    __shared__ float red[256];
    red[t] = mx; __syncthreads();
    for (int s = 128; s > 0; s >>= 1) { if (t < s) red[t] = fmaxf(red[t], red[t + s]); __syncthreads(); }
    mx = red[0]; __syncthreads();
    float sum = 0.f;
#pragma unroll
    for (int q = 0; q < 5; q++) { v[q] = __expf(v[q] - mx); sum += v[q]; }
    red[t] = sum; __syncthreads();
    for (int s = 128; s > 0; s >>= 1) { if (t < s) red[t] += red[t + s]; __syncthreads(); }
    float inv = 1.f / red[0];
    size_t base = (size_t)row * NCC;
#pragma unroll
    for (int q = 0; q < 5; q++)
        WTSh[base + t + q * 256] = __float2bfloat16(v[q] * inv);
}

__global__ void finalize_kernel(float* __restrict__ out_loss) {
    double lg = LOSSACC[0] / ((double)NT * (double)NGC);
    double ll = LOSSACC[1] / ((double)NT * (double)NLC);
    double ldir = LOSSACC[2] / (double)NT;
    *out_loss = (float)(lg + ll + ldir);
}

// ===================== mma.sync GEMM (split or single pass) =================
// C[M,N] = A[M,K] * B[N,K]^T.  SPLIT=1: fp32-effective 3-pass, 2-stage pipe;
//                              SPLIT=0: bf16 1-pass, 3-stage pipe.
// CTA 128x128, 8 warps (2x4), warp tile 64x32 via m16n8k16.
// EPI: 0 store C | 1 relu+bias->Oh/Ol | 2 bias->C2(scalar fp32)+Oh | 3 sigmoid+bias->Oh
//      4 Oh + abs-loss | 5 C=Zin-Gth*acc | 6 fused row argmax (no store)
#define OP_B 10240               // bytes per operand tile (128*80)

template <int EPI, int SPLIT>
__global__ __launch_bounds__(256, 2) void gemm_mma(
    const __nv_bfloat16* __restrict__ Ah, const __nv_bfloat16* __restrict__ Al,
    const __nv_bfloat16* __restrict__ Bh, const __nv_bfloat16* __restrict__ Bl,
    int K, int ldc,
    float* __restrict__ C, const float* __restrict__ bias,
    __nv_bfloat16* __restrict__ Oh, __nv_bfloat16* __restrict__ Ol,
    float* __restrict__ C2,
    const float* __restrict__ Zin, const __nv_bfloat16* __restrict__ Gth)
{
    constexpr int NOPS = SPLIT ? 4 : 2;
    constexpr int STAGES = SPLIT ? 2 : 3;
    constexpr int STG = NOPS * OP_B;
    constexpr int BH_OFF = SPLIT ? 2 * OP_B : OP_B;

    extern __shared__ char smem[];
    const uint32_t sb = smem_u32(smem);
    const int t = threadIdx.x;
    const int lane = t & 31, wid = t >> 5;
    const int wm = wid & 1, wn = wid >> 1;          // 2 x 4 warp grid
    const int row0 = blockIdx.y * 128, col0 = blockIdx.x * 128;

    float acc[4][4][4];
#pragma unroll
    for (int mi = 0; mi < 4; mi++)
#pragma unroll
        for (int ni = 0; ni < 4; ni++)
#pragma unroll
            for (int rr = 0; rr < 4; rr++) acc[mi][ni][rr] = 0.f;

    const int NCH = K >> 5;
    const __nv_bfloat16* srcs[4] = {Ah, SPLIT ? Al : Bh, Bh, Bl};
    const int rbase[4] = {row0, SPLIT ? row0 : col0, col0, col0};

    auto issue = [&](int c, int buf) {
        const int k0 = c << 5;
        const uint32_t base = sb + buf * STG;
#pragma unroll
        for (int o = 0; o < NOPS; o++) {
            const __nv_bfloat16* src = srcs[o];
            const int r0g = rbase[o];
            const uint32_t ob = base + o * OP_B;
#pragma unroll
            for (int s2 = 0; s2 < 2; s2++) {
                int s = t + s2 * 256;
                int row = s >> 2, part = s & 3;
                uint32_t dst = ob + row * 80 + part * 16;
                const void* sp = src + (size_t)(r0g + row) * K + k0 + part * 8;
                CP_ASYNC16(dst, sp);
            }
        }
        CP_COMMIT();
    };

    // prologue: fill STAGES-1 buffers
    issue(0, 0);
    if (STAGES > 2 && NCH > 1) issue(1, 1);

    for (int c = 0; c < NCH; c++) {
        int nxt = c + STAGES - 1;
        if (nxt < NCH) {
            issue(nxt, nxt % STAGES);
            if (STAGES == 3) CP_WAIT2(); else CP_WAIT1();
        } else if (STAGES == 3 && c + 2 == NCH) {
            CP_WAIT1();
        } else {
            CP_WAIT0();
        }
        __syncthreads();
        const uint32_t bb = sb + (c % STAGES) * STG;
#pragma unroll
        for (int ks = 0; ks < 32; ks += 16) {
            uint32_t bh[4][2], bl[4][2];
#pragma unroll
            for (int g2 = 0; g2 < 2; g2++) {
                int n0 = wn * 32 + g2 * 16;
                int r = n0 + (lane & 7) + (lane >> 4) * 8;
                int cc = ks + ((lane >> 3) & 1) * 8;
                uint32_t off = r * 80 + cc * 2;
                uint32_t r0, r1, r2, r3;
                LDSM_X4(r0, r1, r2, r3, bb + BH_OFF + off);
                bh[2 * g2 + 0][0] = r0; bh[2 * g2 + 0][1] = r1;
                bh[2 * g2 + 1][0] = r2; bh[2 * g2 + 1][1] = r3;
                if (SPLIT) {
                    LDSM_X4(r0, r1, r2, r3, bb + 3 * OP_B + off);
                    bl[2 * g2 + 0][0] = r0; bl[2 * g2 + 0][1] = r1;
                    bl[2 * g2 + 1][0] = r2; bl[2 * g2 + 1][1] = r3;
                }
            }
#pragma unroll
            for (int mi = 0; mi < 4; mi++) {
                int m0 = wm * 64 + mi * 16;
                int r = m0 + (lane & 7) + ((lane >> 3) & 1) * 8;
                int cc = ks + (lane >> 4) * 8;
                uint32_t off = r * 80 + cc * 2;
                uint32_t ah[4], al[4];
                LDSM_X4(ah[0], ah[1], ah[2], ah[3], bb + 0 * OP_B + off);
                if (SPLIT) LDSM_X4(al[0], al[1], al[2], al[3], bb + 1 * OP_B + off);
#pragma unroll
                for (int ni = 0; ni < 4; ni++) {
                    mma_bf16(acc[mi][ni], ah, bh[ni]);
                    if (SPLIT) {
                        mma_bf16(acc[mi][ni], ah, bl[ni]);
                        mma_bf16(acc[mi][ni], al, bh[ni]);
                    }
                }
            }
        }
        __syncthreads();
    }

    // ---------------- epilogue ----------------
    const int g = lane >> 2, tid4 = lane & 3;
    if (EPI == 6) {
        unsigned long long best[8];
#pragma unroll
        for (int i = 0; i < 8; i++) best[i] = 0ull;
#pragma unroll
        for (int mi = 0; mi < 4; mi++)
#pragma unroll
            for (int ni = 0; ni < 4; ni++)
#pragma unroll
                for (int rr = 0; rr < 4; rr++) {
                    int ri = mi * 2 + ((rr >> 1) & 1);
                    int lcol = wn * 32 + ni * 8 + tid4 * 2 + (rr & 1);
                    int sidx = (col0 >= NGC) ? (col0 - NGC + lcol) : (col0 + lcol);
                    uint32_t u = fmap(acc[mi][ni][rr]);
                    unsigned long long p =
                        ((unsigned long long)u << 32) | (uint32_t)(~sidx);
                    if (p > best[ri]) best[ri] = p;
                }
#pragma unroll
        for (int i = 0; i < 8; i++)
#pragma unroll
            for (int o = 1; o < 4; o <<= 1) {
                unsigned long long ov = __shfl_xor_sync(0xffffffffu, best[i], o);
                if (ov > best[i]) best[i] = ov;
            }
        unsigned long long* S = (unsigned long long*)smem;
        if (tid4 == 0) {
#pragma unroll
            for (int mi = 0; mi < 4; mi++)
#pragma unroll
                for (int b = 0; b < 2; b++) {
                    int lrow = wm * 64 + mi * 16 + g + b * 8;
                    S[lrow * 4 + wn] = best[mi * 2 + b];
                }
        }
        __syncthreads();
        if (t < 128) {
            unsigned long long m = S[t * 4];
#pragma unroll
            for (int w = 1; w < 4; w++) if (S[t * 4 + w] > m) m = S[t * 4 + w];
            unsigned long long* tgt = (col0 >= NGC) ? AMAXL : AMAXG;
            atomicMax(&tgt[row0 + t], m);
        }
        return;
    }

    float absSum = 0.f;
#pragma unroll
    for (int mi = 0; mi < 4; mi++) {
#pragma unroll
        for (int ni = 0; ni < 4; ni++) {
#pragma unroll
            for (int rr = 0; rr < 4; rr++) {
                int r = row0 + wm * 64 + mi * 16 + g + ((rr >> 1) & 1) * 8;
                int cidx = col0 + wn * 32 + ni * 8 + tid4 * 2 + (rr & 1);
                float v = acc[mi][ni][rr];
                size_t idx = (size_t)r * ldc + cidx;
                if (EPI == 0) C[idx] = v;
                else if (EPI == 1) {
                    v = fmaxf(v + bias[cidx], 0.f);
                    __nv_bfloat16 h, l; split2(v, h, l);
                    Oh[idx] = h; Ol[idx] = l;
                } else if (EPI == 2) {
                    v += bias[cidx];
                    C2[idx] = v;
                    Oh[idx] = __float2bfloat16(v);
                } else if (EPI == 3) {
                    v += bias[cidx];
                    Oh[idx] = __float2bfloat16(1.f / (1.f + __expf(-v)));
                } else if (EPI == 4) {
                    Oh[idx] = __float2bfloat16(v);
                    absSum += fabsf(v);
                } else if (EPI == 5) {
                    C[idx] = Zin[idx] - __bfloat162float(Gth[idx]) * v;
                }
            }
        }
    }
    if (EPI == 4) {
#pragma unroll
        for (int o = 16; o > 0; o >>= 1) absSum += __shfl_xor_sync(0xffffffffu, absSum, o);
        if (lane == 0) atomicAdd(&LOSSACC[col0 >= NGC ? 1 : 0], (double)absSum);
    }
}

// ===================== driver ===============================================
extern "C" void kernel_launch(void* const* d_in, const int* in_sizes, int n_in,
                              void* d_out, int out_size) {
    const float* content = (const float*)d_in[0];
    const float* noise   = (const float*)d_in[1];
    const float* W1 = (const float*)d_in[2];
    const float* b1 = (const float*)d_in[3];
    const float* W2 = (const float*)d_in[4];
    const float* b2 = (const float*)d_in[5];
    const float* Wg = (const float*)d_in[6];
    const float* bg = (const float*)d_in[7];
    const float* gdict = (const float*)d_in[8];
    const float* ldict = (const float*)d_in[9];

    float* out = (float*)d_out;
    float* out_zc   = out;                        // [NT*DD]
    float* out_loss = out + (size_t)NT * DD;      // [1]
    float* out_zp   = out_loss + 1;               // [NT*DD] 4B-aligned only
    float* out_u    = out_zp + (size_t)NT * DD;   // [NT*DD] 4B-aligned only

#define SYM(T, p, s) T* p; cudaGetSymbolAddress((void**)&p, s)
    SYM(float, CMB_p, COMBINED);
    SYM(__nv_bfloat16, CTh_p, CTh);  SYM(__nv_bfloat16, CTl_p, CTl);
    SYM(__nv_bfloat16, UNh_p, UNh);
    SYM(__nv_bfloat16, Hh_p, Hh);    SYM(__nv_bfloat16, Hl_p, Hl);
    SYM(__nv_bfloat16, ZPh_p, ZPh);
    SYM(__nv_bfloat16, ZNh_p, ZNh);
    SYM(__nv_bfloat16, GATEh_p, GATEh);
    SYM(__nv_bfloat16, LOGh_p, LOGh);
    SYM(__nv_bfloat16, WTSh_p, WTSh);
    SYM(__nv_bfloat16, DICh_p, DICh);
    SYM(__nv_bfloat16, CMBh_p, CMBh);
    SYM(__nv_bfloat16, CMBTh_p, CMBTh);
    SYM(__nv_bfloat16, W1Th_p, W1Th); SYM(__nv_bfloat16, W1Tl_p, W1Tl);
    SYM(__nv_bfloat16, W2Th_p, W2Th); SYM(__nv_bfloat16, W2Tl_p, W2Tl);
    SYM(__nv_bfloat16, WgTh_p, WgTh);

    const int SM1 = 2 * 4 * OP_B;   // split GEMM (2 stages x 4 ops): 81920
    const int SM0 = 3 * 2 * OP_B;   // 1-pass GEMM (3 stages x 2 ops): 61440
    cudaFuncSetAttribute(gemm_mma<6, 0>, cudaFuncAttributeMaxDynamicSharedMemorySize, SM0);
    cudaFuncSetAttribute(gemm_mma<4, 0>, cudaFuncAttributeMaxDynamicSharedMemorySize, SM0);
    cudaFuncSetAttribute(gemm_mma<3, 0>, cudaFuncAttributeMaxDynamicSharedMemorySize, SM0);
    cudaFuncSetAttribute(gemm_mma<5, 0>, cudaFuncAttributeMaxDynamicSharedMemorySize, SM0);
    cudaFuncSetAttribute(gemm_mma<1, 1>, cudaFuncAttributeMaxDynamicSharedMemorySize, SM1);
    cudaFuncSetAttribute(gemm_mma<2, 1>, cudaFuncAttributeMaxDynamicSharedMemorySize, SM1);

    // launches 1-5: prep for g1 so launch #6 (ncu -s 5 -c 1 target) is the GEMM
    zero_kernel<<<(NCC * DD + 255) / 256, 256>>>();
    split_kernel<<<2048, 256>>>(content, CTh_p, CTl_p, (size_t)NT * DD);
    tsplit_kernel<<<dim3(DD / 32, DD / 32), dim3(32, 32)>>>(W1, W1Th_p, W1Tl_p, DD, DD);
    tsplit_kernel<<<dim3(DD / 32, DD / 32), dim3(32, 32)>>>(W2, W2Th_p, W2Tl_p, DD, DD);
    tsplit_kernel<<<dim3(DD / 32, DD / 32), dim3(32, 32)>>>(Wg, WgTh_p, nullptr, DD, DD);

    // 6-8: projector chain (z_proj fp32-effective 3-pass; gate 1-pass)
    gemm_mma<1, 1><<<dim3(DD / 128, NT / 128), 256, SM1>>>(
        CTh_p, CTl_p, W1Th_p, W1Tl_p, DD, DD, nullptr, b1,
        Hh_p, Hl_p, nullptr, nullptr, nullptr);
    gemm_mma<2, 1><<<dim3(DD / 128, NT / 128), 256, SM1>>>(
        Hh_p, Hl_p, W2Th_p, W2Tl_p, DD, DD, nullptr, b2,
        ZPh_p, nullptr, out_zp, nullptr, nullptr);
    gemm_mma<3, 0><<<dim3(DD / 128, NT / 128), 256, SM0>>>(
        ZPh_p, nullptr, WgTh_p, nullptr, DD, DD, nullptr, bg,
        GATEh_p, nullptr, nullptr, nullptr, nullptr);

    // 9-11: noise path prep
    unorm_kernel<<<NT, 256>>>(noise, out_u);
    split_kernel<<<256, 256>>>(gdict, DICh_p, nullptr, (size_t)NGC * DD);
    split_kernel<<<64, 256>>>(ldict, DICh_p + (size_t)NGC * DD, nullptr, (size_t)NLC * DD);

    // 12-15: assignment + dict update
    gemm_mma<6, 0><<<dim3(NCC / 128, NT / 128), 256, SM0>>>(
        UNh_p, nullptr, DICh_p, nullptr, DD, NCC, nullptr, nullptr,
        nullptr, nullptr, nullptr, nullptr, nullptr);
    scatter_kernel<<<NT, 256>>>();
    dictupd_kernel<<<NCC, 256>>>(gdict, ldict);
    tsplit_kernel<<<dim3(DD / 32, NCC / 32), dim3(32, 32)>>>(CMB_p, CMBTh_p, nullptr, NCC, DD);

    // 16-20: norms, logits, softmax, combine, loss
    znorm_kernel<<<NT, 256>>>(out_zp);
    gemm_mma<4, 0><<<dim3(NCC / 128, NT / 128), 256, SM0>>>(
        ZNh_p, nullptr, CMBh_p, nullptr, DD, NCC, nullptr, nullptr,
        LOGh_p, nullptr, nullptr, nullptr, nullptr);
    softmax_kernel<<<NT, 256>>>();
    gemm_mma<5, 0><<<dim3(DD / 128, NT / 128), 256, SM0>>>(
        WTSh_p, nullptr, CMBTh_p, nullptr, NCC, DD, out_zc, nullptr,
        nullptr, nullptr, nullptr, content, GATEh_p);
    finalize_kernel<<<1, 1>>>(out_loss);
}

// round 14
// speedup vs baseline: 3.4415x; 1.0198x over previous
#include <cuda_runtime.h>
#include <cuda_bf16.h>
#include <math.h>
#include <cstdint>

#define NT 32768      // B*L tokens
#define DD 1024
#define NGC 1024
#define NLC 256
#define NCC 1280      // NGC + NLC
#define EPSN 1e-12f

// ===================== helpers ==============================================
__device__ __forceinline__ uint32_t smem_u32(const void* p) {
    uint32_t a;
    asm("{ .reg .u64 t; cvta.to.shared.u64 t, %1; cvt.u32.u64 %0, t; }" : "=r"(a) : "l"(p));
    return a;
}

#define LDSM_X4(r0, r1, r2, r3, addr) \
    asm volatile("ldmatrix.sync.aligned.m8n8.x4.shared.b16 {%0,%1,%2,%3}, [%4];" \
                 : "=r"(r0), "=r"(r1), "=r"(r2), "=r"(r3) : "r"(addr))

__device__ __forceinline__ void mma_bf16(float* c, const uint32_t* a, const uint32_t* b) {
    asm volatile(
        "mma.sync.aligned.m16n8k16.row.col.f32.bf16.bf16.f32 "
        "{%0,%1,%2,%3}, {%4,%5,%6,%7}, {%8,%9}, {%0,%1,%2,%3};"
        : "+f"(c[0]), "+f"(c[1]), "+f"(c[2]), "+f"(c[3])
        : "r"(a[0]), "r"(a[1]), "r"(a[2]), "r"(a[3]), "r"(b[0]), "r"(b[1]));
}

#define CP_ASYNC16(dst, src) \
    asm volatile("cp.async.cg.shared.global [%0], [%1], 16;" :: "r"(dst), "l"(src) : "memory")
#define CP_COMMIT() asm volatile("cp.async.commit_group;" ::: "memory")
#define CP_WAIT2()  asm volatile("cp.async.wait_group 2;" ::: "memory")
#define CP_WAIT1()  asm volatile("cp.async.wait_group 1;" ::: "memory")
#define CP_WAIT0()  asm volatile("cp.async.wait_group 0;" ::: "memory")

__device__ __forceinline__ void split2(float x, __nv_bfloat16& h, __nv_bfloat16& l) {
    h = __float2bfloat16(x);
    l = __float2bfloat16(x - __bfloat162float(h));
}

// monotonic float->u32 mapping (order-preserving for all finite floats)
__device__ __forceinline__ uint32_t fmap(float f) {
    uint32_t u = __float_as_uint(f);
    return (u & 0x80000000u) ? ~u : (u | 0x80000000u);
}

// ===================== scratch ==============================================
__device__ float COMBINED[(size_t)NCC * DD];
__device__ __align__(16) float SUMS[(size_t)NCC * DD];
__device__ float COUNTS[NCC];
__device__ unsigned long long AMAXG[NT];   // packed (mapped_val<<32)|~idx
__device__ unsigned long long AMAXL[NT];
__device__ double LOSSACC[3];

#define BUF(name, n) __device__ __align__(256) __nv_bfloat16 name[(size_t)(n)]
BUF(CTh, NT* DD);  BUF(CTl, NT* DD);
BUF(UNh, NT* DD);
BUF(Hh,  NT* DD);  BUF(Hl,  NT* DD);
BUF(ZPh, NT* DD);
BUF(ZNh, NT* DD);
BUF(GATEh, NT* DD);
BUF(LOGh, NT* NCC);
BUF(WTSh, NT* NCC);
BUF(DICh, NCC* DD);
BUF(CMBh, NCC* DD);
BUF(CMBTh, DD* NCC);
BUF(W1Th, DD* DD); BUF(W1Tl, DD* DD);
BUF(W2Th, DD* DD); BUF(W2Tl, DD* DD);
BUF(WgTh, DD* DD);

// ===================== small kernels ========================================
__global__ void zero_kernel() {
    size_t i = (size_t)blockIdx.x * blockDim.x + threadIdx.x;
    size_t tot = (size_t)NCC * DD;
    if (i < tot) SUMS[i] = 0.f;
    if (i < NCC) COUNTS[i] = 0.f;
    if (i < NT) { AMAXG[i] = 0ull; AMAXL[i] = 0ull; }
    if (i < 3) LOSSACC[i] = 0.0;
}

__global__ __launch_bounds__(256) void split_kernel(const float* __restrict__ src,
                                                    __nv_bfloat16* __restrict__ dh,
                                                    __nv_bfloat16* __restrict__ dl, size_t n) {
    for (size_t i = (size_t)blockIdx.x * blockDim.x + threadIdx.x; i < n;
         i += (size_t)gridDim.x * blockDim.x) {
        __nv_bfloat16 h, l;
        split2(src[i], h, l);
        dh[i] = h;
        if (dl) dl[i] = l;
    }
}

// W[R,C] -> out[C,R] with bf16 split (ol may be null)
__global__ void tsplit_kernel(const float* __restrict__ W,
                              __nv_bfloat16* __restrict__ oh, __nv_bfloat16* __restrict__ ol,
                              int R, int Cc) {
    __shared__ float tile[32][33];
    int bx = blockIdx.x, by = blockIdx.y;
    int x = bx * 32 + threadIdx.x;
    int y = by * 32 + threadIdx.y;
    tile[threadIdx.y][threadIdx.x] = W[(size_t)y * Cc + x];
    __syncthreads();
    int orow = bx * 32 + threadIdx.y;
    int ocol = by * 32 + threadIdx.x;
    __nv_bfloat16 h, l;
    split2(tile[threadIdx.x][threadIdx.y], h, l);
    oh[(size_t)orow * R + ocol] = h;
    if (ol) ol[(size_t)orow * R + ocol] = l;
}

__global__ __launch_bounds__(256) void unorm_kernel(const float* __restrict__ u,
                                                    float* __restrict__ out_u) {
    int row = blockIdx.x, t = threadIdx.x;
    const float* ur = u + (size_t)row * DD;
    float v[4]; float ss = 0.f;
#pragma unroll
    for (int q = 0; q < 4; q++) { v[q] = ur[t + q * 256]; ss += v[q] * v[q]; }
    __shared__ float red[256];
    red[t] = ss; __syncthreads();
    for (int s = 128; s > 0; s >>= 1) { if (t < s) red[t] += red[t + s]; __syncthreads(); }
    float inv = 1.f / fmaxf(sqrtf(red[0]), EPSN);
    size_t base = (size_t)row * DD;
#pragma unroll
    for (int q = 0; q < 4; q++) {
        int j = t + q * 256;
        out_u[base + j] = v[q];
        UNh[base + j] = __float2bfloat16(v[q] * inv);
    }
}

// reads z_proj from out_zp (fp32, scalar) and u_norm from UNh (bf16)
__global__ __launch_bounds__(256) void znorm_kernel(const float* __restrict__ zp) {
    int row = blockIdx.x, t = threadIdx.x;
    size_t base = (size_t)row * DD;
    float v[4]; float ss = 0.f, dp = 0.f;
#pragma unroll
    for (int q = 0; q < 4; q++) {
        int j = t + q * 256;
        v[q] = zp[base + j];
        ss += v[q] * v[q];
        dp += v[q] * __bfloat162float(UNh[base + j]);
    }
    __shared__ float redA[256];
    __shared__ float redB[256];
    redA[t] = ss; redB[t] = dp; __syncthreads();
    for (int s = 128; s > 0; s >>= 1) {
        if (t < s) { redA[t] += redA[t + s]; redB[t] += redB[t + s]; }
        __syncthreads();
    }
    float inv = 1.f / fmaxf(sqrtf(redA[0]), EPSN);
#pragma unroll
    for (int q = 0; q < 4; q++) {
        int j = t + q * 256;
        ZNh[base + j] = __float2bfloat16(v[q] * inv);
    }
    if (t == 0) atomicAdd(&LOSSACC[2], (double)(fabsf(redB[0]) * inv));
}

__global__ __launch_bounds__(256) void scatter_kernel() {
    int row = blockIdx.x, t = threadIdx.x;
    int ig = (int)(~(uint32_t)AMAXG[row]);
    int il = (int)(~(uint32_t)AMAXL[row]);
    const __nv_bfloat16* u = UNh + (size_t)row * DD;
    int j = t * 4;
    uint2 raw = *(const uint2*)(u + j);
    __nv_bfloat162 p0 = *reinterpret_cast<__nv_bfloat162*>(&raw.x);
    __nv_bfloat162 p1 = *reinterpret_cast<__nv_bfloat162*>(&raw.y);
    float4 v = make_float4(__low2float(p0), __high2float(p0),
                           __low2float(p1), __high2float(p1));
    atomicAdd((float4*)(SUMS + (size_t)ig * DD + j), v);
    atomicAdd((float4*)(SUMS + (size_t)(NGC + il) * DD + j), v);
    if (t == 0) { atomicAdd(&COUNTS[ig], 1.f); atomicAdd(&COUNTS[NGC + il], 1.f); }
}

__global__ __launch_bounds__(256) void dictupd_kernel(const float* __restrict__ gd,
                                                      const float* __restrict__ ld) {
    int k = blockIdx.x, t = threadIdx.x;
    const float* old = (k < NGC) ? (gd + (size_t)k * DD) : (ld + (size_t)(k - NGC) * DD);
    float m = (k < NGC) ? 0.999f : 0.8f;
    float cnt = COUNTS[k];
    float up[4]; float ss = 0.f;
#pragma unroll
    for (int q = 0; q < 4; q++) {
        int j = t + q * 256;
        float o = old[j];
        float u;
        if (cnt > 0.f) {
            float mean = SUMS[(size_t)k * DD + j] / fmaxf(cnt, 1.f);
            u = m * o + (1.f - m) * mean;
        } else u = o;
        up[q] = u; ss += u * u;
    }
    __shared__ float red[256];
    red[t] = ss; __syncthreads();
    for (int s = 128; s > 0; s >>= 1) { if (t < s) red[t] += red[t + s]; __syncthreads(); }
    float inv = 1.f / fmaxf(sqrtf(red[0]), EPSN);
    size_t base = (size_t)k * DD;
#pragma unroll
    for (int q = 0; q < 4; q++) {
        int j = t + q * 256;
        float u = up[q] * inv;
        COMBINED[base + j] = u;
        CMBh[base + j] = __float2bfloat16(u);
    }
}

__global__ __launch_bounds__(256) void softmax_kernel() {
    int row = blockIdx.x, t = threadIdx.x;
    const __nv_bfloat16* L = LOGh + (size_t)row * NCC;
    const float invT = 1.f / 0.07f;
    float v[5];
    float mx = -3.0e38f;
#pragma unroll
    for (int q = 0; q < 5; q++) {
        v[q] = __bfloat162float(L[t + q * 256]) * invT;
        mx = fmaxf(mx, v[q]);
    }
    __shared__ float red[256];
    red[t] = mx; __syncthreads();
    for (int s = 128; s > 0; s >>= 1) { if (t < s) red[t] = fmaxf(red[t], red[t + s]); __syncthreads(); }
    mx = red[0]; __syncthreads();
    float sum = 0.f;
#pragma unroll
    for (int q = 0; q < 5; q++) { v[q] = __expf(v[q] - mx); sum += v[q]; }
    red[t] = sum; __syncthreads();
    for (int s = 128; s > 0; s >>= 1) { if (t < s) red[t] += red[t + s]; __syncthreads(); }
    float inv = 1.f / red[0];
    size_t base = (size_t)row * NCC;
#pragma unroll
    for (int q = 0; q < 5; q++)
        WTSh[base + t + q * 256] = __float2bfloat16(v[q] * inv);
}

__global__ void finalize_kernel(float* __restrict__ out_loss) {
    double lg = LOSSACC[0] / ((double)NT * (double)NGC);
    double ll = LOSSACC[1] / ((double)NT * (double)NLC);
    double ldir = LOSSACC[2] / (double)NT;
    *out_loss = (float)(lg + ll + ldir);
}

// ===================== mma.sync GEMM (split or single pass) =================
// C[M,N] = A[M,K] * B[N,K]^T.  SPLIT=1: fp32-effective 3-pass, 2-stage pipe;
//                              SPLIT=0: bf16 1-pass, 3-stage pipe.
// CTA 128x128, 8 warps (2x4), warp tile 64x32 via m16n8k16.
// EPI: 0 store C | 1 relu+bias->Oh/Ol | 2 bias->C2(scalar fp32)+Oh | 3 sigmoid+bias->Oh
//      4 Oh + abs-loss | 5 C=Zin-Gth*acc | 6 fused row argmax (no store)
#define OP_B 10240               // bytes per operand tile (128*80)

template <int EPI, int SPLIT>
__global__ __launch_bounds__(256, 2) void gemm_mma(
    const __nv_bfloat16* __restrict__ Ah, const __nv_bfloat16* __restrict__ Al,
    const __nv_bfloat16* __restrict__ Bh, const __nv_bfloat16* __restrict__ Bl,
    int K, int ldc,
    float* __restrict__ C, const float* __restrict__ bias,
    __nv_bfloat16* __restrict__ Oh, __nv_bfloat16* __restrict__ Ol,
    float* __restrict__ C2,
    const float* __restrict__ Zin, const __nv_bfloat16* __restrict__ Gth)
{
    constexpr int NOPS = SPLIT ? 4 : 2;
    constexpr int STAGES = SPLIT ? 2 : 3;
    constexpr int STG = NOPS * OP_B;
    constexpr int BH_OFF = SPLIT ? 2 * OP_B : OP_B;

    extern __shared__ char smem[];
    const uint32_t sb = smem_u32(smem);
    const int t = threadIdx.x;
    const int lane = t & 31, wid = t >> 5;
    const int wm = wid & 1, wn = wid >> 1;          // 2 x 4 warp grid
    const int row0 = blockIdx.y * 128, col0 = blockIdx.x * 128;

    float acc[4][4][4];
#pragma unroll
    for (int mi = 0; mi < 4; mi++)
#pragma unroll
        for (int ni = 0; ni < 4; ni++)
#pragma unroll
            for (int rr = 0; rr < 4; rr++) acc[mi][ni][rr] = 0.f;

    const int NCH = K >> 5;
    const __nv_bfloat16* srcs[4] = {Ah, SPLIT ? Al : Bh, Bh, Bl};
    const int rbase[4] = {row0, SPLIT ? row0 : col0, col0, col0};

    auto issue = [&](int c, int buf) {
        const int k0 = c << 5;
        const uint32_t base = sb + buf * STG;
#pragma unroll
        for (int o = 0; o < NOPS; o++) {
            const __nv_bfloat16* src = srcs[o];
            const int r0g = rbase[o];
            const uint32_t ob = base + o * OP_B;
#pragma unroll
            for (int s2 = 0; s2 < 2; s2++) {
                int s = t + s2 * 256;
                int row = s >> 2, part = s & 3;
                uint32_t dst = ob + row * 80 + part * 16;
                const void* sp = src + (size_t)(r0g + row) * K + k0 + part * 8;
                CP_ASYNC16(dst, sp);
            }
        }
        CP_COMMIT();
    };

    // prologue: fill STAGES-1 buffers
    issue(0, 0);
    if (STAGES > 2 && NCH > 1) issue(1, 1);

    for (int c = 0; c < NCH; c++) {
        int nxt = c + STAGES - 1;
        if (nxt < NCH) {
            issue(nxt, nxt % STAGES);
            if (STAGES == 3) CP_WAIT2(); else CP_WAIT1();
        } else if (STAGES == 3 && c + 2 == NCH) {
            CP_WAIT1();
        } else {
            CP_WAIT0();
        }
        __syncthreads();
        const uint32_t bb = sb + (c % STAGES) * STG;
#pragma unroll
        for (int ks = 0; ks < 32; ks += 16) {
            uint32_t bh[4][2], bl[4][2];
#pragma unroll
            for (int g2 = 0; g2 < 2; g2++) {
                int n0 = wn * 32 + g2 * 16;
                int r = n0 + (lane & 7) + (lane >> 4) * 8;
                int cc = ks + ((lane >> 3) & 1) * 8;
                uint32_t off = r * 80 + cc * 2;
                uint32_t r0, r1, r2, r3;
                LDSM_X4(r0, r1, r2, r3, bb + BH_OFF + off);
                bh[2 * g2 + 0][0] = r0; bh[2 * g2 + 0][1] = r1;
                bh[2 * g2 + 1][0] = r2; bh[2 * g2 + 1][1] = r3;
                if (SPLIT) {
                    LDSM_X4(r0, r1, r2, r3, bb + 3 * OP_B + off);
                    bl[2 * g2 + 0][0] = r0; bl[2 * g2 + 0][1] = r1;
                    bl[2 * g2 + 1][0] = r2; bl[2 * g2 + 1][1] = r3;
                }
            }
#pragma unroll
            for (int mi = 0; mi < 4; mi++) {
                int m0 = wm * 64 + mi * 16;
                int r = m0 + (lane & 7) + ((lane >> 3) & 1) * 8;
                int cc = ks + (lane >> 4) * 8;
                uint32_t off = r * 80 + cc * 2;
                uint32_t ah[4], al[4];
                LDSM_X4(ah[0], ah[1], ah[2], ah[3], bb + 0 * OP_B + off);
                if (SPLIT) LDSM_X4(al[0], al[1], al[2], al[3], bb + 1 * OP_B + off);
#pragma unroll
                for (int ni = 0; ni < 4; ni++) {
                    mma_bf16(acc[mi][ni], ah, bh[ni]);
                    if (SPLIT) {
                        mma_bf16(acc[mi][ni], ah, bl[ni]);
                        mma_bf16(acc[mi][ni], al, bh[ni]);
                    }
                }
            }
        }
        __syncthreads();
    }

    // ---------------- epilogue ----------------
    const int g = lane >> 2, tid4 = lane & 3;
    if (EPI == 6) {
        unsigned long long best[8];
#pragma unroll
        for (int i = 0; i < 8; i++) best[i] = 0ull;
#pragma unroll
        for (int mi = 0; mi < 4; mi++)
#pragma unroll
            for (int ni = 0; ni < 4; ni++)
#pragma unroll
                for (int rr = 0; rr < 4; rr++) {
                    int ri = mi * 2 + ((rr >> 1) & 1);
                    int lcol = wn * 32 + ni * 8 + tid4 * 2 + (rr & 1);
                    int sidx = (col0 >= NGC) ? (col0 - NGC + lcol) : (col0 + lcol);
                    uint32_t u = fmap(acc[mi][ni][rr]);
                    unsigned long long p =
                        ((unsigned long long)u << 32) | (uint32_t)(~sidx);
                    if (p > best[ri]) best[ri] = p;
                }
#pragma unroll
        for (int i = 0; i < 8; i++)
#pragma unroll
            for (int o = 1; o < 4; o <<= 1) {
                unsigned long long ov = __shfl_xor_sync(0xffffffffu, best[i], o);
                if (ov > best[i]) best[i] = ov;
            }
        unsigned long long* S = (unsigned long long*)smem;
        if (tid4 == 0) {
#pragma unroll
            for (int mi = 0; mi < 4; mi++)
#pragma unroll
                for (int b = 0; b < 2; b++) {
                    int lrow = wm * 64 + mi * 16 + g + b * 8;
                    S[lrow * 4 + wn] = best[mi * 2 + b];
                }
        }
        __syncthreads();
        if (t < 128) {
            unsigned long long m = S[t * 4];
#pragma unroll
            for (int w = 1; w < 4; w++) if (S[t * 4 + w] > m) m = S[t * 4 + w];
            unsigned long long* tgt = (col0 >= NGC) ? AMAXL : AMAXG;
            atomicMax(&tgt[row0 + t], m);
        }
        return;
    }

    float absSum = 0.f;
#pragma unroll
    for (int mi = 0; mi < 4; mi++) {
#pragma unroll
        for (int ni = 0; ni < 4; ni++) {
#pragma unroll
            for (int rr = 0; rr < 4; rr++) {
                int r = row0 + wm * 64 + mi * 16 + g + ((rr >> 1) & 1) * 8;
                int cidx = col0 + wn * 32 + ni * 8 + tid4 * 2 + (rr & 1);
                float v = acc[mi][ni][rr];
                size_t idx = (size_t)r * ldc + cidx;
                if (EPI == 0) C[idx] = v;
                else if (EPI == 1) {
                    v = fmaxf(v + bias[cidx], 0.f);
                    __nv_bfloat16 h, l; split2(v, h, l);
                    Oh[idx] = h; Ol[idx] = l;
                } else if (EPI == 2) {
                    v += bias[cidx];
                    C2[idx] = v;
                    Oh[idx] = __float2bfloat16(v);
                } else if (EPI == 3) {
                    v += bias[cidx];
                    Oh[idx] = __float2bfloat16(1.f / (1.f + __expf(-v)));
                } else if (EPI == 4) {
                    Oh[idx] = __float2bfloat16(v);
                    absSum += fabsf(v);
                } else if (EPI == 5) {
                    C[idx] = Zin[idx] - __bfloat162float(Gth[idx]) * v;
                }
            }
        }
    }
    if (EPI == 4) {
#pragma unroll
        for (int o = 16; o > 0; o >>= 1) absSum += __shfl_xor_sync(0xffffffffu, absSum, o);
        if (lane == 0) atomicAdd(&LOSSACC[col0 >= NGC ? 1 : 0], (double)absSum);
    }
}

// ===================== driver ===============================================
extern "C" void kernel_launch(void* const* d_in, const int* in_sizes, int n_in,
                              void* d_out, int out_size) {
    const float* content = (const float*)d_in[0];
    const float* noise   = (const float*)d_in[1];
    const float* W1 = (const float*)d_in[2];
    const float* b1 = (const float*)d_in[3];
    const float* W2 = (const float*)d_in[4];
    const float* b2 = (const float*)d_in[5];
    const float* Wg = (const float*)d_in[6];
    const float* bg = (const float*)d_in[7];
    const float* gdict = (const float*)d_in[8];
    const float* ldict = (const float*)d_in[9];

    float* out = (float*)d_out;
    float* out_zc   = out;                        // [NT*DD]
    float* out_loss = out + (size_t)NT * DD;      // [1]
    float* out_zp   = out_loss + 1;               // [NT*DD] 4B-aligned only
    float* out_u    = out_zp + (size_t)NT * DD;   // [NT*DD] 4B-aligned only

#define SYM(T, p, s) T* p; cudaGetSymbolAddress((void**)&p, s)
    SYM(float, CMB_p, COMBINED);
    SYM(__nv_bfloat16, CTh_p, CTh);  SYM(__nv_bfloat16, CTl_p, CTl);
    SYM(__nv_bfloat16, UNh_p, UNh);
    SYM(__nv_bfloat16, Hh_p, Hh);    SYM(__nv_bfloat16, Hl_p, Hl);
    SYM(__nv_bfloat16, ZPh_p, ZPh);
    SYM(__nv_bfloat16, ZNh_p, ZNh);
    SYM(__nv_bfloat16, GATEh_p, GATEh);
    SYM(__nv_bfloat16, LOGh_p, LOGh);
    SYM(__nv_bfloat16, WTSh_p, WTSh);
    SYM(__nv_bfloat16, DICh_p, DICh);
    SYM(__nv_bfloat16, CMBh_p, CMBh);
    SYM(__nv_bfloat16, CMBTh_p, CMBTh);
    SYM(__nv_bfloat16, W1Th_p, W1Th); SYM(__nv_bfloat16, W1Tl_p, W1Tl);
    SYM(__nv_bfloat16, W2Th_p, W2Th); SYM(__nv_bfloat16, W2Tl_p, W2Tl);
    SYM(__nv_bfloat16, WgTh_p, WgTh);

    const int SM1 = 2 * 4 * OP_B;   // split GEMM (2 stages x 4 ops): 81920
    const int SM0 = 3 * 2 * OP_B;   // 1-pass GEMM (3 stages x 2 ops): 61440
    cudaFuncSetAttribute(gemm_mma<6, 0>, cudaFuncAttributeMaxDynamicSharedMemorySize, SM0);
    cudaFuncSetAttribute(gemm_mma<4, 0>, cudaFuncAttributeMaxDynamicSharedMemorySize, SM0);
    cudaFuncSetAttribute(gemm_mma<3, 0>, cudaFuncAttributeMaxDynamicSharedMemorySize, SM0);
    cudaFuncSetAttribute(gemm_mma<5, 0>, cudaFuncAttributeMaxDynamicSharedMemorySize, SM0);
    cudaFuncSetAttribute(gemm_mma<1, 1>, cudaFuncAttributeMaxDynamicSharedMemorySize, SM1);
    cudaFuncSetAttribute(gemm_mma<2, 1>, cudaFuncAttributeMaxDynamicSharedMemorySize, SM1);

    // ---- stream fork: chain B (noise/dict) runs concurrently with chain A ----
    // Host-side objects only; intentionally not destroyed (kernel_launch is
    // invoked only a handful of times: correctness + capture).
    cudaStream_t sB;
    cudaStreamCreateWithFlags(&sB, cudaStreamNonBlocking);
    cudaEvent_t e0, e1;
    cudaEventCreateWithFlags(&e0, cudaEventDisableTiming);
    cudaEventCreateWithFlags(&e1, cudaEventDisableTiming);

    // zero feeds BOTH chains (SUMS/AMAX for B, LOSSACC for A) -> before fork
    zero_kernel<<<(NCC * DD + 255) / 256, 256>>>();
    cudaEventRecord(e0, 0);
    cudaStreamWaitEvent(sB, e0, 0);

    // ---- chain B (stream sB): noise -> sims/argmax -> scatter -> dict update
    unorm_kernel<<<NT, 256, 0, sB>>>(noise, out_u);
    split_kernel<<<256, 256, 0, sB>>>(gdict, DICh_p, nullptr, (size_t)NGC * DD);
    split_kernel<<<64, 256, 0, sB>>>(ldict, DICh_p + (size_t)NGC * DD, nullptr,
                                     (size_t)NLC * DD);
    gemm_mma<6, 0><<<dim3(NCC / 128, NT / 128), 256, SM0, sB>>>(
        UNh_p, nullptr, DICh_p, nullptr, DD, NCC, nullptr, nullptr,
        nullptr, nullptr, nullptr, nullptr, nullptr);
    scatter_kernel<<<NT, 256, 0, sB>>>();
    dictupd_kernel<<<NCC, 256, 0, sB>>>(gdict, ldict);
    tsplit_kernel<<<dim3(DD / 32, NCC / 32), dim3(32, 32), 0, sB>>>(
        CMB_p, CMBTh_p, nullptr, NCC, DD);
    cudaEventRecord(e1, sB);

    // ---- chain A (default stream): content -> projector -> gate
    split_kernel<<<2048, 256>>>(content, CTh_p, CTl_p, (size_t)NT * DD);
    tsplit_kernel<<<dim3(DD / 32, DD / 32), dim3(32, 32)>>>(W1, W1Th_p, W1Tl_p, DD, DD);
    tsplit_kernel<<<dim3(DD / 32, DD / 32), dim3(32, 32)>>>(W2, W2Th_p, W2Tl_p, DD, DD);
    tsplit_kernel<<<dim3(DD / 32, DD / 32), dim3(32, 32)>>>(Wg, WgTh_p, nullptr, DD, DD);
    gemm_mma<1, 1><<<dim3(DD / 128, NT / 128), 256, SM1>>>(
        CTh_p, CTl_p, W1Th_p, W1Tl_p, DD, DD, nullptr, b1,
        Hh_p, Hl_p, nullptr, nullptr, nullptr);
    gemm_mma<2, 1><<<dim3(DD / 128, NT / 128), 256, SM1>>>(
        Hh_p, Hl_p, W2Th_p, W2Tl_p, DD, DD, nullptr, b2,
        ZPh_p, nullptr, out_zp, nullptr, nullptr);
    gemm_mma<3, 0><<<dim3(DD / 128, NT / 128), 256, SM0>>>(
        ZPh_p, nullptr, WgTh_p, nullptr, DD, DD, nullptr, bg,
        GATEh_p, nullptr, nullptr, nullptr, nullptr);

    // ---- join B into A, then the merged tail
    cudaStreamWaitEvent(0, e1, 0);
    znorm_kernel<<<NT, 256>>>(out_zp);           // needs UNh (B) + out_zp (A)
    gemm_mma<4, 0><<<dim3(NCC / 128, NT / 128), 256, SM0>>>(
        ZNh_p, nullptr, CMBh_p, nullptr, DD, NCC, nullptr, nullptr,
        LOGh_p, nullptr, nullptr, nullptr, nullptr);
    softmax_kernel<<<NT, 256>>>();
    gemm_mma<5, 0><<<dim3(DD / 128, NT / 128), 256, SM0>>>(
        WTSh_p, nullptr, CMBTh_p, nullptr, NCC, DD, out_zc, nullptr,
        nullptr, nullptr, nullptr, content, GATEh_p);
    finalize_kernel<<<1, 1>>>(out_loss);
}

// round 15
// speedup vs baseline: 4.4997x; 1.3075x over previous
#include <cuda_runtime.h>
#include <cuda_bf16.h>
#include <cuda_fp16.h>
#include <math.h>
#include <cstdint>

#define NT 32768      // B*L tokens
#define DD 1024
#define NGC 1024
#define NLC 256
#define NCC 1280      // NGC + NLC
#define EPSN 1e-12f

// ===================== helpers ==============================================
__device__ __forceinline__ uint32_t smem_u32(const void* p) {
    uint32_t a;
    asm("{ .reg .u64 t; cvta.to.shared.u64 t, %1; cvt.u32.u64 %0, t; }" : "=r"(a) : "l"(p));
    return a;
}

#define LDSM_X4(r0, r1, r2, r3, addr) \
    asm volatile("ldmatrix.sync.aligned.m8n8.x4.shared.b16 {%0,%1,%2,%3}, [%4];" \
                 : "=r"(r0), "=r"(r1), "=r"(r2), "=r"(r3) : "r"(addr))

__device__ __forceinline__ void mma_bf16(float* c, const uint32_t* a, const uint32_t* b) {
    asm volatile(
        "mma.sync.aligned.m16n8k16.row.col.f32.bf16.bf16.f32 "
        "{%0,%1,%2,%3}, {%4,%5,%6,%7}, {%8,%9}, {%0,%1,%2,%3};"
        : "+f"(c[0]), "+f"(c[1]), "+f"(c[2]), "+f"(c[3])
        : "r"(a[0]), "r"(a[1]), "r"(a[2]), "r"(a[3]), "r"(b[0]), "r"(b[1]));
}

__device__ __forceinline__ void mma_fp16(float* c, const uint32_t* a, const uint32_t* b) {
    asm volatile(
        "mma.sync.aligned.m16n8k16.row.col.f32.f16.f16.f32 "
        "{%0,%1,%2,%3}, {%4,%5,%6,%7}, {%8,%9}, {%0,%1,%2,%3};"
        : "+f"(c[0]), "+f"(c[1]), "+f"(c[2]), "+f"(c[3])
        : "r"(a[0]), "r"(a[1]), "r"(a[2]), "r"(a[3]), "r"(b[0]), "r"(b[1]));
}

#define CP_ASYNC16(dst, src) \
    asm volatile("cp.async.cg.shared.global [%0], [%1], 16;" :: "r"(dst), "l"(src) : "memory")
#define CP_COMMIT() asm volatile("cp.async.commit_group;" ::: "memory")
#define CP_WAIT2()  asm volatile("cp.async.wait_group 2;" ::: "memory")
#define CP_WAIT1()  asm volatile("cp.async.wait_group 1;" ::: "memory")
#define CP_WAIT0()  asm volatile("cp.async.wait_group 0;" ::: "memory")

__device__ __forceinline__ void split2(float x, __nv_bfloat16& h, __nv_bfloat16& l) {
    h = __float2bfloat16(x);
    l = __float2bfloat16(x - __bfloat162float(h));
}

// monotonic float->u32 mapping (order-preserving for all finite floats)
__device__ __forceinline__ uint32_t fmap(float f) {
    uint32_t u = __float_as_uint(f);
    return (u & 0x80000000u) ? ~u : (u | 0x80000000u);
}

// ===================== scratch ==============================================
__device__ float COMBINED[(size_t)NCC * DD];
__device__ __align__(16) float SUMS[(size_t)NCC * DD];
__device__ float COUNTS[NCC];
__device__ unsigned long long AMAXG[NT];   // packed (mapped_val<<32)|~idx
__device__ unsigned long long AMAXL[NT];
__device__ double LOSSACC[3];

#define BUF(name, n) __device__ __align__(256) __nv_bfloat16 name[(size_t)(n)]
BUF(CT16, NT* DD);                    // content as fp16
BUF(UNh, NT* DD);
BUF(H16,  NT* DD);                    // hidden as fp16
BUF(ZPh, NT* DD);                     // z_proj as bf16 (for gate GEMM)
BUF(ZNh, NT* DD);
BUF(GATEh, NT* DD);
BUF(LOGh, NT* NCC);
BUF(WTSh, NT* NCC);
BUF(DICh, NCC* DD);
BUF(CMBh, NCC* DD);
BUF(CMBTh, DD* NCC);
BUF(W1T16, DD* DD);                   // W1^T as fp16
BUF(W2T16, DD* DD);                   // W2^T as fp16
BUF(WgTh, DD* DD);

// ===================== small kernels ========================================
__global__ void zero_kernel() {
    size_t i = (size_t)blockIdx.x * blockDim.x + threadIdx.x;
    size_t tot = (size_t)NCC * DD;
    if (i < tot) SUMS[i] = 0.f;
    if (i < NCC) COUNTS[i] = 0.f;
    if (i < NT) { AMAXG[i] = 0ull; AMAXL[i] = 0ull; }
    if (i < 3) LOSSACC[i] = 0.0;
}

// FP16OUT=1: write __half; else bf16 (dl unused in both single-output modes)
template <int FP16OUT>
__global__ __launch_bounds__(256) void cvt_kernel(const float* __restrict__ src,
                                                  void* __restrict__ dst, size_t n) {
    for (size_t i = (size_t)blockIdx.x * blockDim.x + threadIdx.x; i < n;
         i += (size_t)gridDim.x * blockDim.x) {
        if (FP16OUT) ((__half*)dst)[i] = __float2half(src[i]);
        else ((__nv_bfloat16*)dst)[i] = __float2bfloat16(src[i]);
    }
}

// W[R,C] -> out[C,R]; FP16OUT selects output type
template <int FP16OUT>
__global__ void tsplit_kernel(const float* __restrict__ W, void* __restrict__ oh,
                              int R, int Cc) {
    __shared__ float tile[32][33];
    int bx = blockIdx.x, by = blockIdx.y;
    int x = bx * 32 + threadIdx.x;
    int y = by * 32 + threadIdx.y;
    tile[threadIdx.y][threadIdx.x] = W[(size_t)y * Cc + x];
    __syncthreads();
    int orow = bx * 32 + threadIdx.y;
    int ocol = by * 32 + threadIdx.x;
    float v = tile[threadIdx.x][threadIdx.y];
    if (FP16OUT) ((__half*)oh)[(size_t)orow * R + ocol] = __float2half(v);
    else ((__nv_bfloat16*)oh)[(size_t)orow * R + ocol] = __float2bfloat16(v);
}

__global__ __launch_bounds__(256) void unorm_kernel(const float* __restrict__ u,
                                                    float* __restrict__ out_u) {
    int row = blockIdx.x, t = threadIdx.x;
    const float* ur = u + (size_t)row * DD;
    float v[4]; float ss = 0.f;
#pragma unroll
    for (int q = 0; q < 4; q++) { v[q] = ur[t + q * 256]; ss += v[q] * v[q]; }
    __shared__ float red[256];
    red[t] = ss; __syncthreads();
    for (int s = 128; s > 0; s >>= 1) { if (t < s) red[t] += red[t + s]; __syncthreads(); }
    float inv = 1.f / fmaxf(sqrtf(red[0]), EPSN);
    size_t base = (size_t)row * DD;
#pragma unroll
    for (int q = 0; q < 4; q++) {
        int j = t + q * 256;
        out_u[base + j] = v[q];
        UNh[base + j] = __float2bfloat16(v[q] * inv);
    }
}

// reads z_proj from out_zp (fp32, scalar) and u_norm from UNh (bf16)
__global__ __launch_bounds__(256) void znorm_kernel(const float* __restrict__ zp) {
    int row = blockIdx.x, t = threadIdx.x;
    size_t base = (size_t)row * DD;
    float v[4]; float ss = 0.f, dp = 0.f;
#pragma unroll
    for (int q = 0; q < 4; q++) {
        int j = t + q * 256;
        v[q] = zp[base + j];
        ss += v[q] * v[q];
        dp += v[q] * __bfloat162float(UNh[base + j]);
    }
    __shared__ float redA[256];
    __shared__ float redB[256];
    redA[t] = ss; redB[t] = dp; __syncthreads();
    for (int s = 128; s > 0; s >>= 1) {
        if (t < s) { redA[t] += redA[t + s]; redB[t] += redB[t + s]; }
        __syncthreads();
    }
    float inv = 1.f / fmaxf(sqrtf(redA[0]), EPSN);
#pragma unroll
    for (int q = 0; q < 4; q++) {
        int j = t + q * 256;
        ZNh[base + j] = __float2bfloat16(v[q] * inv);
    }
    if (t == 0) atomicAdd(&LOSSACC[2], (double)(fabsf(redB[0]) * inv));
}

__global__ __launch_bounds__(256) void scatter_kernel() {
    int row = blockIdx.x, t = threadIdx.x;
    int ig = (int)(~(uint32_t)AMAXG[row]);
    int il = (int)(~(uint32_t)AMAXL[row]);
    const __nv_bfloat16* u = UNh + (size_t)row * DD;
    int j = t * 4;
    uint2 raw = *(const uint2*)(u + j);
    __nv_bfloat162 p0 = *reinterpret_cast<__nv_bfloat162*>(&raw.x);
    __nv_bfloat162 p1 = *reinterpret_cast<__nv_bfloat162*>(&raw.y);
    float4 v = make_float4(__low2float(p0), __high2float(p0),
                           __low2float(p1), __high2float(p1));
    atomicAdd((float4*)(SUMS + (size_t)ig * DD + j), v);
    atomicAdd((float4*)(SUMS + (size_t)(NGC + il) * DD + j), v);
    if (t == 0) { atomicAdd(&COUNTS[ig], 1.f); atomicAdd(&COUNTS[NGC + il], 1.f); }
}

__global__ __launch_bounds__(256) void dictupd_kernel(const float* __restrict__ gd,
                                                      const float* __restrict__ ld) {
    int k = blockIdx.x, t = threadIdx.x;
    const float* old = (k < NGC) ? (gd + (size_t)k * DD) : (ld + (size_t)(k - NGC) * DD);
    float m = (k < NGC) ? 0.999f : 0.8f;
    float cnt = COUNTS[k];
    float up[4]; float ss = 0.f;
#pragma unroll
    for (int q = 0; q < 4; q++) {
        int j = t + q * 256;
        float o = old[j];
        float u;
        if (cnt > 0.f) {
            float mean = SUMS[(size_t)k * DD + j] / fmaxf(cnt, 1.f);
            u = m * o + (1.f - m) * mean;
        } else u = o;
        up[q] = u; ss += u * u;
    }
    __shared__ float red[256];
    red[t] = ss; __syncthreads();
    for (int s = 128; s > 0; s >>= 1) { if (t < s) red[t] += red[t + s]; __syncthreads(); }
    float inv = 1.f / fmaxf(sqrtf(red[0]), EPSN);
    size_t base = (size_t)k * DD;
#pragma unroll
    for (int q = 0; q < 4; q++) {
        int j = t + q * 256;
        float u = up[q] * inv;
        COMBINED[base + j] = u;
        CMBh[base + j] = __float2bfloat16(u);
    }
}

__global__ __launch_bounds__(256) void softmax_kernel() {
    int row = blockIdx.x, t = threadIdx.x;
    const __nv_bfloat16* L = LOGh + (size_t)row * NCC;
    const float invT = 1.f / 0.07f;
    float v[5];
    float mx = -3.0e38f;
#pragma unroll
    for (int q = 0; q < 5; q++) {
        v[q] = __bfloat162float(L[t + q * 256]) * invT;
        mx = fmaxf(mx, v[q]);
    }
    __shared__ float red[256];
    red[t] = mx; __syncthreads();
    for (int s = 128; s > 0; s >>= 1) { if (t < s) red[t] = fmaxf(red[t], red[t + s]); __syncthreads(); }
    mx = red[0]; __syncthreads();
    float sum = 0.f;
#pragma unroll
    for (int q = 0; q < 5; q++) { v[q] = __expf(v[q] - mx); sum += v[q]; }
    red[t] = sum; __syncthreads();
    for (int s = 128; s > 0; s >>= 1) { if (t < s) red[t] += red[t + s]; __syncthreads(); }
    float inv = 1.f / red[0];
    size_t base = (size_t)row * NCC;
#pragma unroll
    for (int q = 0; q < 5; q++)
        WTSh[base + t + q * 256] = __float2bfloat16(v[q] * inv);
}

__global__ void finalize_kernel(float* __restrict__ out_loss) {
    double lg = LOSSACC[0] / ((double)NT * (double)NGC);
    double ll = LOSSACC[1] / ((double)NT * (double)NLC);
    double ldir = LOSSACC[2] / (double)NT;
    *out_loss = (float)(lg + ll + ldir);
}

// ===================== mma.sync GEMM ========================================
// C[M,N] = A[M,K] * B[N,K]^T.
// SPLIT=1: fp32-effective 3-pass bf16, 2-stage pipe; SPLIT=0: 1-pass, 3-stage pipe.
// H16=1: operands are fp16 (mma f16), else bf16.
// CTA 128x128, 8 warps (2x4), warp tile 64x32 via m16n8k16.
// EPI: 0 store C | 1 relu+bias -> Oh (fp16 if H16 else bf16)
//      2 bias -> C2(scalar fp32) + Oh(bf16) | 3 sigmoid+bias -> Oh(bf16)
//      4 Oh(bf16) + abs-loss | 5 C = Zin - Gth*acc | 6 fused row argmax (no store)
#define OP_B 10240               // bytes per operand tile (128*80)

template <int EPI, int SPLIT, int H16>
__global__ __launch_bounds__(256, 2) void gemm_mma(
    const __nv_bfloat16* __restrict__ Ah, const __nv_bfloat16* __restrict__ Al,
    const __nv_bfloat16* __restrict__ Bh, const __nv_bfloat16* __restrict__ Bl,
    int K, int ldc,
    float* __restrict__ C, const float* __restrict__ bias,
    __nv_bfloat16* __restrict__ Oh, __nv_bfloat16* __restrict__ Ol,
    float* __restrict__ C2,
    const float* __restrict__ Zin, const __nv_bfloat16* __restrict__ Gth)
{
    constexpr int NOPS = SPLIT ? 4 : 2;
    constexpr int STAGES = SPLIT ? 2 : 3;
    constexpr int STG = NOPS * OP_B;
    constexpr int BH_OFF = SPLIT ? 2 * OP_B : OP_B;

    extern __shared__ char smem[];
    const uint32_t sb = smem_u32(smem);
    const int t = threadIdx.x;
    const int lane = t & 31, wid = t >> 5;
    const int wm = wid & 1, wn = wid >> 1;          // 2 x 4 warp grid
    const int row0 = blockIdx.y * 128, col0 = blockIdx.x * 128;

    float acc[4][4][4];
#pragma unroll
    for (int mi = 0; mi < 4; mi++)
#pragma unroll
        for (int ni = 0; ni < 4; ni++)
#pragma unroll
            for (int rr = 0; rr < 4; rr++) acc[mi][ni][rr] = 0.f;

    const int NCH = K >> 5;
    const __nv_bfloat16* srcs[4] = {Ah, SPLIT ? Al : Bh, Bh, Bl};
    const int rbase[4] = {row0, SPLIT ? row0 : col0, col0, col0};

    auto issue = [&](int c, int buf) {
        const int k0 = c << 5;
        const uint32_t base = sb + buf * STG;
#pragma unroll
        for (int o = 0; o < NOPS; o++) {
            const __nv_bfloat16* src = srcs[o];
            const int r0g = rbase[o];
            const uint32_t ob = base + o * OP_B;
#pragma unroll
            for (int s2 = 0; s2 < 2; s2++) {
                int s = t + s2 * 256;
                int row = s >> 2, part = s & 3;
                uint32_t dst = ob + row * 80 + part * 16;
                const void* sp = src + (size_t)(r0g + row) * K + k0 + part * 8;
                CP_ASYNC16(dst, sp);
            }
        }
        CP_COMMIT();
    };

    // prologue: fill STAGES-1 buffers
    issue(0, 0);
    if (STAGES > 2 && NCH > 1) issue(1, 1);

    for (int c = 0; c < NCH; c++) {
        int nxt = c + STAGES - 1;
        if (nxt < NCH) {
            issue(nxt, nxt % STAGES);
            if (STAGES == 3) CP_WAIT2(); else CP_WAIT1();
        } else if (STAGES == 3 && c + 2 == NCH) {
            CP_WAIT1();
        } else {
            CP_WAIT0();
        }
        __syncthreads();
        const uint32_t bb = sb + (c % STAGES) * STG;
#pragma unroll
        for (int ks = 0; ks < 32; ks += 16) {
            uint32_t bh[4][2], bl[4][2];
#pragma unroll
            for (int g2 = 0; g2 < 2; g2++) {
                int n0 = wn * 32 + g2 * 16;
                int r = n0 + (lane & 7) + (lane >> 4) * 8;
                int cc = ks + ((lane >> 3) & 1) * 8;
                uint32_t off = r * 80 + cc * 2;
                uint32_t r0, r1, r2, r3;
                LDSM_X4(r0, r1, r2, r3, bb + BH_OFF + off);
                bh[2 * g2 + 0][0] = r0; bh[2 * g2 + 0][1] = r1;
                bh[2 * g2 + 1][0] = r2; bh[2 * g2 + 1][1] = r3;
                if (SPLIT) {
                    LDSM_X4(r0, r1, r2, r3, bb + 3 * OP_B + off);
                    bl[2 * g2 + 0][0] = r0; bl[2 * g2 + 0][1] = r1;
                    bl[2 * g2 + 1][0] = r2; bl[2 * g2 + 1][1] = r3;
                }
            }
#pragma unroll
            for (int mi = 0; mi < 4; mi++) {
                int m0 = wm * 64 + mi * 16;
                int r = m0 + (lane & 7) + ((lane >> 3) & 1) * 8;
                int cc = ks + (lane >> 4) * 8;
                uint32_t off = r * 80 + cc * 2;
                uint32_t ah[4], al[4];
                LDSM_X4(ah[0], ah[1], ah[2], ah[3], bb + 0 * OP_B + off);
                if (SPLIT) LDSM_X4(al[0], al[1], al[2], al[3], bb + 1 * OP_B + off);
#pragma unroll
                for (int ni = 0; ni < 4; ni++) {
                    if (H16) {
                        mma_fp16(acc[mi][ni], ah, bh[ni]);
                    } else {
                        mma_bf16(acc[mi][ni], ah, bh[ni]);
                        if (SPLIT) {
                            mma_bf16(acc[mi][ni], ah, bl[ni]);
                            mma_bf16(acc[mi][ni], al, bh[ni]);
                        }
                    }
                }
            }
        }
        __syncthreads();
    }

    // ---------------- epilogue ----------------
    const int g = lane >> 2, tid4 = lane & 3;
    if (EPI == 6) {
        unsigned long long best[8];
#pragma unroll
        for (int i = 0; i < 8; i++) best[i] = 0ull;
#pragma unroll
        for (int mi = 0; mi < 4; mi++)
#pragma unroll
            for (int ni = 0; ni < 4; ni++)
#pragma unroll
                for (int rr = 0; rr < 4; rr++) {
                    int ri = mi * 2 + ((rr >> 1) & 1);
                    int lcol = wn * 32 + ni * 8 + tid4 * 2 + (rr & 1);
                    int sidx = (col0 >= NGC) ? (col0 - NGC + lcol) : (col0 + lcol);
                    uint32_t u = fmap(acc[mi][ni][rr]);
                    unsigned long long p =
                        ((unsigned long long)u << 32) | (uint32_t)(~sidx);
                    if (p > best[ri]) best[ri] = p;
                }
#pragma unroll
        for (int i = 0; i < 8; i++)
#pragma unroll
            for (int o = 1; o < 4; o <<= 1) {
                unsigned long long ov = __shfl_xor_sync(0xffffffffu, best[i], o);
                if (ov > best[i]) best[i] = ov;
            }
        unsigned long long* S = (unsigned long long*)smem;
        if (tid4 == 0) {
#pragma unroll
            for (int mi = 0; mi < 4; mi++)
#pragma unroll
                for (int b = 0; b < 2; b++) {
                    int lrow = wm * 64 + mi * 16 + g + b * 8;
                    S[lrow * 4 + wn] = best[mi * 2 + b];
                }
        }
        __syncthreads();
        if (t < 128) {
            unsigned long long m = S[t * 4];
#pragma unroll
            for (int w = 1; w < 4; w++) if (S[t * 4 + w] > m) m = S[t * 4 + w];
            unsigned long long* tgt = (col0 >= NGC) ? AMAXL : AMAXG;
            atomicMax(&tgt[row0 + t], m);
        }
        return;
    }

    float absSum = 0.f;
#pragma unroll
    for (int mi = 0; mi < 4; mi++) {
#pragma unroll
        for (int ni = 0; ni < 4; ni++) {
#pragma unroll
            for (int rr = 0; rr < 4; rr++) {
                int r = row0 + wm * 64 + mi * 16 + g + ((rr >> 1) & 1) * 8;
                int cidx = col0 + wn * 32 + ni * 8 + tid4 * 2 + (rr & 1);
                float v = acc[mi][ni][rr];
                size_t idx = (size_t)r * ldc + cidx;
                if (EPI == 0) C[idx] = v;
                else if (EPI == 1) {
                    v = fmaxf(v + bias[cidx], 0.f);
                    if (H16) ((__half*)Oh)[idx] = __float2half(v);
                    else Oh[idx] = __float2bfloat16(v);
                } else if (EPI == 2) {
                    v += bias[cidx];
                    C2[idx] = v;
                    Oh[idx] = __float2bfloat16(v);
                } else if (EPI == 3) {
                    v += bias[cidx];
                    Oh[idx] = __float2bfloat16(1.f / (1.f + __expf(-v)));
                } else if (EPI == 4) {
                    Oh[idx] = __float2bfloat16(v);
                    absSum += fabsf(v);
                } else if (EPI == 5) {
                    C[idx] = Zin[idx] - __bfloat162float(Gth[idx]) * v;
                }
            }
        }
    }
    if (EPI == 4) {
#pragma unroll
        for (int o = 16; o > 0; o >>= 1) absSum += __shfl_xor_sync(0xffffffffu, absSum, o);
        if (lane == 0) atomicAdd(&LOSSACC[col0 >= NGC ? 1 : 0], (double)absSum);
    }
}

// ===================== driver ===============================================
extern "C" void kernel_launch(void* const* d_in, const int* in_sizes, int n_in,
                              void* d_out, int out_size) {
    const float* content = (const float*)d_in[0];
    const float* noise   = (const float*)d_in[1];
    const float* W1 = (const float*)d_in[2];
    const float* b1 = (const float*)d_in[3];
    const float* W2 = (const float*)d_in[4];
    const float* b2 = (const float*)d_in[5];
    const float* Wg = (const float*)d_in[6];
    const float* bg = (const float*)d_in[7];
    const float* gdict = (const float*)d_in[8];
    const float* ldict = (const float*)d_in[9];

    float* out = (float*)d_out;
    float* out_zc   = out;                        // [NT*DD]
    float* out_loss = out + (size_t)NT * DD;      // [1]
    float* out_zp   = out_loss + 1;               // [NT*DD] 4B-aligned only
    float* out_u    = out_zp + (size_t)NT * DD;   // [NT*DD] 4B-aligned only

#define SYM(T, p, s) T* p; cudaGetSymbolAddress((void**)&p, s)
    SYM(float, CMB_p, COMBINED);
    SYM(__nv_bfloat16, CT16_p, CT16);
    SYM(__nv_bfloat16, UNh_p, UNh);
    SYM(__nv_bfloat16, H16_p, H16);
    SYM(__nv_bfloat16, ZPh_p, ZPh);
    SYM(__nv_bfloat16, ZNh_p, ZNh);
    SYM(__nv_bfloat16, GATEh_p, GATEh);
    SYM(__nv_bfloat16, LOGh_p, LOGh);
    SYM(__nv_bfloat16, WTSh_p, WTSh);
    SYM(__nv_bfloat16, DICh_p, DICh);
    SYM(__nv_bfloat16, CMBh_p, CMBh);
    SYM(__nv_bfloat16, CMBTh_p, CMBTh);
    SYM(__nv_bfloat16, W1T16_p, W1T16);
    SYM(__nv_bfloat16, W2T16_p, W2T16);
    SYM(__nv_bfloat16, WgTh_p, WgTh);

    const int SM0 = 3 * 2 * OP_B;   // 1-pass GEMM (3 stages x 2 ops): 61440
    cudaFuncSetAttribute(gemm_mma<6, 0, 0>, cudaFuncAttributeMaxDynamicSharedMemorySize, SM0);
    cudaFuncSetAttribute(gemm_mma<4, 0, 0>, cudaFuncAttributeMaxDynamicSharedMemorySize, SM0);
    cudaFuncSetAttribute(gemm_mma<3, 0, 0>, cudaFuncAttributeMaxDynamicSharedMemorySize, SM0);
    cudaFuncSetAttribute(gemm_mma<5, 0, 0>, cudaFuncAttributeMaxDynamicSharedMemorySize, SM0);
    cudaFuncSetAttribute(gemm_mma<1, 0, 1>, cudaFuncAttributeMaxDynamicSharedMemorySize, SM0);
    cudaFuncSetAttribute(gemm_mma<2, 0, 1>, cudaFuncAttributeMaxDynamicSharedMemorySize, SM0);

    // ---- stream fork: chain B (noise/dict) runs concurrently with chain A ----
    cudaStream_t sB;
    cudaStreamCreateWithFlags(&sB, cudaStreamNonBlocking);
    cudaEvent_t e0, e1;
    cudaEventCreateWithFlags(&e0, cudaEventDisableTiming);
    cudaEventCreateWithFlags(&e1, cudaEventDisableTiming);

    // zero feeds BOTH chains -> before fork
    zero_kernel<<<(NCC * DD + 255) / 256, 256>>>();
    cudaEventRecord(e0, 0);
    cudaStreamWaitEvent(sB, e0, 0);

    // ---- chain B (stream sB): noise -> sims/argmax -> scatter -> dict update
    unorm_kernel<<<NT, 256, 0, sB>>>(noise, out_u);
    cvt_kernel<0><<<256, 256, 0, sB>>>(gdict, DICh_p, (size_t)NGC * DD);
    cvt_kernel<0><<<64, 256, 0, sB>>>(ldict, DICh_p + (size_t)NGC * DD, (size_t)NLC * DD);
    gemm_mma<6, 0, 0><<<dim3(NCC / 128, NT / 128), 256, SM0, sB>>>(
        UNh_p, nullptr, DICh_p, nullptr, DD, NCC, nullptr, nullptr,
        nullptr, nullptr, nullptr, nullptr, nullptr);
    scatter_kernel<<<NT, 256, 0, sB>>>();
    dictupd_kernel<<<NCC, 256, 0, sB>>>(gdict, ldict);
    tsplit_kernel<0><<<dim3(DD / 32, NCC / 32), dim3(32, 32), 0, sB>>>(
        CMB_p, CMBTh_p, NCC, DD);
    cudaEventRecord(e1, sB);

    // ---- chain A (default stream): content -> projector (fp16 1-pass) -> gate
    cvt_kernel<1><<<2048, 256>>>(content, CT16_p, (size_t)NT * DD);
    tsplit_kernel<1><<<dim3(DD / 32, DD / 32), dim3(32, 32)>>>(W1, W1T16_p, DD, DD);
    tsplit_kernel<1><<<dim3(DD / 32, DD / 32), dim3(32, 32)>>>(W2, W2T16_p, DD, DD);
    tsplit_kernel<0><<<dim3(DD / 32, DD / 32), dim3(32, 32)>>>(Wg, WgTh_p, DD, DD);
    gemm_mma<1, 0, 1><<<dim3(DD / 128, NT / 128), 256, SM0>>>(
        CT16_p, nullptr, W1T16_p, nullptr, DD, DD, nullptr, b1,
        H16_p, nullptr, nullptr, nullptr, nullptr);
    gemm_mma<2, 0, 1><<<dim3(DD / 128, NT / 128), 256, SM0>>>(
        H16_p, nullptr, W2T16_p, nullptr, DD, DD, nullptr, b2,
        ZPh_p, nullptr, out_zp, nullptr, nullptr);
    gemm_mma<3, 0, 0><<<dim3(DD / 128, NT / 128), 256, SM0>>>(
        ZPh_p, nullptr, WgTh_p, nullptr, DD, DD, nullptr, bg,
        GATEh_p, nullptr, nullptr, nullptr, nullptr);

    // ---- join B into A, then the merged tail
    cudaStreamWaitEvent(0, e1, 0);
    znorm_kernel<<<NT, 256>>>(out_zp);           // needs UNh (B) + out_zp (A)
    gemm_mma<4, 0, 0><<<dim3(NCC / 128, NT / 128), 256, SM0>>>(
        ZNh_p, nullptr, CMBh_p, nullptr, DD, NCC, nullptr, nullptr,
        LOGh_p, nullptr, nullptr, nullptr, nullptr);
    softmax_kernel<<<NT, 256>>>();
    gemm_mma<5, 0, 0><<<dim3(DD / 128, NT / 128), 256, SM0>>>(
        WTSh_p, nullptr, CMBTh_p, nullptr, NCC, DD, out_zc, nullptr,
        nullptr, nullptr, nullptr, content, GATEh_p);
    finalize_kernel<<<1, 1>>>(out_loss);
}

// round 16
// speedup vs baseline: 4.6322x; 1.0294x over previous
#include <cuda_runtime.h>
#include <cuda_bf16.h>
#include <cuda_fp16.h>
#include <math.h>
#include <cstdint>

#define NT 32768      // B*L tokens
#define DD 1024
#define NGC 1024
#define NLC 256
#define NCC 1280      // NGC + NLC
#define EPSN 1e-12f
#define INVT 14.2857142857f   // 1/0.07

// ===================== helpers ==============================================
__device__ __forceinline__ uint32_t smem_u32(const void* p) {
    uint32_t a;
    asm("{ .reg .u64 t; cvta.to.shared.u64 t, %1; cvt.u32.u64 %0, t; }" : "=r"(a) : "l"(p));
    return a;
}

#define LDSM_X4(r0, r1, r2, r3, addr) \
    asm volatile("ldmatrix.sync.aligned.m8n8.x4.shared.b16 {%0,%1,%2,%3}, [%4];" \
                 : "=r"(r0), "=r"(r1), "=r"(r2), "=r"(r3) : "r"(addr))

__device__ __forceinline__ void mma_bf16(float* c, const uint32_t* a, const uint32_t* b) {
    asm volatile(
        "mma.sync.aligned.m16n8k16.row.col.f32.bf16.bf16.f32 "
        "{%0,%1,%2,%3}, {%4,%5,%6,%7}, {%8,%9}, {%0,%1,%2,%3};"
        : "+f"(c[0]), "+f"(c[1]), "+f"(c[2]), "+f"(c[3])
        : "r"(a[0]), "r"(a[1]), "r"(a[2]), "r"(a[3]), "r"(b[0]), "r"(b[1]));
}

__device__ __forceinline__ void mma_fp16(float* c, const uint32_t* a, const uint32_t* b) {
    asm volatile(
        "mma.sync.aligned.m16n8k16.row.col.f32.f16.f16.f32 "
        "{%0,%1,%2,%3}, {%4,%5,%6,%7}, {%8,%9}, {%0,%1,%2,%3};"
        : "+f"(c[0]), "+f"(c[1]), "+f"(c[2]), "+f"(c[3])
        : "r"(a[0]), "r"(a[1]), "r"(a[2]), "r"(a[3]), "r"(b[0]), "r"(b[1]));
}

#define CP_ASYNC16(dst, src) \
    asm volatile("cp.async.cg.shared.global [%0], [%1], 16;" :: "r"(dst), "l"(src) : "memory")
#define CP_COMMIT() asm volatile("cp.async.commit_group;" ::: "memory")
#define CP_WAIT2()  asm volatile("cp.async.wait_group 2;" ::: "memory")
#define CP_WAIT1()  asm volatile("cp.async.wait_group 1;" ::: "memory")
#define CP_WAIT0()  asm volatile("cp.async.wait_group 0;" ::: "memory")

// monotonic float->u32 mapping (order-preserving for all finite floats)
__device__ __forceinline__ uint32_t fmap(float f) {
    uint32_t u = __float_as_uint(f);
    return (u & 0x80000000u) ? ~u : (u | 0x80000000u);
}

// ===================== scratch ==============================================
__device__ float COMBINED[(size_t)NCC * DD];
__device__ __align__(16) float SUMS[(size_t)NCC * DD];
__device__ float COUNTS[NCC];
__device__ float ROWSUM[NT];               // per-row softmax denominator
__device__ unsigned long long AMAXG[NT];   // packed (mapped_val<<32)|~idx
__device__ unsigned long long AMAXL[NT];
__device__ double LOSSACC[3];

#define BUF(name, n) __device__ __align__(256) __nv_bfloat16 name[(size_t)(n)]
BUF(CT16, NT* DD);                    // content as fp16
BUF(UNh, NT* DD);
BUF(H16,  NT* DD);                    // hidden as fp16
BUF(ZPh, NT* DD);                     // z_proj as bf16 (for gate GEMM)
BUF(ZNh, NT* DD);
BUF(GATEh, NT* DD);
BUF(EXPh, NT* NCC);                   // exp(logit/T) as bf16
BUF(DICh, NCC* DD);
BUF(CMBh, NCC* DD);
BUF(CMBTh, DD* NCC);
BUF(W1T16, DD* DD);                   // W1^T as fp16
BUF(W2T16, DD* DD);                   // W2^T as fp16
BUF(WgTh, DD* DD);

// ===================== small kernels ========================================
__global__ void zero_kernel() {
    size_t i = (size_t)blockIdx.x * blockDim.x + threadIdx.x;
    size_t tot = (size_t)NCC * DD;
    if (i < tot) SUMS[i] = 0.f;
    if (i < NCC) COUNTS[i] = 0.f;
    if (i < NT) { AMAXG[i] = 0ull; AMAXL[i] = 0ull; ROWSUM[i] = 0.f; }
    if (i < 3) LOSSACC[i] = 0.0;
}

// FP16OUT=1: write __half; else bf16
template <int FP16OUT>
__global__ __launch_bounds__(256) void cvt_kernel(const float* __restrict__ src,
                                                  void* __restrict__ dst, size_t n) {
    for (size_t i = (size_t)blockIdx.x * blockDim.x + threadIdx.x; i < n;
         i += (size_t)gridDim.x * blockDim.x) {
        if (FP16OUT) ((__half*)dst)[i] = __float2half(src[i]);
        else ((__nv_bfloat16*)dst)[i] = __float2bfloat16(src[i]);
    }
}

// All three weight transposes in one launch: z=0->W1(fp16), z=1->W2(fp16), z=2->Wg(bf16)
__global__ void wsplit3_kernel(const float* __restrict__ W1, const float* __restrict__ W2,
                               const float* __restrict__ Wg,
                               __half* __restrict__ o1, __half* __restrict__ o2,
                               __nv_bfloat16* __restrict__ og) {
    __shared__ float tile[32][33];
    int z = blockIdx.z;
    const float* W = (z == 0) ? W1 : (z == 1) ? W2 : Wg;
    int bx = blockIdx.x, by = blockIdx.y;
    int x = bx * 32 + threadIdx.x;
    int y = by * 32 + threadIdx.y;
    tile[threadIdx.y][threadIdx.x] = W[(size_t)y * DD + x];
    __syncthreads();
    int orow = bx * 32 + threadIdx.y;
    int ocol = by * 32 + threadIdx.x;
    float v = tile[threadIdx.x][threadIdx.y];
    size_t idx = (size_t)orow * DD + ocol;
    if (z == 0) o1[idx] = __float2half(v);
    else if (z == 1) o2[idx] = __float2half(v);
    else og[idx] = __float2bfloat16(v);
}

// CMB[R=NCC,C=DD] -> CMBTh[C,R] bf16
__global__ void tcvt_kernel(const float* __restrict__ W, __nv_bfloat16* __restrict__ oh,
                            int R, int Cc) {
    __shared__ float tile[32][33];
    int bx = blockIdx.x, by = blockIdx.y;
    int x = bx * 32 + threadIdx.x;
    int y = by * 32 + threadIdx.y;
    tile[threadIdx.y][threadIdx.x] = W[(size_t)y * Cc + x];
    __syncthreads();
    int orow = bx * 32 + threadIdx.y;
    int ocol = by * 32 + threadIdx.x;
    oh[(size_t)orow * R + ocol] = __float2bfloat16(tile[threadIdx.x][threadIdx.y]);
}

__global__ __launch_bounds__(256) void unorm_kernel(const float* __restrict__ u,
                                                    float* __restrict__ out_u) {
    int row = blockIdx.x, t = threadIdx.x;
    const float* ur = u + (size_t)row * DD;
    float v[4]; float ss = 0.f;
#pragma unroll
    for (int q = 0; q < 4; q++) { v[q] = ur[t + q * 256]; ss += v[q] * v[q]; }
    __shared__ float red[256];
    red[t] = ss; __syncthreads();
    for (int s = 128; s > 0; s >>= 1) { if (t < s) red[t] += red[t + s]; __syncthreads(); }
    float inv = 1.f / fmaxf(sqrtf(red[0]), EPSN);
    size_t base = (size_t)row * DD;
#pragma unroll
    for (int q = 0; q < 4; q++) {
        int j = t + q * 256;
        out_u[base + j] = v[q];
        UNh[base + j] = __float2bfloat16(v[q] * inv);
    }
}

// reads z_proj from out_zp (fp32, scalar) and u_norm from UNh (bf16)
__global__ __launch_bounds__(256) void znorm_kernel(const float* __restrict__ zp) {
    int row = blockIdx.x, t = threadIdx.x;
    size_t base = (size_t)row * DD;
    float v[4]; float ss = 0.f, dp = 0.f;
#pragma unroll
    for (int q = 0; q < 4; q++) {
        int j = t + q * 256;
        v[q] = zp[base + j];
        ss += v[q] * v[q];
        dp += v[q] * __bfloat162float(UNh[base + j]);
    }
    __shared__ float redA[256];
    __shared__ float redB[256];
    redA[t] = ss; redB[t] = dp; __syncthreads();
    for (int s = 128; s > 0; s >>= 1) {
        if (t < s) { redA[t] += redA[t + s]; redB[t] += redB[t + s]; }
        __syncthreads();
    }
    float inv = 1.f / fmaxf(sqrtf(redA[0]), EPSN);
#pragma unroll
    for (int q = 0; q < 4; q++) {
        int j = t + q * 256;
        ZNh[base + j] = __float2bfloat16(v[q] * inv);
    }
    if (t == 0) atomicAdd(&LOSSACC[2], (double)(fabsf(redB[0]) * inv));
}

__global__ __launch_bounds__(256) void scatter_kernel() {
    int row = blockIdx.x, t = threadIdx.x;
    int ig = (int)(~(uint32_t)AMAXG[row]);
    int il = (int)(~(uint32_t)AMAXL[row]);
    const __nv_bfloat16* u = UNh + (size_t)row * DD;
    int j = t * 4;
    uint2 raw = *(const uint2*)(u + j);
    __nv_bfloat162 p0 = *reinterpret_cast<__nv_bfloat162*>(&raw.x);
    __nv_bfloat162 p1 = *reinterpret_cast<__nv_bfloat162*>(&raw.y);
    float4 v = make_float4(__low2float(p0), __high2float(p0),
                           __low2float(p1), __high2float(p1));
    atomicAdd((float4*)(SUMS + (size_t)ig * DD + j), v);
    atomicAdd((float4*)(SUMS + (size_t)(NGC + il) * DD + j), v);
    if (t == 0) { atomicAdd(&COUNTS[ig], 1.f); atomicAdd(&COUNTS[NGC + il], 1.f); }
}

__global__ __launch_bounds__(256) void dictupd_kernel(const float* __restrict__ gd,
                                                      const float* __restrict__ ld) {
    int k = blockIdx.x, t = threadIdx.x;
    const float* old = (k < NGC) ? (gd + (size_t)k * DD) : (ld + (size_t)(k - NGC) * DD);
    float m = (k < NGC) ? 0.999f : 0.8f;
    float cnt = COUNTS[k];
    float up[4]; float ss = 0.f;
#pragma unroll
    for (int q = 0; q < 4; q++) {
        int j = t + q * 256;
        float o = old[j];
        float u;
        if (cnt > 0.f) {
            float mean = SUMS[(size_t)k * DD + j] / fmaxf(cnt, 1.f);
            u = m * o + (1.f - m) * mean;
        } else u = o;
        up[q] = u; ss += u * u;
    }
    __shared__ float red[256];
    red[t] = ss; __syncthreads();
    for (int s = 128; s > 0; s >>= 1) { if (t < s) red[t] += red[t + s]; __syncthreads(); }
    float inv = 1.f / fmaxf(sqrtf(red[0]), EPSN);
    size_t base = (size_t)k * DD;
#pragma unroll
    for (int q = 0; q < 4; q++) {
        int j = t + q * 256;
        float u = up[q] * inv;
        COMBINED[base + j] = u;
        CMBh[base + j] = __float2bfloat16(u);
    }
}

__global__ void finalize_kernel(float* __restrict__ out_loss) {
    double lg = LOSSACC[0] / ((double)NT * (double)NGC);
    double ll = LOSSACC[1] / ((double)NT * (double)NLC);
    double ldir = LOSSACC[2] / (double)NT;
    *out_loss = (float)(lg + ll + ldir);
}

// ===================== mma.sync GEMM ========================================
// C[M,N] = A[M,K] * B[N,K]^T.  All 1-pass, 3-stage cp.async pipe.
// H16=1: operands fp16 (mma f16), else bf16.
// CTA 128x128, 8 warps (2x4), warp tile 64x32 via m16n8k16.
// EPI: 1 relu+bias -> Oh (fp16 if H16 else bf16)
//      2 bias -> C2(scalar fp32) + Oh(bf16) | 3 sigmoid+bias -> Oh(bf16)
//      4 exp(acc/T)->Oh(bf16) + ROWSUM atomics + abs-loss on acc
//      5 C = Zin - Gth*acc/ROWSUM | 6 fused row argmax (no store)
#define OP_B 10240               // bytes per operand tile (128*80)

template <int EPI, int H16>
__global__ __launch_bounds__(256, 2) void gemm_mma(
    const __nv_bfloat16* __restrict__ Ah, const __nv_bfloat16* __restrict__ Bh,
    int K, int ldc,
    float* __restrict__ C, const float* __restrict__ bias,
    __nv_bfloat16* __restrict__ Oh, float* __restrict__ C2,
    const float* __restrict__ Zin, const __nv_bfloat16* __restrict__ Gth)
{
    constexpr int STAGES = 3;
    constexpr int STG = 2 * OP_B;

    extern __shared__ char smem[];
    const uint32_t sb = smem_u32(smem);
    const int t = threadIdx.x;
    const int lane = t & 31, wid = t >> 5;
    const int wm = wid & 1, wn = wid >> 1;          // 2 x 4 warp grid
    const int row0 = blockIdx.y * 128, col0 = blockIdx.x * 128;

    float acc[4][4][4];
#pragma unroll
    for (int mi = 0; mi < 4; mi++)
#pragma unroll
        for (int ni = 0; ni < 4; ni++)
#pragma unroll
            for (int rr = 0; rr < 4; rr++) acc[mi][ni][rr] = 0.f;

    const int NCH = K >> 5;

    auto issue = [&](int c, int buf) {
        const int k0 = c << 5;
        const uint32_t base = sb + buf * STG;
#pragma unroll
        for (int o = 0; o < 2; o++) {
            const __nv_bfloat16* src = o ? Bh : Ah;
            const int r0g = o ? col0 : row0;
            const uint32_t ob = base + o * OP_B;
#pragma unroll
            for (int s2 = 0; s2 < 2; s2++) {
                int s = t + s2 * 256;
                int row = s >> 2, part = s & 3;
                uint32_t dst = ob + row * 80 + part * 16;
                const void* sp = src + (size_t)(r0g + row) * K + k0 + part * 8;
                CP_ASYNC16(dst, sp);
            }
        }
        CP_COMMIT();
    };

    issue(0, 0);
    if (NCH > 1) issue(1, 1);

    for (int c = 0; c < NCH; c++) {
        int nxt = c + STAGES - 1;
        if (nxt < NCH)            { issue(nxt, nxt % STAGES); CP_WAIT2(); }
        else if (c + 2 == NCH)    { CP_WAIT1(); }
        else                      { CP_WAIT0(); }
        __syncthreads();
        const uint32_t bb = sb + (c % STAGES) * STG;
#pragma unroll
        for (int ks = 0; ks < 32; ks += 16) {
            uint32_t bh[4][2];
#pragma unroll
            for (int g2 = 0; g2 < 2; g2++) {
                int n0 = wn * 32 + g2 * 16;
                int r = n0 + (lane & 7) + (lane >> 4) * 8;
                int cc = ks + ((lane >> 3) & 1) * 8;
                uint32_t off = r * 80 + cc * 2;
                uint32_t r0, r1, r2, r3;
                LDSM_X4(r0, r1, r2, r3, bb + OP_B + off);
                bh[2 * g2 + 0][0] = r0; bh[2 * g2 + 0][1] = r1;
                bh[2 * g2 + 1][0] = r2; bh[2 * g2 + 1][1] = r3;
            }
#pragma unroll
            for (int mi = 0; mi < 4; mi++) {
                int m0 = wm * 64 + mi * 16;
                int r = m0 + (lane & 7) + ((lane >> 3) & 1) * 8;
                int cc = ks + (lane >> 4) * 8;
                uint32_t off = r * 80 + cc * 2;
                uint32_t ah[4];
                LDSM_X4(ah[0], ah[1], ah[2], ah[3], bb + off);
#pragma unroll
                for (int ni = 0; ni < 4; ni++) {
                    if (H16) mma_fp16(acc[mi][ni], ah, bh[ni]);
                    else     mma_bf16(acc[mi][ni], ah, bh[ni]);
                }
            }
        }
        __syncthreads();
    }

    // ---------------- epilogue ----------------
    const int g = lane >> 2, tid4 = lane & 3;
    if (EPI == 6) {
        unsigned long long best[8];
#pragma unroll
        for (int i = 0; i < 8; i++) best[i] = 0ull;
#pragma unroll
        for (int mi = 0; mi < 4; mi++)
#pragma unroll
            for (int ni = 0; ni < 4; ni++)
#pragma unroll
                for (int rr = 0; rr < 4; rr++) {
                    int ri = mi * 2 + ((rr >> 1) & 1);
                    int lcol = wn * 32 + ni * 8 + tid4 * 2 + (rr & 1);
                    int sidx = (col0 >= NGC) ? (col0 - NGC + lcol) : (col0 + lcol);
                    uint32_t u = fmap(acc[mi][ni][rr]);
                    unsigned long long p =
                        ((unsigned long long)u << 32) | (uint32_t)(~sidx);
                    if (p > best[ri]) best[ri] = p;
                }
#pragma unroll
        for (int i = 0; i < 8; i++)
#pragma unroll
            for (int o = 1; o < 4; o <<= 1) {
                unsigned long long ov = __shfl_xor_sync(0xffffffffu, best[i], o);
                if (ov > best[i]) best[i] = ov;
            }
        unsigned long long* S = (unsigned long long*)smem;
        if (tid4 == 0) {
#pragma unroll
            for (int mi = 0; mi < 4; mi++)
#pragma unroll
                for (int b = 0; b < 2; b++) {
                    int lrow = wm * 64 + mi * 16 + g + b * 8;
                    S[lrow * 4 + wn] = best[mi * 2 + b];
                }
        }
        __syncthreads();
        if (t < 128) {
            unsigned long long m = S[t * 4];
#pragma unroll
            for (int w = 1; w < 4; w++) if (S[t * 4 + w] > m) m = S[t * 4 + w];
            unsigned long long* tgt = (col0 >= NGC) ? AMAXL : AMAXG;
            atomicMax(&tgt[row0 + t], m);
        }
        return;
    }

    float absSum = 0.f;
    float rowPart[8];
    if (EPI == 4) {
#pragma unroll
        for (int i = 0; i < 8; i++) rowPart[i] = 0.f;
    }
#pragma unroll
    for (int mi = 0; mi < 4; mi++) {
#pragma unroll
        for (int ni = 0; ni < 4; ni++) {
#pragma unroll
            for (int rr = 0; rr < 4; rr++) {
                int r = row0 + wm * 64 + mi * 16 + g + ((rr >> 1) & 1) * 8;
                int cidx = col0 + wn * 32 + ni * 8 + tid4 * 2 + (rr & 1);
                float v = acc[mi][ni][rr];
                size_t idx = (size_t)r * ldc + cidx;
                if (EPI == 1) {
                    v = fmaxf(v + bias[cidx], 0.f);
                    if (H16) ((__half*)Oh)[idx] = __float2half(v);
                    else Oh[idx] = __float2bfloat16(v);
                } else if (EPI == 2) {
                    v += bias[cidx];
                    C2[idx] = v;
                    Oh[idx] = __float2bfloat16(v);
                } else if (EPI == 3) {
                    v += bias[cidx];
                    Oh[idx] = __float2bfloat16(1.f / (1.f + __expf(-v)));
                } else if (EPI == 4) {
                    absSum += fabsf(v);
                    float e = __expf(v * INVT);
                    Oh[idx] = __float2bfloat16(e);
                    rowPart[mi * 2 + ((rr >> 1) & 1)] += e;
                } else if (EPI == 5) {
                    float invRS = 1.f / ROWSUM[r];
                    C[idx] = Zin[idx] - __bfloat162float(Gth[idx]) * v * invRS;
                }
            }
        }
    }
    if (EPI == 4) {
        // reduce rowPart across the quad (tid4), then atomic per row
#pragma unroll
        for (int i = 0; i < 8; i++) {
            rowPart[i] += __shfl_xor_sync(0xffffffffu, rowPart[i], 1);
            rowPart[i] += __shfl_xor_sync(0xffffffffu, rowPart[i], 2);
        }
        if (tid4 == 0) {
#pragma unroll
            for (int mi = 0; mi < 4; mi++)
#pragma unroll
                for (int b = 0; b < 2; b++) {
                    int r = row0 + wm * 64 + mi * 16 + g + b * 8;
                    atomicAdd(&ROWSUM[r], rowPart[mi * 2 + b]);
                }
        }
#pragma unroll
        for (int o = 16; o > 0; o >>= 1) absSum += __shfl_xor_sync(0xffffffffu, absSum, o);
        if (lane == 0) atomicAdd(&LOSSACC[col0 >= NGC ? 1 : 0], (double)absSum);
    }
}

// ===================== driver ===============================================
extern "C" void kernel_launch(void* const* d_in, const int* in_sizes, int n_in,
                              void* d_out, int out_size) {
    const float* content = (const float*)d_in[0];
    const float* noise   = (const float*)d_in[1];
    const float* W1 = (const float*)d_in[2];
    const float* b1 = (const float*)d_in[3];
    const float* W2 = (const float*)d_in[4];
    const float* b2 = (const float*)d_in[5];
    const float* Wg = (const float*)d_in[6];
    const float* bg = (const float*)d_in[7];
    const float* gdict = (const float*)d_in[8];
    const float* ldict = (const float*)d_in[9];

    float* out = (float*)d_out;
    float* out_zc   = out;                        // [NT*DD]
    float* out_loss = out + (size_t)NT * DD;      // [1]
    float* out_zp   = out_loss + 1;               // [NT*DD] 4B-aligned only
    float* out_u    = out_zp + (size_t)NT * DD;   // [NT*DD] 4B-aligned only

#define SYM(T, p, s) T* p; cudaGetSymbolAddress((void**)&p, s)
    SYM(float, CMB_p, COMBINED);
    SYM(__nv_bfloat16, CT16_p, CT16);
    SYM(__nv_bfloat16, UNh_p, UNh);
    SYM(__nv_bfloat16, H16_p, H16);
    SYM(__nv_bfloat16, ZPh_p, ZPh);
    SYM(__nv_bfloat16, ZNh_p, ZNh);
    SYM(__nv_bfloat16, GATEh_p, GATEh);
    SYM(__nv_bfloat16, EXPh_p, EXPh);
    SYM(__nv_bfloat16, DICh_p, DICh);
    SYM(__nv_bfloat16, CMBh_p, CMBh);
    SYM(__nv_bfloat16, CMBTh_p, CMBTh);
    SYM(__nv_bfloat16, W1T16_p, W1T16);
    SYM(__nv_bfloat16, W2T16_p, W2T16);
    SYM(__nv_bfloat16, WgTh_p, WgTh);

    const int SM0 = 3 * 2 * OP_B;   // 3 stages x 2 ops: 61440
    cudaFuncSetAttribute(gemm_mma<6, 0>, cudaFuncAttributeMaxDynamicSharedMemorySize, SM0);
    cudaFuncSetAttribute(gemm_mma<4, 0>, cudaFuncAttributeMaxDynamicSharedMemorySize, SM0);
    cudaFuncSetAttribute(gemm_mma<3, 0>, cudaFuncAttributeMaxDynamicSharedMemorySize, SM0);
    cudaFuncSetAttribute(gemm_mma<5, 0>, cudaFuncAttributeMaxDynamicSharedMemorySize, SM0);
    cudaFuncSetAttribute(gemm_mma<1, 1>, cudaFuncAttributeMaxDynamicSharedMemorySize, SM0);
    cudaFuncSetAttribute(gemm_mma<2, 1>, cudaFuncAttributeMaxDynamicSharedMemorySize, SM0);

    // ---- stream fork: chain B (noise/dict) runs concurrently with chain A ----
    cudaStream_t sB;
    cudaStreamCreateWithFlags(&sB, cudaStreamNonBlocking);
    cudaEvent_t e0, e1;
    cudaEventCreateWithFlags(&e0, cudaEventDisableTiming);
    cudaEventCreateWithFlags(&e1, cudaEventDisableTiming);

    // zero feeds BOTH chains -> before fork
    zero_kernel<<<(NCC * DD + 255) / 256, 256>>>();
    cudaEventRecord(e0, 0);
    cudaStreamWaitEvent(sB, e0, 0);

    // ---- chain B (stream sB): noise -> sims/argmax -> scatter -> dict update
    unorm_kernel<<<NT, 256, 0, sB>>>(noise, out_u);
    cvt_kernel<0><<<256, 256, 0, sB>>>(gdict, DICh_p, (size_t)NGC * DD);
    cvt_kernel<0><<<64, 256, 0, sB>>>(ldict, DICh_p + (size_t)NGC * DD, (size_t)NLC * DD);
    gemm_mma<6, 0><<<dim3(NCC / 128, NT / 128), 256, SM0, sB>>>(
        UNh_p, DICh_p, DD, NCC, nullptr, nullptr, nullptr, nullptr, nullptr, nullptr);
    scatter_kernel<<<NT, 256, 0, sB>>>();
    dictupd_kernel<<<NCC, 256, 0, sB>>>(gdict, ldict);
    tcvt_kernel<<<dim3(DD / 32, NCC / 32), dim3(32, 32), 0, sB>>>(CMB_p, CMBTh_p, NCC, DD);
    cudaEventRecord(e1, sB);

    // ---- chain A (default stream): content -> projector (fp16 1-pass) -> gate
    cvt_kernel<1><<<2048, 256>>>(content, CT16_p, (size_t)NT * DD);
    wsplit3_kernel<<<dim3(DD / 32, DD / 32, 3), dim3(32, 32)>>>(
        W1, W2, Wg, (__half*)W1T16_p, (__half*)W2T16_p, WgTh_p);
    gemm_mma<1, 1><<<dim3(DD / 128, NT / 128), 256, SM0>>>(
        CT16_p, W1T16_p, DD, DD, nullptr, b1, H16_p, nullptr, nullptr, nullptr);
    gemm_mma<2, 1><<<dim3(DD / 128, NT / 128), 256, SM0>>>(
        H16_p, W2T16_p, DD, DD, nullptr, b2, ZPh_p, out_zp, nullptr, nullptr);
    gemm_mma<3, 0><<<dim3(DD / 128, NT / 128), 256, SM0>>>(
        ZPh_p, WgTh_p, DD, DD, nullptr, bg, GATEh_p, nullptr, nullptr, nullptr);

    // ---- join B into A, then the merged tail
    cudaStreamWaitEvent(0, e1, 0);
    znorm_kernel<<<NT, 256>>>(out_zp);           // needs UNh (B) + out_zp (A)
    gemm_mma<4, 0><<<dim3(NCC / 128, NT / 128), 256, SM0>>>(
        ZNh_p, CMBh_p, DD, NCC, nullptr, nullptr, EXPh_p, nullptr, nullptr, nullptr);
    gemm_mma<5, 0><<<dim3(DD / 128, NT / 128), 256, SM0>>>(
        EXPh_p, CMBTh_p, NCC, DD, out_zc, nullptr, nullptr, nullptr, content, GATEh_p);
    finalize_kernel<<<1, 1>>>(out_loss);
}